// round 1
// baseline (speedup 1.0000x reference)
#include <cuda_runtime.h>
#include <math.h>

#define NN 4096
#define EE_MAX 131072
#define EPMAX (EE_MAX + NN)
#define INC 512
#define NHEADS 8
#define HID 64
#define OUTC 256
#define WORDS (NN / 32)
#define NEG 0.2f

// ------------------------- device scratch (static, no allocs) ---------------
__device__ unsigned g_is64;
__device__ int g_src[EE_MAX], g_dst[EE_MAX];
__device__ unsigned g_adj[NN * WORDS];            // 2 MB bitmap A[s][d]
__device__ int g_deg[NN];
__device__ int g_rowptr[NN + 1];
__device__ int g_cols[EPMAX];                     // deduped CSR (src -> dst), sorted
__device__ float g_d1[NN], g_d2[NN], g_d3[NN];    // A*1, A^2*1, A^3*1 (row sums)
__device__ float g_A2[NN * NN];                   // 64 MB dense A@A (small int counts)
__device__ float g_mw[EPMAX];                     // motif weight per edge (incl self loops)
__device__ float g_h1[NN * INC];                  // x @ W1
__device__ float g_h2[NN * INC];                  // elu(layer1 out)
__device__ float g_h2w[NN * OUTC];                // h2 @ W2
__device__ float g_s1s[NN * NHEADS], g_s1d[NN * NHEADS];
__device__ float g_s2s[NN], g_s2d[NN];
__device__ int g_hist[NN];
__device__ int g_dptr[NN + 1];                    // CSR over dst for E' edges
__device__ int g_eidx[EPMAX];
__device__ float g_max1[NN * NHEADS], g_sum1[NN * NHEADS];
__device__ float g_max2[NN * NHEADS], g_sum2[NN * NHEADS];
__device__ float g_a1[EPMAX * NHEADS];            // layer1 alphas
__device__ float g_m21[NN], g_s21[NN], g_m22[NN], g_s22[NN];
__device__ float g_a2[EPMAX];                     // layer2 alphas

// ------------------------- edge dtype detect / convert ----------------------
__global__ void k_detect(const void* p) {
    // If data is int64, every odd 32-bit word (high half) of the first 2048
    // words is zero (indices < 4096). For int32 data those words are real
    // indices; P(all 1024 samples == 0) ~ (1/4096)^1024 ~ 0.
    __shared__ int any;
    if (threadIdx.x == 0) any = 0;
    __syncthreads();
    const int* w = (const int*)p;
    if (w[2 * threadIdx.x + 1] != 0) any = 1;
    __syncthreads();
    if (threadIdx.x == 0) g_is64 = (any == 0) ? 1u : 0u;
}

__global__ void k_convert(const void* p, int E) {
    int i = blockIdx.x * blockDim.x + threadIdx.x;
    if (i >= E) return;
    if (g_is64) {
        const long long* q = (const long long*)p;
        g_src[i] = (int)q[i];
        g_dst[i] = (int)q[E + i];
    } else {
        const int* q = (const int*)p;
        g_src[i] = q[i];
        g_dst[i] = q[E + i];
    }
}

// ------------------------- zeroing -----------------------------------------
__global__ void k_zero_all() {
    int stride = gridDim.x * blockDim.x;
    int gid = blockIdx.x * blockDim.x + threadIdx.x;
    for (int i = gid; i < NN * NN; i += stride) g_A2[i] = 0.f;
    for (int i = gid; i < NN * WORDS; i += stride) g_adj[i] = 0u;
    for (int i = gid; i < NN; i += stride) g_hist[i] = 0;
}

__global__ void k_zerohist() {
    int i = blockIdx.x * blockDim.x + threadIdx.x;
    if (i < NN) g_hist[i] = 0;
}

// ------------------------- adjacency ----------------------------------------
__global__ void k_bitmap(int E) {
    int i = blockIdx.x * blockDim.x + threadIdx.x;
    int EP = E + NN;
    if (i >= EP) return;
    int s, d;
    if (i < E) { s = g_src[i]; d = g_dst[i]; }
    else { s = i - E; d = i - E; }
    atomicOr(&g_adj[s * WORDS + (d >> 5)], 1u << (d & 31));
}

__global__ void k_deg() {
    int r = blockIdx.x * blockDim.x + threadIdx.x;
    if (r >= NN) return;
    int c = 0;
    for (int w = 0; w < WORDS; w++) c += __popc(g_adj[r * WORDS + w]);
    g_deg[r] = c;
    g_d1[r] = (float)c;
}

// single-block exclusive scan of 4096 ints; which=0: deg->rowptr, 1: hist->dptr
__global__ void k_scan4096(int which) {
    __shared__ int s[1024];
    const int* in = which ? g_hist : g_deg;
    int* out = which ? g_dptr : g_rowptr;
    int tid = threadIdx.x;
    int base = tid * 4;
    int loc[4];
    int tot = 0;
#pragma unroll
    for (int i = 0; i < 4; i++) { loc[i] = tot; tot += in[base + i]; }
    s[tid] = tot;
    __syncthreads();
    for (int off = 1; off < 1024; off <<= 1) {
        int t = (tid >= off) ? s[tid - off] : 0;
        __syncthreads();
        s[tid] += t;
        __syncthreads();
    }
    int pre = (tid == 0) ? 0 : s[tid - 1];
#pragma unroll
    for (int i = 0; i < 4; i++) out[base + i] = pre + loc[i];
    if (tid == 1023) out[4096] = s[1023];
}

__global__ void k_fillcols() {
    int r = blockIdx.x * blockDim.x + threadIdx.x;
    if (r >= NN) return;
    int p = g_rowptr[r];
    for (int w = 0; w < WORDS; w++) {
        unsigned m = g_adj[r * WORDS + w];
        while (m) {
            int b = __ffs(m) - 1;
            g_cols[p++] = w * 32 + b;
            m &= m - 1;
        }
    }
}

// which=0: d2 = A*d1 ; which=1: d3 = A*d2
__global__ void k_spmv(int which) {
    int r = blockIdx.x * blockDim.x + threadIdx.x;
    if (r >= NN) return;
    const float* vin = which ? g_d2 : g_d1;
    float s = 0.f;
    int p1 = g_rowptr[r + 1];
    for (int i = g_rowptr[r]; i < p1; i++) s += vin[g_cols[i]];
    if (which) g_d3[r] = s; else g_d2[r] = s;
}

// A2[k][d] += 1 for each 2-path k->m->d
__global__ void k_a2() {
    int k = blockIdx.x;
    int p0 = g_rowptr[k], p1 = g_rowptr[k + 1];
    float* row = g_A2 + k * NN;
    for (int mi = p0; mi < p1; mi++) {
        int m = g_cols[mi];
        int q0 = g_rowptr[m], q1 = g_rowptr[m + 1];
        for (int j = q0 + threadIdx.x; j < q1; j += blockDim.x)
            atomicAdd(&row[g_cols[j]], 1.0f);
    }
}

// mw[e] = A^3[s,d] / max(rowsum(A^3)[s], 1)
__global__ void k_mw(int E) {
    int e = blockIdx.x * blockDim.x + threadIdx.x;
    int EP = E + NN;
    if (e >= EP) return;
    int s = (e < E) ? g_src[e] : (e - E);
    int d = (e < E) ? g_dst[e] : (e - E);
    float a3 = 0.f;
    int p1 = g_rowptr[s + 1];
    for (int i = g_rowptr[s]; i < p1; i++) a3 += g_A2[g_cols[i] * NN + d];
    float nm = g_d3[s];
    if (nm < 1.f) nm = 1.f;
    g_mw[e] = a3 / nm;
}

// ------------------------- GEMM ---------------------------------------------
#define BM 64
#define BN 64
#define BK 16
__device__ __forceinline__ void gemm_body(const float* __restrict__ A,
                                          const float* __restrict__ B,
                                          float* __restrict__ C,
                                          int M, int Nc, int K) {
    __shared__ float As[BK][BM];
    __shared__ float Bs[BK][BN];
    int tid = threadIdx.x;
    int tx = tid % 16, ty = tid / 16;
    int row0 = blockIdx.y * BM, col0 = blockIdx.x * BN;
    float acc[4][4] = {};
    for (int k0 = 0; k0 < K; k0 += BK) {
        for (int i = tid; i < BM * BK; i += 256) {
            int r = i / BK, c = i % BK;
            As[c][r] = A[(row0 + r) * K + k0 + c];
        }
        for (int i = tid; i < BK * BN; i += 256) {
            int r = i / BN, c = i % BN;
            Bs[r][c] = B[(k0 + r) * Nc + col0 + c];
        }
        __syncthreads();
#pragma unroll
        for (int kk = 0; kk < BK; kk++) {
            float a[4], b[4];
#pragma unroll
            for (int i = 0; i < 4; i++) a[i] = As[kk][ty * 4 + i];
#pragma unroll
            for (int j = 0; j < 4; j++) b[j] = Bs[kk][tx * 4 + j];
#pragma unroll
            for (int i = 0; i < 4; i++)
#pragma unroll
                for (int j = 0; j < 4; j++) acc[i][j] += a[i] * b[j];
        }
        __syncthreads();
    }
#pragma unroll
    for (int i = 0; i < 4; i++)
#pragma unroll
        for (int j = 0; j < 4; j++)
            C[(row0 + ty * 4 + i) * Nc + col0 + tx * 4 + j] = acc[i][j];
}

__global__ void k_gemm1(const float* x, const float* W1) { gemm_body(x, W1, g_h1, NN, INC, INC); }
__global__ void k_gemm2(const float* W2) { gemm_body(g_h2, W2, g_h2w, NN, OUTC, INC); }
__global__ void k_gemm3(const float* rW, float* out) { gemm_body(g_h2, rW, out, NN, OUTC, INC); }

// ------------------------- attention scores ----------------------------------
__global__ void k_s1(const float* __restrict__ as1, const float* __restrict__ ad1) {
    int i = blockIdx.x * blockDim.x + threadIdx.x;
    if (i >= NN * NHEADS) return;
    int n = i / NHEADS, h = i % NHEADS;
    const float* hp = g_h1 + n * INC + h * HID;
    float ss = 0.f, sd = 0.f;
    for (int c = 0; c < HID; c++) {
        float v = hp[c];
        ss += v * as1[h * HID + c];
        sd += v * ad1[h * HID + c];
    }
    g_s1s[i] = ss;
    g_s1d[i] = sd;
}

__global__ void k_s2(const float* __restrict__ as2, const float* __restrict__ ad2) {
    int n = blockIdx.x * blockDim.x + threadIdx.x;
    if (n >= NN) return;
    const float* hp = g_h2w + n * OUTC;
    float ss = 0.f, sd = 0.f;
    for (int c = 0; c < OUTC; c++) {
        float v = hp[c];
        ss += v * as2[c];
        sd += v * ad2[c];
    }
    g_s2s[n] = ss;
    g_s2d[n] = sd;
}

// ------------------------- dst CSR -------------------------------------------
__global__ void k_hist(int E) {
    int e = blockIdx.x * blockDim.x + threadIdx.x;
    int EP = E + NN;
    if (e >= EP) return;
    int d = (e < E) ? g_dst[e] : (e - E);
    atomicAdd(&g_hist[d], 1);
}

__global__ void k_scatter(int E) {
    int e = blockIdx.x * blockDim.x + threadIdx.x;
    int EP = E + NN;
    if (e >= EP) return;
    int d = (e < E) ? g_dst[e] : (e - E);
    int pos = g_dptr[d] + atomicAdd(&g_hist[d], 1);
    g_eidx[pos] = e;
}

// ------------------------- layer1 softmax stats ------------------------------
__device__ __forceinline__ float lrelu(float x) { return x > 0.f ? x : NEG * x; }

__global__ void k_maxsum1(int E) {
    int n = blockIdx.x;
    int h = threadIdx.x >> 5;
    int lane = threadIdx.x & 31;
    int p0 = g_dptr[n], p1 = g_dptr[n + 1];
    float sd = g_s1d[n * NHEADS + h];
    float m1 = -1e30f, m2 = -1e30f;
    for (int i = p0 + lane; i < p1; i += 32) {
        int e = g_eidx[i];
        int s = (e < E) ? g_src[e] : (e - E);
        float ev = g_s1s[s * NHEADS + h] + sd;
        float l1 = lrelu(ev);
        float l2 = lrelu(ev * g_mw[e]);
        m1 = fmaxf(m1, l1);
        m2 = fmaxf(m2, l2);
    }
    for (int o = 16; o; o >>= 1) {
        m1 = fmaxf(m1, __shfl_xor_sync(0xffffffffu, m1, o));
        m2 = fmaxf(m2, __shfl_xor_sync(0xffffffffu, m2, o));
    }
    float s1 = 0.f, s2 = 0.f;
    for (int i = p0 + lane; i < p1; i += 32) {
        int e = g_eidx[i];
        int s = (e < E) ? g_src[e] : (e - E);
        float ev = g_s1s[s * NHEADS + h] + sd;
        s1 += expf(lrelu(ev) - m1);
        s2 += expf(lrelu(ev * g_mw[e]) - m2);
    }
    for (int o = 16; o; o >>= 1) {
        s1 += __shfl_xor_sync(0xffffffffu, s1, o);
        s2 += __shfl_xor_sync(0xffffffffu, s2, o);
    }
    if (lane == 0) {
        g_max1[n * NHEADS + h] = m1;
        g_sum1[n * NHEADS + h] = s1;
        g_max2[n * NHEADS + h] = m2;
        g_sum2[n * NHEADS + h] = s2;
    }
}

__global__ void k_alpha1(int E) {
    int i = blockIdx.x * blockDim.x + threadIdx.x;
    int EP = E + NN;
    if (i >= EP * NHEADS) return;
    int e = i / NHEADS, h = i % NHEADS;
    int s = (e < E) ? g_src[e] : (e - E);
    int d = (e < E) ? g_dst[e] : (e - E);
    float ev = g_s1s[s * NHEADS + h] + g_s1d[d * NHEADS + h];
    float l1 = lrelu(ev);
    float l2 = lrelu(ev * g_mw[e]);
    float a = 0.5f * expf(l1 - g_max1[d * NHEADS + h]) / (g_sum1[d * NHEADS + h] + 1e-16f)
            + 0.5f * expf(l2 - g_max2[d * NHEADS + h]) / (g_sum2[d * NHEADS + h] + 1e-16f);
    g_a1[i] = a;
}

__global__ void k_agg1(const float* __restrict__ b1, int E) {
    int n = blockIdx.x;
    int j = threadIdx.x;  // 0..511 -> (head = j/64, ch = j%64)
    int h = j >> 6;
    float acc = 0.f;
    int p0 = g_dptr[n], p1 = g_dptr[n + 1];
    for (int i = p0; i < p1; i++) {
        int e = g_eidx[i];
        int s = (e < E) ? g_src[e] : (e - E);
        acc += g_a1[e * NHEADS + h] * g_h1[s * INC + j];
    }
    float v = acc + b1[j];
    g_h2[n * INC + j] = v > 0.f ? v : expm1f(v);  // elu
}

// ------------------------- layer 2 -------------------------------------------
__global__ void k_maxsum2(int E) {
    int n = blockIdx.x;
    int lane = threadIdx.x;
    int p0 = g_dptr[n], p1 = g_dptr[n + 1];
    float sd = g_s2d[n];
    float m1 = -1e30f, m2 = -1e30f;
    for (int i = p0 + lane; i < p1; i += 32) {
        int e = g_eidx[i];
        int s = (e < E) ? g_src[e] : (e - E);
        float ev = g_s2s[s] + sd;
        m1 = fmaxf(m1, lrelu(ev));
        m2 = fmaxf(m2, lrelu(ev * g_mw[e]));
    }
    for (int o = 16; o; o >>= 1) {
        m1 = fmaxf(m1, __shfl_xor_sync(0xffffffffu, m1, o));
        m2 = fmaxf(m2, __shfl_xor_sync(0xffffffffu, m2, o));
    }
    float s1 = 0.f, s2 = 0.f;
    for (int i = p0 + lane; i < p1; i += 32) {
        int e = g_eidx[i];
        int s = (e < E) ? g_src[e] : (e - E);
        float ev = g_s2s[s] + sd;
        s1 += expf(lrelu(ev) - m1);
        s2 += expf(lrelu(ev * g_mw[e]) - m2);
    }
    for (int o = 16; o; o >>= 1) {
        s1 += __shfl_xor_sync(0xffffffffu, s1, o);
        s2 += __shfl_xor_sync(0xffffffffu, s2, o);
    }
    if (lane == 0) { g_m21[n] = m1; g_s21[n] = s1; g_m22[n] = m2; g_s22[n] = s2; }
}

__global__ void k_alpha2(int E) {
    int e = blockIdx.x * blockDim.x + threadIdx.x;
    int EP = E + NN;
    if (e >= EP) return;
    int s = (e < E) ? g_src[e] : (e - E);
    int d = (e < E) ? g_dst[e] : (e - E);
    float ev = g_s2s[s] + g_s2d[d];
    float l1 = lrelu(ev);
    float l2 = lrelu(ev * g_mw[e]);
    g_a2[e] = 0.5f * expf(l1 - g_m21[d]) / (g_s21[d] + 1e-16f)
            + 0.5f * expf(l2 - g_m22[d]) / (g_s22[d] + 1e-16f);
}

__global__ void k_agg2(const float* __restrict__ b2, float* __restrict__ out, int E) {
    int n = blockIdx.x;
    int c = threadIdx.x;  // 0..255
    float acc = 0.f;
    int p0 = g_dptr[n], p1 = g_dptr[n + 1];
    for (int i = p0; i < p1; i++) {
        int e = g_eidx[i];
        int s = (e < E) ? g_src[e] : (e - E);
        acc += g_a2[e] * g_h2w[s * OUTC + c];
    }
    // out already holds residual h2 @ resW2 (written by k_gemm3)
    out[n * OUTC + c] = out[n * OUTC + c] + acc + b2[c];
}

// ------------------------- launch --------------------------------------------
extern "C" void kernel_launch(void* const* d_in, const int* in_sizes, int n_in,
                              void* d_out, int out_size) {
    const float* x    = (const float*)d_in[0];
    const void*  ei   = d_in[1];
    const float* W1   = (const float*)d_in[2];
    const float* as1  = (const float*)d_in[3];
    const float* ad1  = (const float*)d_in[4];
    const float* b1   = (const float*)d_in[5];
    const float* W2   = (const float*)d_in[6];
    const float* as2  = (const float*)d_in[7];
    const float* ad2  = (const float*)d_in[8];
    const float* b2   = (const float*)d_in[9];
    const float* rW2  = (const float*)d_in[10];
    float* out = (float*)d_out;

    int E = in_sizes[1] / 2;
    int EP = E + NN;

    k_detect<<<1, 1024>>>(ei);
    k_convert<<<(E + 255) / 256, 256>>>(ei, E);
    k_zero_all<<<2048, 256>>>();
    k_bitmap<<<(EP + 255) / 256, 256>>>(E);
    k_deg<<<16, 256>>>();
    k_scan4096<<<1, 1024>>>(0);
    k_fillcols<<<16, 256>>>();
    k_spmv<<<16, 256>>>(0);
    k_spmv<<<16, 256>>>(1);
    k_a2<<<NN, 64>>>();
    k_mw<<<(EP + 127) / 128, 128>>>(E);

    k_gemm1<<<dim3(INC / BN, NN / BM), 256>>>(x, W1);
    k_s1<<<(NN * NHEADS + 255) / 256, 256>>>(as1, ad1);

    k_hist<<<(EP + 255) / 256, 256>>>(E);
    k_scan4096<<<1, 1024>>>(1);
    k_zerohist<<<16, 256>>>();
    k_scatter<<<(EP + 255) / 256, 256>>>(E);

    k_maxsum1<<<NN, 256>>>(E);
    k_alpha1<<<(EP * NHEADS + 255) / 256, 256>>>(E);
    k_agg1<<<NN, 512>>>(b1, E);

    k_gemm2<<<dim3(OUTC / BN, NN / BM), 256>>>(W2);
    k_gemm3<<<dim3(OUTC / BN, NN / BM), 256>>>(rW2, out);
    k_s2<<<16, 256>>>(as2, ad2);
    k_maxsum2<<<NN, 32>>>(E);
    k_alpha2<<<(EP + 255) / 256, 256>>>(E);
    k_agg2<<<NN, 256>>>(b2, out, E);
}

// round 2
// speedup vs baseline: 1.3616x; 1.3616x over previous
#include <cuda_runtime.h>
#include <math.h>

#define NN 4096
#define EE_MAX 131072
#define EPMAX (EE_MAX + NN)
#define INC 512
#define NHEADS 8
#define HID 64
#define OUTC 256
#define WORDS (NN / 32)
#define NEG 0.2f

// ------------------------- device scratch (static, no allocs) ---------------
__device__ unsigned g_is64;
__device__ int g_src[EE_MAX], g_dst[EE_MAX];
__device__ unsigned g_adj[NN * WORDS];            // 2 MB bitmap A[s][d]
__device__ int g_deg[NN];
__device__ int g_rowptr[NN + 1];
__device__ int g_cols[EPMAX];                     // deduped CSR (src -> dst), sorted
__device__ float g_d1[NN], g_d2[NN], g_d3[NN];    // A*1, A^2*1, A^3*1 (row sums)
__device__ float g_A2[NN * NN];                   // 64 MB dense A@A (small int counts)
__device__ float g_mw[EPMAX];                     // motif weight per edge (incl self loops)
__device__ float g_h1[NN * INC];                  // x @ W1
__device__ float g_h2[NN * INC];                  // elu(layer1 out)
__device__ float g_h2w[NN * OUTC];                // h2 @ W2
__device__ float g_s1s[NN * NHEADS], g_s1d[NN * NHEADS];
__device__ float g_s2s[NN], g_s2d[NN];
__device__ int g_hist[NN];
__device__ int g_dptr[NN + 1];                    // CSR over dst for E' edges
__device__ int g_eidx[EPMAX];
__device__ float g_max1[NN * NHEADS], g_sum1[NN * NHEADS];
__device__ float g_max2[NN * NHEADS], g_sum2[NN * NHEADS];
__device__ float g_a1[EPMAX * NHEADS];            // layer1 alphas
__device__ float g_m21[NN], g_s21[NN], g_m22[NN], g_s22[NN];
__device__ float g_a2[EPMAX];                     // layer2 alphas

// ------------------------- edge dtype detect / convert ----------------------
__global__ void k_detect(const void* p) {
    __shared__ int any;
    if (threadIdx.x == 0) any = 0;
    __syncthreads();
    const int* w = (const int*)p;
    if (w[2 * threadIdx.x + 1] != 0) any = 1;
    __syncthreads();
    if (threadIdx.x == 0) g_is64 = (any == 0) ? 1u : 0u;
}

__global__ void k_convert(const void* p, int E) {
    int i = blockIdx.x * blockDim.x + threadIdx.x;
    if (i >= E) return;
    if (g_is64) {
        const long long* q = (const long long*)p;
        g_src[i] = (int)q[i];
        g_dst[i] = (int)q[E + i];
    } else {
        const int* q = (const int*)p;
        g_src[i] = q[i];
        g_dst[i] = q[E + i];
    }
}

// ------------------------- zeroing -----------------------------------------
__global__ void k_zero_all() {
    int stride = gridDim.x * blockDim.x;
    int gid = blockIdx.x * blockDim.x + threadIdx.x;
    float4 z = make_float4(0.f, 0.f, 0.f, 0.f);
    float4* A2v = (float4*)g_A2;
    for (int i = gid; i < NN * NN / 4; i += stride) A2v[i] = z;
    uint4* adjv = (uint4*)g_adj;
    uint4 zu = make_uint4(0u, 0u, 0u, 0u);
    for (int i = gid; i < NN * WORDS / 4; i += stride) adjv[i] = zu;
    for (int i = gid; i < NN; i += stride) g_hist[i] = 0;
}

__global__ void k_zerohist() {
    int i = blockIdx.x * blockDim.x + threadIdx.x;
    if (i < NN) g_hist[i] = 0;
}

// ------------------------- adjacency ----------------------------------------
__global__ void k_bitmap(int E) {
    int i = blockIdx.x * blockDim.x + threadIdx.x;
    int EP = E + NN;
    if (i >= EP) return;
    int s, d;
    if (i < E) { s = g_src[i]; d = g_dst[i]; }
    else { s = i - E; d = i - E; }
    atomicOr(&g_adj[s * WORDS + (d >> 5)], 1u << (d & 31));
}

__global__ void k_deg() {
    int r = blockIdx.x * blockDim.x + threadIdx.x;
    if (r >= NN) return;
    int c = 0;
    for (int w = 0; w < WORDS; w++) c += __popc(g_adj[r * WORDS + w]);
    g_deg[r] = c;
    g_d1[r] = (float)c;
}

// single-block exclusive scan of 4096 ints; which=0: deg->rowptr, 1: hist->dptr
__global__ void k_scan4096(int which) {
    __shared__ int s[1024];
    const int* in = which ? g_hist : g_deg;
    int* out = which ? g_dptr : g_rowptr;
    int tid = threadIdx.x;
    int base = tid * 4;
    int loc[4];
    int tot = 0;
#pragma unroll
    for (int i = 0; i < 4; i++) { loc[i] = tot; tot += in[base + i]; }
    s[tid] = tot;
    __syncthreads();
    for (int off = 1; off < 1024; off <<= 1) {
        int t = (tid >= off) ? s[tid - off] : 0;
        __syncthreads();
        s[tid] += t;
        __syncthreads();
    }
    int pre = (tid == 0) ? 0 : s[tid - 1];
#pragma unroll
    for (int i = 0; i < 4; i++) out[base + i] = pre + loc[i];
    if (tid == 1023) out[4096] = s[1023];
}

__global__ void k_fillcols() {
    int r = blockIdx.x * blockDim.x + threadIdx.x;
    if (r >= NN) return;
    int p = g_rowptr[r];
    for (int w = 0; w < WORDS; w++) {
        unsigned m = g_adj[r * WORDS + w];
        while (m) {
            int b = __ffs(m) - 1;
            g_cols[p++] = w * 32 + b;
            m &= m - 1;
        }
    }
}

// which=0: d2 = A*d1 ; which=1: d3 = A*d2
__global__ void k_spmv(int which) {
    int r = blockIdx.x * blockDim.x + threadIdx.x;
    if (r >= NN) return;
    const float* vin = which ? g_d2 : g_d1;
    float s = 0.f;
    int p1 = g_rowptr[r + 1];
    for (int i = g_rowptr[r]; i < p1; i++) s += vin[g_cols[i]];
    if (which) g_d3[r] = s; else g_d2[r] = s;
}

// A2[k][d] += 1 for each 2-path k->m->d
__global__ void k_a2() {
    int k = blockIdx.x;
    int p0 = g_rowptr[k], p1 = g_rowptr[k + 1];
    float* row = g_A2 + k * NN;
    for (int mi = p0; mi < p1; mi++) {
        int m = g_cols[mi];
        int q0 = g_rowptr[m], q1 = g_rowptr[m + 1];
        for (int j = q0 + threadIdx.x; j < q1; j += blockDim.x)
            atomicAdd(&row[g_cols[j]], 1.0f);
    }
}

// mw[e] = A^3[s,d] / max(rowsum(A^3)[s], 1)
__global__ void k_mw(int E) {
    int e = blockIdx.x * blockDim.x + threadIdx.x;
    int EP = E + NN;
    if (e >= EP) return;
    int s = (e < E) ? g_src[e] : (e - E);
    int d = (e < E) ? g_dst[e] : (e - E);
    float a3 = 0.f;
    int p1 = g_rowptr[s + 1];
    for (int i = g_rowptr[s]; i < p1; i++) a3 += g_A2[g_cols[i] * NN + d];
    float nm = g_d3[s];
    if (nm < 1.f) nm = 1.f;
    g_mw[e] = a3 / nm;
}

// ------------------------- GEMM (128x128x16, 8x8/thread, fp32) --------------
#define GBM 128
#define GBN 128
#define GBK 16
#define ASTR (GBM + 4)

__device__ __forceinline__ void gemm_core(const float* __restrict__ A, int K,
                                          const float* __restrict__ B, int ldb, int col0,
                                          float* __restrict__ C, int ldc) {
    __shared__ float As[GBK][ASTR];   // As[k][m] (transposed A tile)
    __shared__ float Bs[GBK][GBN];
    int tid = threadIdx.x;
    int tx = tid & 15, ty = tid >> 4;
    int row0 = blockIdx.y * GBM;
    float acc[8][8] = {};
    for (int k0 = 0; k0 < K; k0 += GBK) {
        // A tile: 128 rows x 16 k, float4 along K, scatter-transpose to As
#pragma unroll
        for (int l = 0; l < 2; l++) {
            int f = tid + l * 256;          // float4 slot, 512 total
            int r = f >> 2;
            int c = (f & 3) << 2;
            float4 v = *(const float4*)&A[(row0 + r) * K + k0 + c];
            As[c + 0][r] = v.x;
            As[c + 1][r] = v.y;
            As[c + 2][r] = v.z;
            As[c + 3][r] = v.w;
        }
        // B tile: 16 rows x 128 cols, direct float4
#pragma unroll
        for (int l = 0; l < 2; l++) {
            int f = tid + l * 256;
            int r = f >> 5;
            int c = (f & 31) << 2;
            *(float4*)&Bs[r][c] = *(const float4*)&B[(k0 + r) * ldb + col0 + c];
        }
        __syncthreads();
#pragma unroll
        for (int kk = 0; kk < GBK; kk++) {
            float a[8], b[8];
            *(float4*)&a[0] = *(const float4*)&As[kk][ty * 8];
            *(float4*)&a[4] = *(const float4*)&As[kk][ty * 8 + 4];
            *(float4*)&b[0] = *(const float4*)&Bs[kk][tx * 8];
            *(float4*)&b[4] = *(const float4*)&Bs[kk][tx * 8 + 4];
#pragma unroll
            for (int i = 0; i < 8; i++)
#pragma unroll
                for (int j = 0; j < 8; j++) acc[i][j] += a[i] * b[j];
        }
        __syncthreads();
    }
#pragma unroll
    for (int i = 0; i < 8; i++) {
        float* cp = &C[(row0 + ty * 8 + i) * ldc + col0 + tx * 8];
        *(float4*)&cp[0] = make_float4(acc[i][0], acc[i][1], acc[i][2], acc[i][3]);
        *(float4*)&cp[4] = make_float4(acc[i][4], acc[i][5], acc[i][6], acc[i][7]);
    }
}

__global__ void __launch_bounds__(256) k_gemm1(const float* __restrict__ x,
                                               const float* __restrict__ W1) {
    gemm_core(x, INC, W1, INC, blockIdx.x * GBN, g_h1, INC);
}

// fused: cols 0-255 -> g_h2w = h2 @ W2 ; cols 256-511 -> out = h2 @ resW2
__global__ void __launch_bounds__(256) k_gemm23(const float* __restrict__ W2,
                                                const float* __restrict__ rW,
                                                float* __restrict__ out) {
    int bx = blockIdx.x;
    const float* B = (bx < 2) ? W2 : rW;
    float* C = (bx < 2) ? g_h2w : out;
    int col0 = (bx & 1) * GBN;
    gemm_core(g_h2, INC, B, OUTC, col0, C, OUTC);
}

// ------------------------- attention scores ----------------------------------
__global__ void k_s1(const float* __restrict__ as1, const float* __restrict__ ad1) {
    int i = blockIdx.x * blockDim.x + threadIdx.x;
    if (i >= NN * NHEADS) return;
    int n = i / NHEADS, h = i % NHEADS;
    const float* hp = g_h1 + n * INC + h * HID;
    float ss = 0.f, sd = 0.f;
    for (int c = 0; c < HID; c++) {
        float v = hp[c];
        ss += v * as1[h * HID + c];
        sd += v * ad1[h * HID + c];
    }
    g_s1s[i] = ss;
    g_s1d[i] = sd;
}

__global__ void k_s2(const float* __restrict__ as2, const float* __restrict__ ad2) {
    int n = blockIdx.x * blockDim.x + threadIdx.x;
    if (n >= NN) return;
    const float* hp = g_h2w + n * OUTC;
    float ss = 0.f, sd = 0.f;
    for (int c = 0; c < OUTC; c++) {
        float v = hp[c];
        ss += v * as2[c];
        sd += v * ad2[c];
    }
    g_s2s[n] = ss;
    g_s2d[n] = sd;
}

// ------------------------- dst CSR -------------------------------------------
__global__ void k_hist(int E) {
    int e = blockIdx.x * blockDim.x + threadIdx.x;
    int EP = E + NN;
    if (e >= EP) return;
    int d = (e < E) ? g_dst[e] : (e - E);
    atomicAdd(&g_hist[d], 1);
}

__global__ void k_scatter(int E) {
    int e = blockIdx.x * blockDim.x + threadIdx.x;
    int EP = E + NN;
    if (e >= EP) return;
    int d = (e < E) ? g_dst[e] : (e - E);
    int pos = g_dptr[d] + atomicAdd(&g_hist[d], 1);
    g_eidx[pos] = e;
}

// ------------------------- layer1 softmax stats ------------------------------
__device__ __forceinline__ float lrelu(float x) { return x > 0.f ? x : NEG * x; }

__global__ void k_maxsum1(int E) {
    int n = blockIdx.x;
    int h = threadIdx.x >> 5;
    int lane = threadIdx.x & 31;
    int p0 = g_dptr[n], p1 = g_dptr[n + 1];
    float sd = g_s1d[n * NHEADS + h];
    float m1 = -1e30f, m2 = -1e30f;
    for (int i = p0 + lane; i < p1; i += 32) {
        int e = g_eidx[i];
        int s = (e < E) ? g_src[e] : (e - E);
        float ev = g_s1s[s * NHEADS + h] + sd;
        float l1 = lrelu(ev);
        float l2 = lrelu(ev * g_mw[e]);
        m1 = fmaxf(m1, l1);
        m2 = fmaxf(m2, l2);
    }
    for (int o = 16; o; o >>= 1) {
        m1 = fmaxf(m1, __shfl_xor_sync(0xffffffffu, m1, o));
        m2 = fmaxf(m2, __shfl_xor_sync(0xffffffffu, m2, o));
    }
    float s1 = 0.f, s2 = 0.f;
    for (int i = p0 + lane; i < p1; i += 32) {
        int e = g_eidx[i];
        int s = (e < E) ? g_src[e] : (e - E);
        float ev = g_s1s[s * NHEADS + h] + sd;
        s1 += expf(lrelu(ev) - m1);
        s2 += expf(lrelu(ev * g_mw[e]) - m2);
    }
    for (int o = 16; o; o >>= 1) {
        s1 += __shfl_xor_sync(0xffffffffu, s1, o);
        s2 += __shfl_xor_sync(0xffffffffu, s2, o);
    }
    if (lane == 0) {
        g_max1[n * NHEADS + h] = m1;
        g_sum1[n * NHEADS + h] = s1;
        g_max2[n * NHEADS + h] = m2;
        g_sum2[n * NHEADS + h] = s2;
    }
}

__global__ void k_alpha1(int E) {
    int i = blockIdx.x * blockDim.x + threadIdx.x;
    int EP = E + NN;
    if (i >= EP * NHEADS) return;
    int e = i / NHEADS, h = i % NHEADS;
    int s = (e < E) ? g_src[e] : (e - E);
    int d = (e < E) ? g_dst[e] : (e - E);
    float ev = g_s1s[s * NHEADS + h] + g_s1d[d * NHEADS + h];
    float l1 = lrelu(ev);
    float l2 = lrelu(ev * g_mw[e]);
    float a = 0.5f * expf(l1 - g_max1[d * NHEADS + h]) / (g_sum1[d * NHEADS + h] + 1e-16f)
            + 0.5f * expf(l2 - g_max2[d * NHEADS + h]) / (g_sum2[d * NHEADS + h] + 1e-16f);
    g_a1[i] = a;
}

__global__ void k_agg1(const float* __restrict__ b1, int E) {
    int n = blockIdx.x;
    int j = threadIdx.x;  // 0..511 -> (head = j/64, ch = j%64)
    int h = j >> 6;
    float acc = 0.f;
    int p0 = g_dptr[n], p1 = g_dptr[n + 1];
    for (int i = p0; i < p1; i++) {
        int e = g_eidx[i];
        int s = (e < E) ? g_src[e] : (e - E);
        acc += g_a1[e * NHEADS + h] * g_h1[s * INC + j];
    }
    float v = acc + b1[j];
    g_h2[n * INC + j] = v > 0.f ? v : expm1f(v);  // elu
}

// ------------------------- layer 2 -------------------------------------------
__global__ void k_maxsum2(int E) {
    int n = blockIdx.x;
    int lane = threadIdx.x;
    int p0 = g_dptr[n], p1 = g_dptr[n + 1];
    float sd = g_s2d[n];
    float m1 = -1e30f, m2 = -1e30f;
    for (int i = p0 + lane; i < p1; i += 32) {
        int e = g_eidx[i];
        int s = (e < E) ? g_src[e] : (e - E);
        float ev = g_s2s[s] + sd;
        m1 = fmaxf(m1, lrelu(ev));
        m2 = fmaxf(m2, lrelu(ev * g_mw[e]));
    }
    for (int o = 16; o; o >>= 1) {
        m1 = fmaxf(m1, __shfl_xor_sync(0xffffffffu, m1, o));
        m2 = fmaxf(m2, __shfl_xor_sync(0xffffffffu, m2, o));
    }
    float s1 = 0.f, s2 = 0.f;
    for (int i = p0 + lane; i < p1; i += 32) {
        int e = g_eidx[i];
        int s = (e < E) ? g_src[e] : (e - E);
        float ev = g_s2s[s] + sd;
        s1 += expf(lrelu(ev) - m1);
        s2 += expf(lrelu(ev * g_mw[e]) - m2);
    }
    for (int o = 16; o; o >>= 1) {
        s1 += __shfl_xor_sync(0xffffffffu, s1, o);
        s2 += __shfl_xor_sync(0xffffffffu, s2, o);
    }
    if (lane == 0) { g_m21[n] = m1; g_s21[n] = s1; g_m22[n] = m2; g_s22[n] = s2; }
}

__global__ void k_alpha2(int E) {
    int e = blockIdx.x * blockDim.x + threadIdx.x;
    int EP = E + NN;
    if (e >= EP) return;
    int s = (e < E) ? g_src[e] : (e - E);
    int d = (e < E) ? g_dst[e] : (e - E);
    float ev = g_s2s[s] + g_s2d[d];
    float l1 = lrelu(ev);
    float l2 = lrelu(ev * g_mw[e]);
    g_a2[e] = 0.5f * expf(l1 - g_m21[d]) / (g_s21[d] + 1e-16f)
            + 0.5f * expf(l2 - g_m22[d]) / (g_s22[d] + 1e-16f);
}

__global__ void k_agg2(const float* __restrict__ b2, float* __restrict__ out, int E) {
    int n = blockIdx.x;
    int c = threadIdx.x;  // 0..255
    float acc = 0.f;
    int p0 = g_dptr[n], p1 = g_dptr[n + 1];
    for (int i = p0; i < p1; i++) {
        int e = g_eidx[i];
        int s = (e < E) ? g_src[e] : (e - E);
        acc += g_a2[e] * g_h2w[s * OUTC + c];
    }
    out[n * OUTC + c] = out[n * OUTC + c] + acc + b2[c];
}

// ------------------------- launch --------------------------------------------
extern "C" void kernel_launch(void* const* d_in, const int* in_sizes, int n_in,
                              void* d_out, int out_size) {
    const float* x    = (const float*)d_in[0];
    const void*  ei   = d_in[1];
    const float* W1   = (const float*)d_in[2];
    const float* as1  = (const float*)d_in[3];
    const float* ad1  = (const float*)d_in[4];
    const float* b1   = (const float*)d_in[5];
    const float* W2   = (const float*)d_in[6];
    const float* as2  = (const float*)d_in[7];
    const float* ad2  = (const float*)d_in[8];
    const float* b2   = (const float*)d_in[9];
    const float* rW2  = (const float*)d_in[10];
    float* out = (float*)d_out;

    int E = in_sizes[1] / 2;
    int EP = E + NN;

    k_detect<<<1, 1024>>>(ei);
    k_convert<<<(E + 255) / 256, 256>>>(ei, E);
    k_zero_all<<<2048, 256>>>();
    k_bitmap<<<(EP + 255) / 256, 256>>>(E);
    k_deg<<<16, 256>>>();
    k_scan4096<<<1, 1024>>>(0);
    k_fillcols<<<16, 256>>>();
    k_spmv<<<16, 256>>>(0);
    k_spmv<<<16, 256>>>(1);
    k_a2<<<NN, 128>>>();
    k_mw<<<(EP + 127) / 128, 128>>>(E);

    k_gemm1<<<dim3(INC / GBN, NN / GBM), 256>>>(x, W1);
    k_s1<<<(NN * NHEADS + 255) / 256, 256>>>(as1, ad1);

    k_hist<<<(EP + 255) / 256, 256>>>(E);
    k_scan4096<<<1, 1024>>>(1);
    k_zerohist<<<16, 256>>>();
    k_scatter<<<(EP + 255) / 256, 256>>>(E);

    k_maxsum1<<<NN, 256>>>(E);
    k_alpha1<<<(EP * NHEADS + 255) / 256, 256>>>(E);
    k_agg1<<<NN, 512>>>(b1, E);

    k_gemm23<<<dim3(4, NN / GBM), 256>>>(W2, rW2, out);
    k_s2<<<16, 256>>>(as2, ad2);
    k_maxsum2<<<NN, 32>>>(E);
    k_alpha2<<<(EP + 255) / 256, 256>>>(E);
    k_agg2<<<NN, 256>>>(b2, out, E);
}

// round 3
// speedup vs baseline: 1.5821x; 1.1619x over previous
#include <cuda_runtime.h>
#include <cuda_bf16.h>
#include <math.h>

#define NN 4096
#define EE_MAX 131072
#define EPMAX (EE_MAX + NN)
#define INC 512
#define NHEADS 8
#define HID 64
#define OUTC 256
#define WORDS (NN / 32)
#define NEG 0.2f

// ------------------------- device scratch (static, no allocs) ---------------
__device__ unsigned g_is64;
__device__ int g_src[EE_MAX], g_dst[EE_MAX];
__device__ unsigned g_adj[NN * WORDS];
__device__ int g_deg[NN];
__device__ int g_rowptr[NN + 1];
__device__ int g_cols[EPMAX];
__device__ float g_d1[NN], g_d2[NN], g_d3[NN];
__device__ float g_A2[NN * NN];                   // 64 MB dense A@A
__device__ float g_mw[EPMAX];
__device__ float g_h1[NN * INC];
__device__ float g_h2[NN * INC];
__device__ float g_h2w[NN * OUTC];
__device__ float g_s1s[NN * NHEADS], g_s1d[NN * NHEADS];
__device__ float g_s2s[NN], g_s2d[NN];
__device__ int g_hist[NN];
__device__ int g_dptr[NN + 1];
__device__ int g_eidx[EPMAX];
__device__ float g_max1[NN * NHEADS], g_sum1[NN * NHEADS];
__device__ float g_max2[NN * NHEADS], g_sum2[NN * NHEADS];
__device__ float g_a1[EPMAX * NHEADS];
__device__ float g_m21[NN], g_s21[NN], g_m22[NN], g_s22[NN];
__device__ float g_a2[EPMAX];

// bf16 split operands (hi + lo), 16B aligned for float4 loads
__device__ __align__(16) __nv_bfloat16 g_xhi[NN * INC], g_xlo[NN * INC];
__device__ __align__(16) __nv_bfloat16 g_w1hi[INC * INC], g_w1lo[INC * INC];
__device__ __align__(16) __nv_bfloat16 g_w2hi[INC * OUTC], g_w2lo[INC * OUTC];
__device__ __align__(16) __nv_bfloat16 g_rwhi[INC * OUTC], g_rwlo[INC * OUTC];
__device__ __align__(16) __nv_bfloat16 g_h2hi[NN * INC], g_h2lo[NN * INC];

// ------------------------- edge dtype detect / convert ----------------------
__global__ void k_detect(const void* p) {
    __shared__ int any;
    if (threadIdx.x == 0) any = 0;
    __syncthreads();
    const int* w = (const int*)p;
    if (w[2 * threadIdx.x + 1] != 0) any = 1;
    __syncthreads();
    if (threadIdx.x == 0) g_is64 = (any == 0) ? 1u : 0u;
}

__global__ void k_convert(const void* p, int E) {
    int i = blockIdx.x * blockDim.x + threadIdx.x;
    if (i >= E) return;
    if (g_is64) {
        const long long* q = (const long long*)p;
        g_src[i] = (int)q[i];
        g_dst[i] = (int)q[E + i];
    } else {
        const int* q = (const int*)p;
        g_src[i] = q[i];
        g_dst[i] = q[E + i];
    }
}

// ------------------------- fp32 -> (hi,lo) bf16 split ------------------------
__global__ void k_split(const float* __restrict__ src, __nv_bfloat16* __restrict__ hi,
                        __nv_bfloat16* __restrict__ lo, int n) {
    int i = blockIdx.x * blockDim.x + threadIdx.x;
    if (i >= n) return;
    float v = src[i];
    __nv_bfloat16 h = __float2bfloat16(v);
    hi[i] = h;
    lo[i] = __float2bfloat16(v - __bfloat162float(h));
}

// ------------------------- zeroing -----------------------------------------
__global__ void k_zero_all() {
    int stride = gridDim.x * blockDim.x;
    int gid = blockIdx.x * blockDim.x + threadIdx.x;
    float4 z = make_float4(0.f, 0.f, 0.f, 0.f);
    float4* A2v = (float4*)g_A2;
    for (int i = gid; i < NN * NN / 4; i += stride) A2v[i] = z;
    uint4* adjv = (uint4*)g_adj;
    uint4 zu = make_uint4(0u, 0u, 0u, 0u);
    for (int i = gid; i < NN * WORDS / 4; i += stride) adjv[i] = zu;
    for (int i = gid; i < NN; i += stride) g_hist[i] = 0;
}

__global__ void k_zerohist() {
    int i = blockIdx.x * blockDim.x + threadIdx.x;
    if (i < NN) g_hist[i] = 0;
}

// ------------------------- adjacency ----------------------------------------
__global__ void k_bitmap(int E) {
    int i = blockIdx.x * blockDim.x + threadIdx.x;
    int EP = E + NN;
    if (i >= EP) return;
    int s, d;
    if (i < E) { s = g_src[i]; d = g_dst[i]; }
    else { s = i - E; d = i - E; }
    atomicOr(&g_adj[s * WORDS + (d >> 5)], 1u << (d & 31));
}

__global__ void k_deg() {
    int r = blockIdx.x * blockDim.x + threadIdx.x;
    if (r >= NN) return;
    int c = 0;
    for (int w = 0; w < WORDS; w++) c += __popc(g_adj[r * WORDS + w]);
    g_deg[r] = c;
    g_d1[r] = (float)c;
}

__global__ void k_scan4096(int which) {
    __shared__ int s[1024];
    const int* in = which ? g_hist : g_deg;
    int* out = which ? g_dptr : g_rowptr;
    int tid = threadIdx.x;
    int base = tid * 4;
    int loc[4];
    int tot = 0;
#pragma unroll
    for (int i = 0; i < 4; i++) { loc[i] = tot; tot += in[base + i]; }
    s[tid] = tot;
    __syncthreads();
    for (int off = 1; off < 1024; off <<= 1) {
        int t = (tid >= off) ? s[tid - off] : 0;
        __syncthreads();
        s[tid] += t;
        __syncthreads();
    }
    int pre = (tid == 0) ? 0 : s[tid - 1];
#pragma unroll
    for (int i = 0; i < 4; i++) out[base + i] = pre + loc[i];
    if (tid == 1023) out[4096] = s[1023];
}

__global__ void k_fillcols() {
    int r = blockIdx.x * blockDim.x + threadIdx.x;
    if (r >= NN) return;
    int p = g_rowptr[r];
    for (int w = 0; w < WORDS; w++) {
        unsigned m = g_adj[r * WORDS + w];
        while (m) {
            int b = __ffs(m) - 1;
            g_cols[p++] = w * 32 + b;
            m &= m - 1;
        }
    }
}

__global__ void k_spmv(int which) {
    int r = blockIdx.x * blockDim.x + threadIdx.x;
    if (r >= NN) return;
    const float* vin = which ? g_d2 : g_d1;
    float s = 0.f;
    int p1 = g_rowptr[r + 1];
    for (int i = g_rowptr[r]; i < p1; i++) s += vin[g_cols[i]];
    if (which) g_d3[r] = s; else g_d2[r] = s;
}

__global__ void k_a2() {
    int k = blockIdx.x;
    int p0 = g_rowptr[k], p1 = g_rowptr[k + 1];
    float* row = g_A2 + k * NN;
    for (int mi = p0; mi < p1; mi++) {
        int m = g_cols[mi];
        int q0 = g_rowptr[m], q1 = g_rowptr[m + 1];
        for (int j = q0 + threadIdx.x; j < q1; j += blockDim.x)
            atomicAdd(&row[g_cols[j]], 1.0f);
    }
}

__global__ void k_mw(int E) {
    int e = blockIdx.x * blockDim.x + threadIdx.x;
    int EP = E + NN;
    if (e >= EP) return;
    int s = (e < E) ? g_src[e] : (e - E);
    int d = (e < E) ? g_dst[e] : (e - E);
    float a3 = 0.f;
    int p1 = g_rowptr[s + 1];
    for (int i = g_rowptr[s]; i < p1; i++) a3 += g_A2[g_cols[i] * NN + d];
    float nm = g_d3[s];
    if (nm < 1.f) nm = 1.f;
    g_mw[e] = a3 / nm;
}

// ------------------------- split-bf16 tensor-core GEMM -----------------------
// C[M,N] = Ahi*Bhi + Ahi*Blo + Alo*Bhi, fp32 accum, block 128x128, 8 warps.
#define PAD_A 40     // As pitch in bf16 elems ([m][k], k-tile 32)
#define PITCH_B 136  // Bs pitch in bf16 elems ([k][n], n-tile 128)

__device__ __forceinline__ void mma_bf16(float* c, const unsigned* a, const unsigned* b) {
    asm volatile(
        "mma.sync.aligned.m16n8k16.row.col.f32.bf16.bf16.f32 "
        "{%0,%1,%2,%3}, {%4,%5,%6,%7}, {%8,%9}, {%0,%1,%2,%3};"
        : "+f"(c[0]), "+f"(c[1]), "+f"(c[2]), "+f"(c[3])
        : "r"(a[0]), "r"(a[1]), "r"(a[2]), "r"(a[3]), "r"(b[0]), "r"(b[1]));
}

__device__ __forceinline__ void gemm_split(const __nv_bfloat16* __restrict__ Ahi,
                                           const __nv_bfloat16* __restrict__ Alo,
                                           const __nv_bfloat16* __restrict__ Bhi,
                                           const __nv_bfloat16* __restrict__ Blo,
                                           int ldb, int col0,
                                           float* __restrict__ C, int ldc, int row0) {
    __shared__ __nv_bfloat16 As[2][128 * PAD_A];
    __shared__ __nv_bfloat16 Bs[2][32 * PITCH_B];
    int tid = threadIdx.x;
    int wid = tid >> 5, lane = tid & 31;
    int wm = (wid >> 2) * 64;
    int wn = (wid & 3) * 32;
    int g = lane >> 2, q = lane & 3;
    float acc[4][4][4] = {};

    for (int k0 = 0; k0 < INC; k0 += 32) {
#pragma unroll
        for (int l = 0; l < 2; l++) {
            int slot = tid + l * 256;               // 512 slots: A tile 128x32
            int r = slot >> 2, cg = (slot & 3) << 3;
            const float4* ph = (const float4*)&Ahi[(row0 + r) * INC + k0 + cg];
            const float4* pl = (const float4*)&Alo[(row0 + r) * INC + k0 + cg];
            *(float4*)&As[0][r * PAD_A + cg] = *ph;
            *(float4*)&As[1][r * PAD_A + cg] = *pl;
        }
#pragma unroll
        for (int l = 0; l < 2; l++) {
            int slot = tid + l * 256;               // B tile 32x128
            int kr = slot >> 4, ng = (slot & 15) << 3;
            const float4* ph = (const float4*)&Bhi[(k0 + kr) * ldb + col0 + ng];
            const float4* pl = (const float4*)&Blo[(k0 + kr) * ldb + col0 + ng];
            *(float4*)&Bs[0][kr * PITCH_B + ng] = *ph;
            *(float4*)&Bs[1][kr * PITCH_B + ng] = *pl;
        }
        __syncthreads();
#pragma unroll
        for (int ks = 0; ks < 2; ks++) {
            int kb = ks * 16;
            unsigned ah[4][4], al[4][4], bh[4][2], bl[4][2];
#pragma unroll
            for (int i = 0; i < 4; i++) {
                int m = wm + i * 16 + g;
                int o0 = m * PAD_A + kb + q * 2;
                int o1 = (m + 8) * PAD_A + kb + q * 2;
                ah[i][0] = *(const unsigned*)&As[0][o0];
                ah[i][1] = *(const unsigned*)&As[0][o1];
                ah[i][2] = *(const unsigned*)&As[0][o0 + 8];
                ah[i][3] = *(const unsigned*)&As[0][o1 + 8];
                al[i][0] = *(const unsigned*)&As[1][o0];
                al[i][1] = *(const unsigned*)&As[1][o1];
                al[i][2] = *(const unsigned*)&As[1][o0 + 8];
                al[i][3] = *(const unsigned*)&As[1][o1 + 8];
            }
#pragma unroll
            for (int j = 0; j < 4; j++) {
                int n = wn + j * 8 + g;
                int k2 = kb + q * 2;
#pragma unroll
                for (int t = 0; t < 2; t++) {
                    int kk = k2 + t * 8;
                    unsigned h0 = *(const unsigned short*)&Bs[0][kk * PITCH_B + n];
                    unsigned h1 = *(const unsigned short*)&Bs[0][(kk + 1) * PITCH_B + n];
                    bh[j][t] = h0 | (h1 << 16);
                    unsigned l0 = *(const unsigned short*)&Bs[1][kk * PITCH_B + n];
                    unsigned l1 = *(const unsigned short*)&Bs[1][(kk + 1) * PITCH_B + n];
                    bl[j][t] = l0 | (l1 << 16);
                }
            }
#pragma unroll
            for (int i = 0; i < 4; i++)
#pragma unroll
                for (int j = 0; j < 4; j++) {
                    mma_bf16(acc[i][j], ah[i], bh[j]);
                    mma_bf16(acc[i][j], ah[i], bl[j]);
                    mma_bf16(acc[i][j], al[i], bh[j]);
                }
        }
        __syncthreads();
    }
    // epilogue: c0,c1 -> (row, col..col+1); c2,c3 -> (row+8, ...)
#pragma unroll
    for (int i = 0; i < 4; i++)
#pragma unroll
        for (int j = 0; j < 4; j++) {
            int r = row0 + wm + i * 16 + g;
            int c = col0 + wn + j * 8 + q * 2;
            C[r * ldc + c] = acc[i][j][0];
            C[r * ldc + c + 1] = acc[i][j][1];
            C[(r + 8) * ldc + c] = acc[i][j][2];
            C[(r + 8) * ldc + c + 1] = acc[i][j][3];
        }
}

__global__ void __launch_bounds__(256) k_gemm1() {
    gemm_split(g_xhi, g_xlo, g_w1hi, g_w1lo, INC, blockIdx.x * 128, g_h1, INC,
               blockIdx.y * 128);
}

// bx 0,1: g_h2w = h2 @ W2 ; bx 2,3: out = h2 @ resW2
__global__ void __launch_bounds__(256) k_gemm23(float* __restrict__ out) {
    int bx = blockIdx.x;
    const __nv_bfloat16* Bh = (bx < 2) ? g_w2hi : g_rwhi;
    const __nv_bfloat16* Bl = (bx < 2) ? g_w2lo : g_rwlo;
    float* C = (bx < 2) ? g_h2w : out;
    gemm_split(g_h2hi, g_h2lo, Bh, Bl, OUTC, (bx & 1) * 128, C, OUTC, blockIdx.y * 128);
}

// ------------------------- attention scores ----------------------------------
__global__ void k_s1(const float* __restrict__ as1, const float* __restrict__ ad1) {
    int i = blockIdx.x * blockDim.x + threadIdx.x;
    if (i >= NN * NHEADS) return;
    int n = i / NHEADS, h = i % NHEADS;
    const float* hp = g_h1 + n * INC + h * HID;
    float ss = 0.f, sd = 0.f;
    for (int c = 0; c < HID; c++) {
        float v = hp[c];
        ss += v * as1[h * HID + c];
        sd += v * ad1[h * HID + c];
    }
    g_s1s[i] = ss;
    g_s1d[i] = sd;
}

__global__ void k_s2(const float* __restrict__ as2, const float* __restrict__ ad2) {
    int n = blockIdx.x * blockDim.x + threadIdx.x;
    if (n >= NN) return;
    const float* hp = g_h2w + n * OUTC;
    float ss = 0.f, sd = 0.f;
    for (int c = 0; c < OUTC; c++) {
        float v = hp[c];
        ss += v * as2[c];
        sd += v * ad2[c];
    }
    g_s2s[n] = ss;
    g_s2d[n] = sd;
}

// ------------------------- dst CSR -------------------------------------------
__global__ void k_hist(int E) {
    int e = blockIdx.x * blockDim.x + threadIdx.x;
    int EP = E + NN;
    if (e >= EP) return;
    int d = (e < E) ? g_dst[e] : (e - E);
    atomicAdd(&g_hist[d], 1);
}

__global__ void k_scatter(int E) {
    int e = blockIdx.x * blockDim.x + threadIdx.x;
    int EP = E + NN;
    if (e >= EP) return;
    int d = (e < E) ? g_dst[e] : (e - E);
    int pos = g_dptr[d] + atomicAdd(&g_hist[d], 1);
    g_eidx[pos] = e;
}

// ------------------------- layer1 softmax stats ------------------------------
__device__ __forceinline__ float lrelu(float x) { return x > 0.f ? x : NEG * x; }

__global__ void k_maxsum1(int E) {
    int n = blockIdx.x;
    int h = threadIdx.x >> 5;
    int lane = threadIdx.x & 31;
    int p0 = g_dptr[n], p1 = g_dptr[n + 1];
    float sd = g_s1d[n * NHEADS + h];
    float m1 = -1e30f, m2 = -1e30f;
    for (int i = p0 + lane; i < p1; i += 32) {
        int e = g_eidx[i];
        int s = (e < E) ? g_src[e] : (e - E);
        float ev = g_s1s[s * NHEADS + h] + sd;
        m1 = fmaxf(m1, lrelu(ev));
        m2 = fmaxf(m2, lrelu(ev * g_mw[e]));
    }
    for (int o = 16; o; o >>= 1) {
        m1 = fmaxf(m1, __shfl_xor_sync(0xffffffffu, m1, o));
        m2 = fmaxf(m2, __shfl_xor_sync(0xffffffffu, m2, o));
    }
    float s1 = 0.f, s2 = 0.f;
    for (int i = p0 + lane; i < p1; i += 32) {
        int e = g_eidx[i];
        int s = (e < E) ? g_src[e] : (e - E);
        float ev = g_s1s[s * NHEADS + h] + sd;
        s1 += expf(lrelu(ev) - m1);
        s2 += expf(lrelu(ev * g_mw[e]) - m2);
    }
    for (int o = 16; o; o >>= 1) {
        s1 += __shfl_xor_sync(0xffffffffu, s1, o);
        s2 += __shfl_xor_sync(0xffffffffu, s2, o);
    }
    if (lane == 0) {
        g_max1[n * NHEADS + h] = m1;
        g_sum1[n * NHEADS + h] = s1;
        g_max2[n * NHEADS + h] = m2;
        g_sum2[n * NHEADS + h] = s2;
    }
}

__global__ void k_alpha1(int E) {
    int i = blockIdx.x * blockDim.x + threadIdx.x;
    int EP = E + NN;
    if (i >= EP * NHEADS) return;
    int e = i / NHEADS, h = i % NHEADS;
    int s = (e < E) ? g_src[e] : (e - E);
    int d = (e < E) ? g_dst[e] : (e - E);
    float ev = g_s1s[s * NHEADS + h] + g_s1d[d * NHEADS + h];
    float l1 = lrelu(ev);
    float l2 = lrelu(ev * g_mw[e]);
    float a = 0.5f * expf(l1 - g_max1[d * NHEADS + h]) / (g_sum1[d * NHEADS + h] + 1e-16f)
            + 0.5f * expf(l2 - g_max2[d * NHEADS + h]) / (g_sum2[d * NHEADS + h] + 1e-16f);
    g_a1[i] = a;
}

__global__ void k_agg1(const float* __restrict__ b1, int E) {
    int n = blockIdx.x;
    int j = threadIdx.x;
    int h = j >> 6;
    float acc = 0.f;
    int p0 = g_dptr[n], p1 = g_dptr[n + 1];
    for (int i = p0; i < p1; i++) {
        int e = g_eidx[i];
        int s = (e < E) ? g_src[e] : (e - E);
        acc += g_a1[e * NHEADS + h] * g_h1[s * INC + j];
    }
    float v = acc + b1[j];
    g_h2[n * INC + j] = v > 0.f ? v : expm1f(v);
}

// ------------------------- layer 2 -------------------------------------------
__global__ void k_maxsum2(int E) {
    int n = blockIdx.x;
    int lane = threadIdx.x;
    int p0 = g_dptr[n], p1 = g_dptr[n + 1];
    float sd = g_s2d[n];
    float m1 = -1e30f, m2 = -1e30f;
    for (int i = p0 + lane; i < p1; i += 32) {
        int e = g_eidx[i];
        int s = (e < E) ? g_src[e] : (e - E);
        float ev = g_s2s[s] + sd;
        m1 = fmaxf(m1, lrelu(ev));
        m2 = fmaxf(m2, lrelu(ev * g_mw[e]));
    }
    for (int o = 16; o; o >>= 1) {
        m1 = fmaxf(m1, __shfl_xor_sync(0xffffffffu, m1, o));
        m2 = fmaxf(m2, __shfl_xor_sync(0xffffffffu, m2, o));
    }
    float s1 = 0.f, s2 = 0.f;
    for (int i = p0 + lane; i < p1; i += 32) {
        int e = g_eidx[i];
        int s = (e < E) ? g_src[e] : (e - E);
        float ev = g_s2s[s] + sd;
        s1 += expf(lrelu(ev) - m1);
        s2 += expf(lrelu(ev * g_mw[e]) - m2);
    }
    for (int o = 16; o; o >>= 1) {
        s1 += __shfl_xor_sync(0xffffffffu, s1, o);
        s2 += __shfl_xor_sync(0xffffffffu, s2, o);
    }
    if (lane == 0) { g_m21[n] = m1; g_s21[n] = s1; g_m22[n] = m2; g_s22[n] = s2; }
}

__global__ void k_alpha2(int E) {
    int e = blockIdx.x * blockDim.x + threadIdx.x;
    int EP = E + NN;
    if (e >= EP) return;
    int s = (e < E) ? g_src[e] : (e - E);
    int d = (e < E) ? g_dst[e] : (e - E);
    float ev = g_s2s[s] + g_s2d[d];
    float l1 = lrelu(ev);
    float l2 = lrelu(ev * g_mw[e]);
    g_a2[e] = 0.5f * expf(l1 - g_m21[d]) / (g_s21[d] + 1e-16f)
            + 0.5f * expf(l2 - g_m22[d]) / (g_s22[d] + 1e-16f);
}

__global__ void k_agg2(const float* __restrict__ b2, float* __restrict__ out, int E) {
    int n = blockIdx.x;
    int c = threadIdx.x;
    float acc = 0.f;
    int p0 = g_dptr[n], p1 = g_dptr[n + 1];
    for (int i = p0; i < p1; i++) {
        int e = g_eidx[i];
        int s = (e < E) ? g_src[e] : (e - E);
        acc += g_a2[e] * g_h2w[s * OUTC + c];
    }
    out[n * OUTC + c] = out[n * OUTC + c] + acc + b2[c];
}

// ------------------------- launch --------------------------------------------
extern "C" void kernel_launch(void* const* d_in, const int* in_sizes, int n_in,
                              void* d_out, int out_size) {
    const float* x    = (const float*)d_in[0];
    const void*  ei   = d_in[1];
    const float* W1   = (const float*)d_in[2];
    const float* as1  = (const float*)d_in[3];
    const float* ad1  = (const float*)d_in[4];
    const float* b1   = (const float*)d_in[5];
    const float* W2   = (const float*)d_in[6];
    const float* as2  = (const float*)d_in[7];
    const float* ad2  = (const float*)d_in[8];
    const float* b2   = (const float*)d_in[9];
    const float* rW2  = (const float*)d_in[10];
    float* out = (float*)d_out;

    int E = in_sizes[1] / 2;
    int EP = E + NN;

    k_detect<<<1, 1024>>>(ei);
    k_convert<<<(E + 255) / 256, 256>>>(ei, E);
    k_zero_all<<<2048, 256>>>();

    // split conversions for GEMM operands (independent of motif chain)
    {
        __nv_bfloat16 *xhi, *xlo, *w1hi, *w1lo, *w2hi, *w2lo, *rwhi, *rwlo;
        cudaGetSymbolAddress((void**)&xhi, g_xhi);
        cudaGetSymbolAddress((void**)&xlo, g_xlo);
        cudaGetSymbolAddress((void**)&w1hi, g_w1hi);
        cudaGetSymbolAddress((void**)&w1lo, g_w1lo);
        cudaGetSymbolAddress((void**)&w2hi, g_w2hi);
        cudaGetSymbolAddress((void**)&w2lo, g_w2lo);
        cudaGetSymbolAddress((void**)&rwhi, g_rwhi);
        cudaGetSymbolAddress((void**)&rwlo, g_rwlo);
        k_split<<<(NN * INC + 255) / 256, 256>>>(x, xhi, xlo, NN * INC);
        k_split<<<(INC * INC + 255) / 256, 256>>>(W1, w1hi, w1lo, INC * INC);
        k_split<<<(INC * OUTC + 255) / 256, 256>>>(W2, w2hi, w2lo, INC * OUTC);
        k_split<<<(INC * OUTC + 255) / 256, 256>>>(rW2, rwhi, rwlo, INC * OUTC);
    }

    k_bitmap<<<(EP + 255) / 256, 256>>>(E);
    k_deg<<<16, 256>>>();
    k_scan4096<<<1, 1024>>>(0);
    k_fillcols<<<16, 256>>>();
    k_spmv<<<16, 256>>>(0);
    k_spmv<<<16, 256>>>(1);
    k_a2<<<NN, 128>>>();
    k_mw<<<(EP + 127) / 128, 128>>>(E);

    k_gemm1<<<dim3(INC / 128, NN / 128), 256>>>();
    k_s1<<<(NN * NHEADS + 255) / 256, 256>>>(as1, ad1);

    k_hist<<<(EP + 255) / 256, 256>>>(E);
    k_scan4096<<<1, 1024>>>(1);
    k_zerohist<<<16, 256>>>();
    k_scatter<<<(EP + 255) / 256, 256>>>(E);

    k_maxsum1<<<NN, 256>>>(E);
    k_alpha1<<<(EP * NHEADS + 255) / 256, 256>>>(E);
    k_agg1<<<NN, 512>>>(b1, E);

    {
        __nv_bfloat16 *h2hi, *h2lo;
        cudaGetSymbolAddress((void**)&h2hi, g_h2hi);
        cudaGetSymbolAddress((void**)&h2lo, g_h2lo);
        float* h2;
        cudaGetSymbolAddress((void**)&h2, g_h2);
        k_split<<<(NN * INC + 255) / 256, 256>>>(h2, h2hi, h2lo, NN * INC);
    }

    k_gemm23<<<dim3(4, NN / 128), 256>>>(out);
    k_s2<<<16, 256>>>(as2, ad2);
    k_maxsum2<<<NN, 32>>>(E);
    k_alpha2<<<(EP + 255) / 256, 256>>>(E);
    k_agg2<<<NN, 256>>>(b2, out, E);
}

// round 4
// speedup vs baseline: 1.8003x; 1.1379x over previous
#include <cuda_runtime.h>
#include <cuda_bf16.h>
#include <math.h>

#define NN 4096
#define EE_MAX 131072
#define EPMAX (EE_MAX + NN)
#define INC 512
#define NHEADS 8
#define HID 64
#define OUTC 256
#define WORDS (NN / 32)
#define NEG 0.2f

// ------------------------- device scratch (static, no allocs) ---------------
__device__ int g_src[EE_MAX], g_dst[EE_MAX];
__device__ unsigned g_adj[NN * WORDS];
__device__ int g_deg[NN];
__device__ int g_rowptr[NN + 1];
__device__ int g_cols[EPMAX];
__device__ float g_d1[NN], g_d2[NN], g_d3[NN];
__device__ __align__(16) unsigned short g_A2h[NN * NN];   // 32 MB dense A@A (u16 counts)
__device__ float g_mw[EPMAX];
__device__ float g_h1[NN * INC];
__device__ float g_h2[NN * INC];
__device__ float g_h2w[NN * OUTC];
__device__ float g_s1s[NN * NHEADS], g_s1d[NN * NHEADS];
__device__ float g_s2s[NN], g_s2d[NN];
__device__ int g_hist[NN];
__device__ int g_dptr[NN + 1];
__device__ int g_eidx[EPMAX];
__device__ float g_a1[EPMAX * NHEADS];
__device__ float g_a2[EPMAX];

// bf16 split operands (hi + lo), 16B aligned for float4 loads
__device__ __align__(16) __nv_bfloat16 g_xhi[NN * INC], g_xlo[NN * INC];
__device__ __align__(16) __nv_bfloat16 g_w1hi[INC * INC], g_w1lo[INC * INC];
__device__ __align__(16) __nv_bfloat16 g_w2hi[INC * OUTC], g_w2lo[INC * OUTC];
__device__ __align__(16) __nv_bfloat16 g_rwhi[INC * OUTC], g_rwlo[INC * OUTC];
__device__ __align__(16) __nv_bfloat16 g_h2hi[NN * INC], g_h2lo[NN * INC];

// ------------------------- edge convert (detect inline) ----------------------
__global__ void k_convert(const void* p, int E) {
    // per-block int64 detection: if data is int64 (values < 4096), every odd
    // 32-bit word of the first 2048 words is 0.
    __shared__ int any;
    if (threadIdx.x == 0) any = 0;
    __syncthreads();
    const int* w = (const int*)p;
#pragma unroll
    for (int t = 0; t < 4; t++) {
        int idx = threadIdx.x + t * 256;
        if (w[2 * idx + 1] != 0) any = 1;
    }
    __syncthreads();
    bool is64 = (any == 0);
    int i = blockIdx.x * blockDim.x + threadIdx.x;
    if (i >= E) return;
    if (is64) {
        const long long* q = (const long long*)p;
        g_src[i] = (int)q[i];
        g_dst[i] = (int)q[E + i];
    } else {
        const int* q = (const int*)p;
        g_src[i] = q[i];
        g_dst[i] = q[E + i];
    }
}

// ------------------------- fp32 -> (hi,lo) bf16 split, 8 elems/thread --------
__global__ void k_split(const float* __restrict__ src, __nv_bfloat16* __restrict__ hi,
                        __nv_bfloat16* __restrict__ lo, int n8) {
    int i = blockIdx.x * blockDim.x + threadIdx.x;
    if (i >= n8) return;
    const float4* s4 = (const float4*)src;
    float4 v0 = s4[2 * i], v1 = s4[2 * i + 1];
    float f[8] = {v0.x, v0.y, v0.z, v0.w, v1.x, v1.y, v1.z, v1.w};
    __nv_bfloat16 h[8], l[8];
#pragma unroll
    for (int k = 0; k < 8; k++) {
        h[k] = __float2bfloat16(f[k]);
        l[k] = __float2bfloat16(f[k] - __bfloat162float(h[k]));
    }
    ((uint4*)hi)[i] = *(uint4*)h;
    ((uint4*)lo)[i] = *(uint4*)l;
}

// ------------------------- zeroing -----------------------------------------
__global__ void k_zero_all() {
    int stride = gridDim.x * blockDim.x;
    int gid = blockIdx.x * blockDim.x + threadIdx.x;
    uint4 zu = make_uint4(0u, 0u, 0u, 0u);
    uint4* A2v = (uint4*)g_A2h;
    for (int i = gid; i < NN * NN / 8; i += stride) A2v[i] = zu;
    uint4* adjv = (uint4*)g_adj;
    for (int i = gid; i < NN * WORDS / 4; i += stride) adjv[i] = zu;
    for (int i = gid; i < NN; i += stride) g_hist[i] = 0;
}

__global__ void k_zerohist() {
    int i = blockIdx.x * blockDim.x + threadIdx.x;
    if (i < NN) g_hist[i] = 0;
}

// ------------------------- adjacency + dst histogram -------------------------
__global__ void k_bitmap(int E) {
    int i = blockIdx.x * blockDim.x + threadIdx.x;
    int EP = E + NN;
    if (i >= EP) return;
    int s, d;
    if (i < E) { s = g_src[i]; d = g_dst[i]; }
    else { s = i - E; d = i - E; }
    atomicOr(&g_adj[s * WORDS + (d >> 5)], 1u << (d & 31));
    atomicAdd(&g_hist[d], 1);   // dst-CSR histogram (per-edge, not deduped)
}

__global__ void k_deg() {
    int r = blockIdx.x * blockDim.x + threadIdx.x;
    if (r >= NN) return;
    int c = 0;
    for (int w = 0; w < WORDS; w++) c += __popc(g_adj[r * WORDS + w]);
    g_deg[r] = c;
    g_d1[r] = (float)c;
}

// single-block exclusive scan of 4096 ints; which=0: deg->rowptr, 1: hist->dptr
__global__ void k_scan4096(int which) {
    __shared__ int s[1024];
    const int* in = which ? g_hist : g_deg;
    int* out = which ? g_dptr : g_rowptr;
    int tid = threadIdx.x;
    int base = tid * 4;
    int loc[4];
    int tot = 0;
#pragma unroll
    for (int i = 0; i < 4; i++) { loc[i] = tot; tot += in[base + i]; }
    s[tid] = tot;
    __syncthreads();
    for (int off = 1; off < 1024; off <<= 1) {
        int t = (tid >= off) ? s[tid - off] : 0;
        __syncthreads();
        s[tid] += t;
        __syncthreads();
    }
    int pre = (tid == 0) ? 0 : s[tid - 1];
#pragma unroll
    for (int i = 0; i < 4; i++) out[base + i] = pre + loc[i];
    if (tid == 1023) out[4096] = s[1023];
}

__global__ void k_fillcols() {
    int r = blockIdx.x * blockDim.x + threadIdx.x;
    if (r >= NN) return;
    int p = g_rowptr[r];
    for (int w = 0; w < WORDS; w++) {
        unsigned m = g_adj[r * WORDS + w];
        while (m) {
            int b = __ffs(m) - 1;
            g_cols[p++] = w * 32 + b;
            m &= m - 1;
        }
    }
}

__global__ void k_spmv(int which) {
    int r = blockIdx.x * blockDim.x + threadIdx.x;
    if (r >= NN) return;
    const float* vin = which ? g_d2 : g_d1;
    float s = 0.f;
    int p1 = g_rowptr[r + 1];
    for (int i = g_rowptr[r]; i < p1; i++) s += vin[g_cols[i]];
    if (which) g_d3[r] = s; else g_d2[r] = s;
}

// A2[k][d] += 1 for each 2-path k->m->d (u16 lanes via u32 atomics)
__global__ void k_a2() {
    int k = blockIdx.x;
    int p0 = g_rowptr[k], p1 = g_rowptr[k + 1];
    unsigned* roww = (unsigned*)(g_A2h + (size_t)k * NN);
    for (int mi = p0; mi < p1; mi++) {
        int m = g_cols[mi];
        int q0 = g_rowptr[m], q1 = g_rowptr[m + 1];
        for (int j = q0 + threadIdx.x; j < q1; j += blockDim.x) {
            int d = g_cols[j];
            atomicAdd(&roww[d >> 1], (d & 1) ? 0x10000u : 1u);
        }
    }
}

// mw[e] = A^3[s,d] / max(rowsum(A^3)[s], 1)
__global__ void k_mw(int E) {
    int e = blockIdx.x * blockDim.x + threadIdx.x;
    int EP = E + NN;
    if (e >= EP) return;
    int s = (e < E) ? g_src[e] : (e - E);
    int d = (e < E) ? g_dst[e] : (e - E);
    float a3 = 0.f;
    int p1 = g_rowptr[s + 1];
    for (int i = g_rowptr[s]; i < p1; i++)
        a3 += (float)g_A2h[(size_t)g_cols[i] * NN + d];
    float nm = g_d3[s];
    if (nm < 1.f) nm = 1.f;
    g_mw[e] = a3 / nm;
}

// ------------------------- split-bf16 tensor-core GEMM -----------------------
#define PAD_A 40
#define PITCH_B 136

__device__ __forceinline__ void mma_bf16(float* c, const unsigned* a, const unsigned* b) {
    asm volatile(
        "mma.sync.aligned.m16n8k16.row.col.f32.bf16.bf16.f32 "
        "{%0,%1,%2,%3}, {%4,%5,%6,%7}, {%8,%9}, {%0,%1,%2,%3};"
        : "+f"(c[0]), "+f"(c[1]), "+f"(c[2]), "+f"(c[3])
        : "r"(a[0]), "r"(a[1]), "r"(a[2]), "r"(a[3]), "r"(b[0]), "r"(b[1]));
}

__device__ __forceinline__ void gemm_split(const __nv_bfloat16* __restrict__ Ahi,
                                           const __nv_bfloat16* __restrict__ Alo,
                                           const __nv_bfloat16* __restrict__ Bhi,
                                           const __nv_bfloat16* __restrict__ Blo,
                                           int ldb, int col0,
                                           float* __restrict__ C, int ldc, int row0) {
    __shared__ __nv_bfloat16 As[2][128 * PAD_A];
    __shared__ __nv_bfloat16 Bs[2][32 * PITCH_B];
    int tid = threadIdx.x;
    int wid = tid >> 5, lane = tid & 31;
    int wm = (wid >> 2) * 64;
    int wn = (wid & 3) * 32;
    int g = lane >> 2, q = lane & 3;
    float acc[4][4][4] = {};

    for (int k0 = 0; k0 < INC; k0 += 32) {
#pragma unroll
        for (int l = 0; l < 2; l++) {
            int slot = tid + l * 256;
            int r = slot >> 2, cg = (slot & 3) << 3;
            *(float4*)&As[0][r * PAD_A + cg] = *(const float4*)&Ahi[(row0 + r) * INC + k0 + cg];
            *(float4*)&As[1][r * PAD_A + cg] = *(const float4*)&Alo[(row0 + r) * INC + k0 + cg];
        }
#pragma unroll
        for (int l = 0; l < 2; l++) {
            int slot = tid + l * 256;
            int kr = slot >> 4, ng = (slot & 15) << 3;
            *(float4*)&Bs[0][kr * PITCH_B + ng] = *(const float4*)&Bhi[(k0 + kr) * ldb + col0 + ng];
            *(float4*)&Bs[1][kr * PITCH_B + ng] = *(const float4*)&Blo[(k0 + kr) * ldb + col0 + ng];
        }
        __syncthreads();
#pragma unroll
        for (int ks = 0; ks < 2; ks++) {
            int kb = ks * 16;
            unsigned ah[4][4], al[4][4], bh[4][2], bl[4][2];
#pragma unroll
            for (int i = 0; i < 4; i++) {
                int m = wm + i * 16 + g;
                int o0 = m * PAD_A + kb + q * 2;
                int o1 = (m + 8) * PAD_A + kb + q * 2;
                ah[i][0] = *(const unsigned*)&As[0][o0];
                ah[i][1] = *(const unsigned*)&As[0][o1];
                ah[i][2] = *(const unsigned*)&As[0][o0 + 8];
                ah[i][3] = *(const unsigned*)&As[0][o1 + 8];
                al[i][0] = *(const unsigned*)&As[1][o0];
                al[i][1] = *(const unsigned*)&As[1][o1];
                al[i][2] = *(const unsigned*)&As[1][o0 + 8];
                al[i][3] = *(const unsigned*)&As[1][o1 + 8];
            }
#pragma unroll
            for (int j = 0; j < 4; j++) {
                int n = wn + j * 8 + g;
                int k2 = kb + q * 2;
#pragma unroll
                for (int t = 0; t < 2; t++) {
                    int kk = k2 + t * 8;
                    unsigned h0 = *(const unsigned short*)&Bs[0][kk * PITCH_B + n];
                    unsigned h1 = *(const unsigned short*)&Bs[0][(kk + 1) * PITCH_B + n];
                    bh[j][t] = h0 | (h1 << 16);
                    unsigned l0 = *(const unsigned short*)&Bs[1][kk * PITCH_B + n];
                    unsigned l1 = *(const unsigned short*)&Bs[1][(kk + 1) * PITCH_B + n];
                    bl[j][t] = l0 | (l1 << 16);
                }
            }
#pragma unroll
            for (int i = 0; i < 4; i++)
#pragma unroll
                for (int j = 0; j < 4; j++) {
                    mma_bf16(acc[i][j], ah[i], bh[j]);
                    mma_bf16(acc[i][j], ah[i], bl[j]);
                    mma_bf16(acc[i][j], al[i], bh[j]);
                }
        }
        __syncthreads();
    }
#pragma unroll
    for (int i = 0; i < 4; i++)
#pragma unroll
        for (int j = 0; j < 4; j++) {
            int r = row0 + wm + i * 16 + g;
            int c = col0 + wn + j * 8 + q * 2;
            C[r * ldc + c] = acc[i][j][0];
            C[r * ldc + c + 1] = acc[i][j][1];
            C[(r + 8) * ldc + c] = acc[i][j][2];
            C[(r + 8) * ldc + c + 1] = acc[i][j][3];
        }
}

__global__ void __launch_bounds__(256) k_gemm1() {
    gemm_split(g_xhi, g_xlo, g_w1hi, g_w1lo, INC, blockIdx.x * 128, g_h1, INC,
               blockIdx.y * 128);
}

__global__ void __launch_bounds__(256) k_gemm23(float* __restrict__ out) {
    int bx = blockIdx.x;
    const __nv_bfloat16* Bh = (bx < 2) ? g_w2hi : g_rwhi;
    const __nv_bfloat16* Bl = (bx < 2) ? g_w2lo : g_rwlo;
    float* C = (bx < 2) ? g_h2w : out;
    gemm_split(g_h2hi, g_h2lo, Bh, Bl, OUTC, (bx & 1) * 128, C, OUTC, blockIdx.y * 128);
}

// ------------------------- attention scores ----------------------------------
__global__ void k_s1(const float* __restrict__ as1, const float* __restrict__ ad1) {
    int i = blockIdx.x * blockDim.x + threadIdx.x;
    if (i >= NN * NHEADS) return;
    int n = i / NHEADS, h = i % NHEADS;
    const float4* hp = (const float4*)(g_h1 + n * INC + h * HID);
    const float4* asp = (const float4*)(as1 + h * HID);
    const float4* adp = (const float4*)(ad1 + h * HID);
    float ss = 0.f, sd = 0.f;
#pragma unroll
    for (int c = 0; c < HID / 4; c++) {
        float4 v = hp[c], a = asp[c], d = adp[c];
        ss += v.x * a.x + v.y * a.y + v.z * a.z + v.w * a.w;
        sd += v.x * d.x + v.y * d.y + v.z * d.z + v.w * d.w;
    }
    g_s1s[i] = ss;
    g_s1d[i] = sd;
}

__global__ void k_s2(const float* __restrict__ as2, const float* __restrict__ ad2) {
    int n = blockIdx.x * blockDim.x + threadIdx.x;
    if (n >= NN) return;
    const float4* hp = (const float4*)(g_h2w + n * OUTC);
    const float4* asp = (const float4*)as2;
    const float4* adp = (const float4*)ad2;
    float ss = 0.f, sd = 0.f;
#pragma unroll
    for (int c = 0; c < OUTC / 4; c++) {
        float4 v = hp[c], a = asp[c], d = adp[c];
        ss += v.x * a.x + v.y * a.y + v.z * a.z + v.w * a.w;
        sd += v.x * d.x + v.y * d.y + v.z * d.z + v.w * d.w;
    }
    g_s2s[n] = ss;
    g_s2d[n] = sd;
}

// ------------------------- dst CSR scatter -----------------------------------
__global__ void k_scatter(int E) {
    int e = blockIdx.x * blockDim.x + threadIdx.x;
    int EP = E + NN;
    if (e >= EP) return;
    int d = (e < E) ? g_dst[e] : (e - E);
    int pos = g_dptr[d] + atomicAdd(&g_hist[d], 1);
    g_eidx[pos] = e;
}

// ------------------------- layer1 softmax (max+sum+alpha fused) --------------
__device__ __forceinline__ float lrelu(float x) { return x > 0.f ? x : NEG * x; }

__global__ void k_softmax1(int E) {
    int n = blockIdx.x;
    int h = threadIdx.x >> 5;
    int lane = threadIdx.x & 31;
    int p0 = g_dptr[n], p1 = g_dptr[n + 1];
    float sd = g_s1d[n * NHEADS + h];
    float m1 = -1e30f, m2 = -1e30f;
    for (int i = p0 + lane; i < p1; i += 32) {
        int e = g_eidx[i];
        int s = (e < E) ? g_src[e] : (e - E);
        float ev = g_s1s[s * NHEADS + h] + sd;
        m1 = fmaxf(m1, lrelu(ev));
        m2 = fmaxf(m2, lrelu(ev * g_mw[e]));
    }
    for (int o = 16; o; o >>= 1) {
        m1 = fmaxf(m1, __shfl_xor_sync(0xffffffffu, m1, o));
        m2 = fmaxf(m2, __shfl_xor_sync(0xffffffffu, m2, o));
    }
    float s1 = 0.f, s2 = 0.f;
    for (int i = p0 + lane; i < p1; i += 32) {
        int e = g_eidx[i];
        int s = (e < E) ? g_src[e] : (e - E);
        float ev = g_s1s[s * NHEADS + h] + sd;
        s1 += expf(lrelu(ev) - m1);
        s2 += expf(lrelu(ev * g_mw[e]) - m2);
    }
    for (int o = 16; o; o >>= 1) {
        s1 += __shfl_xor_sync(0xffffffffu, s1, o);
        s2 += __shfl_xor_sync(0xffffffffu, s2, o);
    }
    float r1 = 0.5f / (s1 + 1e-16f);
    float r2 = 0.5f / (s2 + 1e-16f);
    for (int i = p0 + lane; i < p1; i += 32) {
        int e = g_eidx[i];
        int s = (e < E) ? g_src[e] : (e - E);
        float ev = g_s1s[s * NHEADS + h] + sd;
        g_a1[e * NHEADS + h] = expf(lrelu(ev) - m1) * r1
                             + expf(lrelu(ev * g_mw[e]) - m2) * r2;
    }
}

__global__ void k_agg1(const float* __restrict__ b1, int E) {
    int n = blockIdx.x;
    int j = threadIdx.x;
    int h = j >> 6;
    float acc = 0.f;
    int p0 = g_dptr[n], p1 = g_dptr[n + 1];
    for (int i = p0; i < p1; i++) {
        int e = g_eidx[i];
        int s = (e < E) ? g_src[e] : (e - E);
        acc += g_a1[e * NHEADS + h] * g_h1[s * INC + j];
    }
    float v = acc + b1[j];
    g_h2[n * INC + j] = v > 0.f ? v : expm1f(v);
}

// ------------------------- layer 2 (max+sum+alpha fused) ---------------------
__global__ void k_softmax2(int E) {
    int n = blockIdx.x;
    int lane = threadIdx.x;
    int p0 = g_dptr[n], p1 = g_dptr[n + 1];
    float sd = g_s2d[n];
    float m1 = -1e30f, m2 = -1e30f;
    for (int i = p0 + lane; i < p1; i += 32) {
        int e = g_eidx[i];
        int s = (e < E) ? g_src[e] : (e - E);
        float ev = g_s2s[s] + sd;
        m1 = fmaxf(m1, lrelu(ev));
        m2 = fmaxf(m2, lrelu(ev * g_mw[e]));
    }
    for (int o = 16; o; o >>= 1) {
        m1 = fmaxf(m1, __shfl_xor_sync(0xffffffffu, m1, o));
        m2 = fmaxf(m2, __shfl_xor_sync(0xffffffffu, m2, o));
    }
    float s1 = 0.f, s2 = 0.f;
    for (int i = p0 + lane; i < p1; i += 32) {
        int e = g_eidx[i];
        int s = (e < E) ? g_src[e] : (e - E);
        float ev = g_s2s[s] + sd;
        s1 += expf(lrelu(ev) - m1);
        s2 += expf(lrelu(ev * g_mw[e]) - m2);
    }
    for (int o = 16; o; o >>= 1) {
        s1 += __shfl_xor_sync(0xffffffffu, s1, o);
        s2 += __shfl_xor_sync(0xffffffffu, s2, o);
    }
    float r1 = 0.5f / (s1 + 1e-16f);
    float r2 = 0.5f / (s2 + 1e-16f);
    for (int i = p0 + lane; i < p1; i += 32) {
        int e = g_eidx[i];
        int s = (e < E) ? g_src[e] : (e - E);
        float ev = g_s2s[s] + sd;
        g_a2[e] = expf(lrelu(ev) - m1) * r1 + expf(lrelu(ev * g_mw[e]) - m2) * r2;
    }
}

__global__ void k_agg2(const float* __restrict__ b2, float* __restrict__ out, int E) {
    int n = blockIdx.x;
    int c = threadIdx.x;
    float acc = 0.f;
    int p0 = g_dptr[n], p1 = g_dptr[n + 1];
    for (int i = p0; i < p1; i++) {
        int e = g_eidx[i];
        int s = (e < E) ? g_src[e] : (e - E);
        acc += g_a2[e] * g_h2w[s * OUTC + c];
    }
    out[n * OUTC + c] = out[n * OUTC + c] + acc + b2[c];
}

// ------------------------- launch --------------------------------------------
extern "C" void kernel_launch(void* const* d_in, const int* in_sizes, int n_in,
                              void* d_out, int out_size) {
    const float* x    = (const float*)d_in[0];
    const void*  ei   = d_in[1];
    const float* W1   = (const float*)d_in[2];
    const float* as1  = (const float*)d_in[3];
    const float* ad1  = (const float*)d_in[4];
    const float* b1   = (const float*)d_in[5];
    const float* W2   = (const float*)d_in[6];
    const float* as2  = (const float*)d_in[7];
    const float* ad2  = (const float*)d_in[8];
    const float* b2   = (const float*)d_in[9];
    const float* rW2  = (const float*)d_in[10];
    float* out = (float*)d_out;

    int E = in_sizes[1] / 2;
    int EP = E + NN;

    k_convert<<<(E + 255) / 256, 256>>>(ei, E);
    k_zero_all<<<1024, 256>>>();

    {
        __nv_bfloat16 *xhi, *xlo, *w1hi, *w1lo, *w2hi, *w2lo, *rwhi, *rwlo;
        cudaGetSymbolAddress((void**)&xhi, g_xhi);
        cudaGetSymbolAddress((void**)&xlo, g_xlo);
        cudaGetSymbolAddress((void**)&w1hi, g_w1hi);
        cudaGetSymbolAddress((void**)&w1lo, g_w1lo);
        cudaGetSymbolAddress((void**)&w2hi, g_w2hi);
        cudaGetSymbolAddress((void**)&w2lo, g_w2lo);
        cudaGetSymbolAddress((void**)&rwhi, g_rwhi);
        cudaGetSymbolAddress((void**)&rwlo, g_rwlo);
        k_split<<<(NN * INC / 8 + 255) / 256, 256>>>(x, xhi, xlo, NN * INC / 8);
        k_split<<<(INC * INC / 8 + 255) / 256, 256>>>(W1, w1hi, w1lo, INC * INC / 8);
        k_split<<<(INC * OUTC / 8 + 255) / 256, 256>>>(W2, w2hi, w2lo, INC * OUTC / 8);
        k_split<<<(INC * OUTC / 8 + 255) / 256, 256>>>(rW2, rwhi, rwlo, INC * OUTC / 8);
    }

    k_bitmap<<<(EP + 255) / 256, 256>>>(E);
    k_deg<<<16, 256>>>();
    k_scan4096<<<1, 1024>>>(0);
    k_fillcols<<<16, 256>>>();
    k_spmv<<<16, 256>>>(0);
    k_spmv<<<16, 256>>>(1);
    k_a2<<<NN, 128>>>();
    k_mw<<<(EP + 127) / 128, 128>>>(E);

    k_gemm1<<<dim3(INC / 128, NN / 128), 256>>>();
    k_s1<<<(NN * NHEADS + 255) / 256, 256>>>(as1, ad1);

    k_scan4096<<<1, 1024>>>(1);
    k_zerohist<<<16, 256>>>();
    k_scatter<<<(EP + 255) / 256, 256>>>(E);

    k_softmax1<<<NN, 256>>>(E);
    k_agg1<<<NN, 512>>>(b1, E);

    {
        __nv_bfloat16 *h2hi, *h2lo;
        cudaGetSymbolAddress((void**)&h2hi, g_h2hi);
        cudaGetSymbolAddress((void**)&h2lo, g_h2lo);
        float* h2;
        cudaGetSymbolAddress((void**)&h2, g_h2);
        k_split<<<(NN * INC / 8 + 255) / 256, 256>>>(h2, h2hi, h2lo, NN * INC / 8);
    }

    k_gemm23<<<dim3(4, NN / 128), 256>>>(out);
    k_s2<<<16, 256>>>(as2, ad2);
    k_softmax2<<<NN, 32>>>(E);
    k_agg2<<<NN, 256>>>(b2, out, E);
}

// round 5
// speedup vs baseline: 2.1968x; 1.2202x over previous
#include <cuda_runtime.h>
#include <cuda_bf16.h>
#include <math.h>

#define NN 4096
#define EE_MAX 131072
#define EPMAX (EE_MAX + NN)
#define INC 512
#define NHEADS 8
#define HID 64
#define OUTC 256
#define WORDS (NN / 32)
#define NEG 0.2f

// ------------------------- device scratch (static, no allocs) ---------------
__device__ int g_src[EE_MAX], g_dst[EE_MAX];
__device__ unsigned g_adj[NN * WORDS];
__device__ int g_deg[NN];
__device__ int g_rowptr[NN + 1];
__device__ int g_cols[EPMAX];
__device__ float g_d1[NN], g_d2[NN], g_d3[NN];
__device__ __align__(16) unsigned short g_A2h[NN * NN];   // 32 MB dense A@A (u16)
__device__ float g_mw[EPMAX];
__device__ float g_h1[NN * INC];
__device__ float g_h2[NN * INC];
__device__ float g_h2w[NN * OUTC];
__device__ float g_s1s[NN * NHEADS], g_s1d[NN * NHEADS];
__device__ float g_s2s[NN], g_s2d[NN];
__device__ int g_hist[NN];
__device__ int g_dptr[NN + 1];
__device__ int g_dcur[NN];
__device__ int g_eidx[EPMAX];
__device__ float g_a1[EPMAX * NHEADS];
__device__ float g_a2[EPMAX];

// bf16 split operands
__device__ __align__(16) __nv_bfloat16 g_xhi[NN * INC], g_xlo[NN * INC];
__device__ __align__(16) __nv_bfloat16 g_w1hi[INC * INC], g_w1lo[INC * INC];
__device__ __align__(16) __nv_bfloat16 g_w2hi[INC * OUTC], g_w2lo[INC * OUTC];
__device__ __align__(16) __nv_bfloat16 g_rwhi[INC * OUTC], g_rwlo[INC * OUTC];
__device__ __align__(16) __nv_bfloat16 g_h2hi[NN * INC], g_h2lo[NN * INC];

// ------------------------- convert + zero adj/hist ---------------------------
__global__ void k_convert(const void* p, int E) {
    __shared__ int any;
    if (threadIdx.x == 0) any = 0;
    __syncthreads();
    const int* w = (const int*)p;
#pragma unroll
    for (int t = 0; t < 4; t++) {
        int idx = threadIdx.x + t * 256;
        if (w[2 * idx + 1] != 0) any = 1;
    }
    __syncthreads();
    bool is64 = (any == 0);
    int i = blockIdx.x * blockDim.x + threadIdx.x;
    if (i < E) {
        if (is64) {
            const long long* q = (const long long*)p;
            g_src[i] = (int)q[i];
            g_dst[i] = (int)q[E + i];
        } else {
            const int* q = (const int*)p;
            g_src[i] = q[i];
            g_dst[i] = q[E + i];
        }
    }
    int total = gridDim.x * blockDim.x;
    uint4 zu = make_uint4(0u, 0u, 0u, 0u);
    uint4* adjv = (uint4*)g_adj;
    for (int k = i; k < NN * WORDS / 4; k += total) adjv[k] = zu;
    for (int k = i; k < NN; k += total) g_hist[k] = 0;
}

// ------------------------- zero A2 (side stream) -----------------------------
__global__ void k_zeroA2() {
    int stride = gridDim.x * blockDim.x;
    int gid = blockIdx.x * blockDim.x + threadIdx.x;
    uint4 zu = make_uint4(0u, 0u, 0u, 0u);
    uint4* A2v = (uint4*)g_A2h;
    for (int i = gid; i < NN * NN / 8; i += stride) A2v[i] = zu;
}

// ------------------------- all operand splits in one kernel ------------------
__device__ __forceinline__ void split8(const float* __restrict__ src,
                                       __nv_bfloat16* __restrict__ hi,
                                       __nv_bfloat16* __restrict__ lo, int i) {
    const float4* s4 = (const float4*)src;
    float4 v0 = s4[2 * i], v1 = s4[2 * i + 1];
    float f[8] = {v0.x, v0.y, v0.z, v0.w, v1.x, v1.y, v1.z, v1.w};
    __nv_bfloat16 h[8], l[8];
#pragma unroll
    for (int k = 0; k < 8; k++) {
        h[k] = __float2bfloat16(f[k]);
        l[k] = __float2bfloat16(f[k] - __bfloat162float(h[k]));
    }
    ((uint4*)hi)[i] = *(uint4*)h;
    ((uint4*)lo)[i] = *(uint4*)l;
}

#define NX8 (NN * INC / 8)
#define NW18 (INC * INC / 8)
#define NW28 (INC * OUTC / 8)
__global__ void k_splitall(const float* __restrict__ x, const float* __restrict__ W1,
                           const float* __restrict__ W2, const float* __restrict__ rW2) {
    int i = blockIdx.x * blockDim.x + threadIdx.x;
    if (i < NX8) { split8(x, g_xhi, g_xlo, i); return; }
    i -= NX8;
    if (i < NW18) { split8(W1, g_w1hi, g_w1lo, i); return; }
    i -= NW18;
    if (i < NW28) { split8(W2, g_w2hi, g_w2lo, i); return; }
    i -= NW28;
    if (i < NW28) { split8(rW2, g_rwhi, g_rwlo, i); return; }
}

__global__ void k_split(const float* __restrict__ src, __nv_bfloat16* __restrict__ hi,
                        __nv_bfloat16* __restrict__ lo, int n8) {
    int i = blockIdx.x * blockDim.x + threadIdx.x;
    if (i < n8) split8(src, hi, lo, i);
}

// ------------------------- adjacency + dst histogram -------------------------
__global__ void k_bitmap(int E) {
    int i = blockIdx.x * blockDim.x + threadIdx.x;
    int EP = E + NN;
    if (i >= EP) return;
    int s, d;
    if (i < E) { s = g_src[i]; d = g_dst[i]; }
    else { s = i - E; d = i - E; }
    atomicOr(&g_adj[s * WORDS + (d >> 5)], 1u << (d & 31));
    atomicAdd(&g_hist[d], 1);
}

__global__ void k_deg() {
    int r = blockIdx.x * blockDim.x + threadIdx.x;
    if (r >= NN) return;
    int c = 0;
    for (int w = 0; w < WORDS; w++) c += __popc(g_adj[r * WORDS + w]);
    g_deg[r] = c;
    g_d1[r] = (float)c;
}

// which=0: deg->rowptr ; which=1: hist->dptr (+dcur copy)
__global__ void k_scan4096(int which) {
    __shared__ int s[1024];
    const int* in = which ? g_hist : g_deg;
    int* out = which ? g_dptr : g_rowptr;
    int tid = threadIdx.x;
    int base = tid * 4;
    int loc[4];
    int tot = 0;
#pragma unroll
    for (int i = 0; i < 4; i++) { loc[i] = tot; tot += in[base + i]; }
    s[tid] = tot;
    __syncthreads();
    for (int off = 1; off < 1024; off <<= 1) {
        int t = (tid >= off) ? s[tid - off] : 0;
        __syncthreads();
        s[tid] += t;
        __syncthreads();
    }
    int pre = (tid == 0) ? 0 : s[tid - 1];
#pragma unroll
    for (int i = 0; i < 4; i++) {
        out[base + i] = pre + loc[i];
        if (which) g_dcur[base + i] = pre + loc[i];
    }
    if (tid == 1023) out[4096] = s[1023];
}

__global__ void k_fillcols() {
    int r = blockIdx.x * blockDim.x + threadIdx.x;
    if (r >= NN) return;
    int p = g_rowptr[r];
    for (int w = 0; w < WORDS; w++) {
        unsigned m = g_adj[r * WORDS + w];
        while (m) {
            int b = __ffs(m) - 1;
            g_cols[p++] = w * 32 + b;
            m &= m - 1;
        }
    }
}

__global__ void k_scatter(int E) {
    int e = blockIdx.x * blockDim.x + threadIdx.x;
    int EP = E + NN;
    if (e >= EP) return;
    int d = (e < E) ? g_dst[e] : (e - E);
    int pos = atomicAdd(&g_dcur[d], 1);
    g_eidx[pos] = e;
}

__global__ void k_spmv(int which) {
    int r = blockIdx.x * blockDim.x + threadIdx.x;
    if (r >= NN) return;
    const float* vin = which ? g_d2 : g_d1;
    float s = 0.f;
    int p1 = g_rowptr[r + 1];
    for (int i = g_rowptr[r]; i < p1; i++) s += vin[g_cols[i]];
    if (which) g_d3[r] = s; else g_d2[r] = s;
}

// A2[k][d] += 1 per 2-path (u16 lanes via u32 atomics)
__global__ void k_a2() {
    int k = blockIdx.x;
    int p0 = g_rowptr[k], p1 = g_rowptr[k + 1];
    unsigned* roww = (unsigned*)(g_A2h + (size_t)k * NN);
    for (int mi = p0; mi < p1; mi++) {
        int m = g_cols[mi];
        int q0 = g_rowptr[m], q1 = g_rowptr[m + 1];
        for (int j = q0 + threadIdx.x; j < q1; j += blockDim.x) {
            int d = g_cols[j];
            atomicAdd(&roww[d >> 1], (d & 1) ? 0x10000u : 1u);
        }
    }
}

__global__ void k_mw(int E) {
    int e = blockIdx.x * blockDim.x + threadIdx.x;
    int EP = E + NN;
    if (e >= EP) return;
    int s = (e < E) ? g_src[e] : (e - E);
    int d = (e < E) ? g_dst[e] : (e - E);
    float a3 = 0.f;
    int p1 = g_rowptr[s + 1];
    for (int i = g_rowptr[s]; i < p1; i++)
        a3 += (float)g_A2h[(size_t)g_cols[i] * NN + d];
    float nm = g_d3[s];
    if (nm < 1.f) nm = 1.f;
    g_mw[e] = a3 / nm;
}

// ------------------------- split-bf16 tensor-core GEMM -----------------------
#define PAD_A 40
#define PITCH_B 136

__device__ __forceinline__ void mma_bf16(float* c, const unsigned* a, const unsigned* b) {
    asm volatile(
        "mma.sync.aligned.m16n8k16.row.col.f32.bf16.bf16.f32 "
        "{%0,%1,%2,%3}, {%4,%5,%6,%7}, {%8,%9}, {%0,%1,%2,%3};"
        : "+f"(c[0]), "+f"(c[1]), "+f"(c[2]), "+f"(c[3])
        : "r"(a[0]), "r"(a[1]), "r"(a[2]), "r"(a[3]), "r"(b[0]), "r"(b[1]));
}

__device__ __forceinline__ void gemm_split(const __nv_bfloat16* __restrict__ Ahi,
                                           const __nv_bfloat16* __restrict__ Alo,
                                           const __nv_bfloat16* __restrict__ Bhi,
                                           const __nv_bfloat16* __restrict__ Blo,
                                           int ldb, int col0,
                                           float* __restrict__ C, int ldc, int row0) {
    __shared__ __nv_bfloat16 As[2][128 * PAD_A];
    __shared__ __nv_bfloat16 Bs[2][32 * PITCH_B];
    int tid = threadIdx.x;
    int wid = tid >> 5, lane = tid & 31;
    int wm = (wid >> 2) * 64;
    int wn = (wid & 3) * 32;
    int g = lane >> 2, q = lane & 3;
    float acc[4][4][4] = {};

    for (int k0 = 0; k0 < INC; k0 += 32) {
#pragma unroll
        for (int l = 0; l < 2; l++) {
            int slot = tid + l * 256;
            int r = slot >> 2, cg = (slot & 3) << 3;
            *(float4*)&As[0][r * PAD_A + cg] = *(const float4*)&Ahi[(row0 + r) * INC + k0 + cg];
            *(float4*)&As[1][r * PAD_A + cg] = *(const float4*)&Alo[(row0 + r) * INC + k0 + cg];
        }
#pragma unroll
        for (int l = 0; l < 2; l++) {
            int slot = tid + l * 256;
            int kr = slot >> 4, ng = (slot & 15) << 3;
            *(float4*)&Bs[0][kr * PITCH_B + ng] = *(const float4*)&Bhi[(k0 + kr) * ldb + col0 + ng];
            *(float4*)&Bs[1][kr * PITCH_B + ng] = *(const float4*)&Blo[(k0 + kr) * ldb + col0 + ng];
        }
        __syncthreads();
#pragma unroll
        for (int ks = 0; ks < 2; ks++) {
            int kb = ks * 16;
            unsigned ah[4][4], al[4][4], bh[4][2], bl[4][2];
#pragma unroll
            for (int i = 0; i < 4; i++) {
                int m = wm + i * 16 + g;
                int o0 = m * PAD_A + kb + q * 2;
                int o1 = (m + 8) * PAD_A + kb + q * 2;
                ah[i][0] = *(const unsigned*)&As[0][o0];
                ah[i][1] = *(const unsigned*)&As[0][o1];
                ah[i][2] = *(const unsigned*)&As[0][o0 + 8];
                ah[i][3] = *(const unsigned*)&As[0][o1 + 8];
                al[i][0] = *(const unsigned*)&As[1][o0];
                al[i][1] = *(const unsigned*)&As[1][o1];
                al[i][2] = *(const unsigned*)&As[1][o0 + 8];
                al[i][3] = *(const unsigned*)&As[1][o1 + 8];
            }
#pragma unroll
            for (int j = 0; j < 4; j++) {
                int n = wn + j * 8 + g;
                int k2 = kb + q * 2;
#pragma unroll
                for (int t = 0; t < 2; t++) {
                    int kk = k2 + t * 8;
                    unsigned h0 = *(const unsigned short*)&Bs[0][kk * PITCH_B + n];
                    unsigned h1 = *(const unsigned short*)&Bs[0][(kk + 1) * PITCH_B + n];
                    bh[j][t] = h0 | (h1 << 16);
                    unsigned l0 = *(const unsigned short*)&Bs[1][kk * PITCH_B + n];
                    unsigned l1 = *(const unsigned short*)&Bs[1][(kk + 1) * PITCH_B + n];
                    bl[j][t] = l0 | (l1 << 16);
                }
            }
#pragma unroll
            for (int i = 0; i < 4; i++)
#pragma unroll
                for (int j = 0; j < 4; j++) {
                    mma_bf16(acc[i][j], ah[i], bh[j]);
                    mma_bf16(acc[i][j], ah[i], bl[j]);
                    mma_bf16(acc[i][j], al[i], bh[j]);
                }
        }
        __syncthreads();
    }
#pragma unroll
    for (int i = 0; i < 4; i++)
#pragma unroll
        for (int j = 0; j < 4; j++) {
            int r = row0 + wm + i * 16 + g;
            int c = col0 + wn + j * 8 + q * 2;
            C[r * ldc + c] = acc[i][j][0];
            C[r * ldc + c + 1] = acc[i][j][1];
            C[(r + 8) * ldc + c] = acc[i][j][2];
            C[(r + 8) * ldc + c + 1] = acc[i][j][3];
        }
}

__global__ void __launch_bounds__(256) k_gemm1() {
    gemm_split(g_xhi, g_xlo, g_w1hi, g_w1lo, INC, blockIdx.x * 128, g_h1, INC,
               blockIdx.y * 128);
}

__global__ void __launch_bounds__(256) k_gemm23(float* __restrict__ out) {
    int bx = blockIdx.x;
    const __nv_bfloat16* Bh = (bx < 2) ? g_w2hi : g_rwhi;
    const __nv_bfloat16* Bl = (bx < 2) ? g_w2lo : g_rwlo;
    float* C = (bx < 2) ? g_h2w : out;
    gemm_split(g_h2hi, g_h2lo, Bh, Bl, OUTC, (bx & 1) * 128, C, OUTC, blockIdx.y * 128);
}

// ------------------------- attention scores ----------------------------------
__global__ void k_s1(const float* __restrict__ as1, const float* __restrict__ ad1) {
    int i = blockIdx.x * blockDim.x + threadIdx.x;
    if (i >= NN * NHEADS) return;
    int n = i / NHEADS, h = i % NHEADS;
    const float4* hp = (const float4*)(g_h1 + n * INC + h * HID);
    const float4* asp = (const float4*)(as1 + h * HID);
    const float4* adp = (const float4*)(ad1 + h * HID);
    float ss = 0.f, sd = 0.f;
#pragma unroll
    for (int c = 0; c < HID / 4; c++) {
        float4 v = hp[c], a = asp[c], d = adp[c];
        ss += v.x * a.x + v.y * a.y + v.z * a.z + v.w * a.w;
        sd += v.x * d.x + v.y * d.y + v.z * d.z + v.w * d.w;
    }
    g_s1s[i] = ss;
    g_s1d[i] = sd;
}

__global__ void k_s2(const float* __restrict__ as2, const float* __restrict__ ad2) {
    int n = blockIdx.x * blockDim.x + threadIdx.x;
    if (n >= NN) return;
    const float4* hp = (const float4*)(g_h2w + n * OUTC);
    const float4* asp = (const float4*)as2;
    const float4* adp = (const float4*)ad2;
    float ss = 0.f, sd = 0.f;
#pragma unroll
    for (int c = 0; c < OUTC / 4; c++) {
        float4 v = hp[c], a = asp[c], d = adp[c];
        ss += v.x * a.x + v.y * a.y + v.z * a.z + v.w * a.w;
        sd += v.x * d.x + v.y * d.y + v.z * d.z + v.w * d.w;
    }
    g_s2s[n] = ss;
    g_s2d[n] = sd;
}

// ------------------------- fused softmaxes -----------------------------------
__device__ __forceinline__ float lrelu(float x) { return x > 0.f ? x : NEG * x; }

__global__ void k_softmax1(int E) {
    int n = blockIdx.x;
    int h = threadIdx.x >> 5;
    int lane = threadIdx.x & 31;
    int p0 = g_dptr[n], p1 = g_dptr[n + 1];
    float sd = g_s1d[n * NHEADS + h];
    float m1 = -1e30f, m2 = -1e30f;
    for (int i = p0 + lane; i < p1; i += 32) {
        int e = g_eidx[i];
        int s = (e < E) ? g_src[e] : (e - E);
        float ev = g_s1s[s * NHEADS + h] + sd;
        m1 = fmaxf(m1, lrelu(ev));
        m2 = fmaxf(m2, lrelu(ev * g_mw[e]));
    }
    for (int o = 16; o; o >>= 1) {
        m1 = fmaxf(m1, __shfl_xor_sync(0xffffffffu, m1, o));
        m2 = fmaxf(m2, __shfl_xor_sync(0xffffffffu, m2, o));
    }
    float s1 = 0.f, s2 = 0.f;
    for (int i = p0 + lane; i < p1; i += 32) {
        int e = g_eidx[i];
        int s = (e < E) ? g_src[e] : (e - E);
        float ev = g_s1s[s * NHEADS + h] + sd;
        s1 += expf(lrelu(ev) - m1);
        s2 += expf(lrelu(ev * g_mw[e]) - m2);
    }
    for (int o = 16; o; o >>= 1) {
        s1 += __shfl_xor_sync(0xffffffffu, s1, o);
        s2 += __shfl_xor_sync(0xffffffffu, s2, o);
    }
    float r1 = 0.5f / (s1 + 1e-16f);
    float r2 = 0.5f / (s2 + 1e-16f);
    for (int i = p0 + lane; i < p1; i += 32) {
        int e = g_eidx[i];
        int s = (e < E) ? g_src[e] : (e - E);
        float ev = g_s1s[s * NHEADS + h] + sd;
        g_a1[e * NHEADS + h] = expf(lrelu(ev) - m1) * r1
                             + expf(lrelu(ev * g_mw[e]) - m2) * r2;
    }
}

__global__ void k_softmax2(int E) {
    int n = blockIdx.x;
    int lane = threadIdx.x;
    int p0 = g_dptr[n], p1 = g_dptr[n + 1];
    float sd = g_s2d[n];
    float m1 = -1e30f, m2 = -1e30f;
    for (int i = p0 + lane; i < p1; i += 32) {
        int e = g_eidx[i];
        int s = (e < E) ? g_src[e] : (e - E);
        float ev = g_s2s[s] + sd;
        m1 = fmaxf(m1, lrelu(ev));
        m2 = fmaxf(m2, lrelu(ev * g_mw[e]));
    }
    for (int o = 16; o; o >>= 1) {
        m1 = fmaxf(m1, __shfl_xor_sync(0xffffffffu, m1, o));
        m2 = fmaxf(m2, __shfl_xor_sync(0xffffffffu, m2, o));
    }
    float s1 = 0.f, s2 = 0.f;
    for (int i = p0 + lane; i < p1; i += 32) {
        int e = g_eidx[i];
        int s = (e < E) ? g_src[e] : (e - E);
        float ev = g_s2s[s] + sd;
        s1 += expf(lrelu(ev) - m1);
        s2 += expf(lrelu(ev * g_mw[e]) - m2);
    }
    for (int o = 16; o; o >>= 1) {
        s1 += __shfl_xor_sync(0xffffffffu, s1, o);
        s2 += __shfl_xor_sync(0xffffffffu, s2, o);
    }
    float r1 = 0.5f / (s1 + 1e-16f);
    float r2 = 0.5f / (s2 + 1e-16f);
    for (int i = p0 + lane; i < p1; i += 32) {
        int e = g_eidx[i];
        int s = (e < E) ? g_src[e] : (e - E);
        float ev = g_s2s[s] + sd;
        g_a2[e] = expf(lrelu(ev) - m1) * r1 + expf(lrelu(ev * g_mw[e]) - m2) * r2;
    }
}

// ------------------------- aggregations (float4) -----------------------------
__global__ void k_agg1(const float* __restrict__ b1, int E) {
    int n = blockIdx.x;
    int j4 = threadIdx.x;           // 0..127, channels 4*j4..4*j4+3
    int h = j4 >> 4;
    float4 acc = make_float4(0.f, 0.f, 0.f, 0.f);
    int p0 = g_dptr[n], p1 = g_dptr[n + 1];
    for (int i = p0; i < p1; i++) {
        int e = g_eidx[i];
        int s = (e < E) ? g_src[e] : (e - E);
        float a = g_a1[e * NHEADS + h];
        float4 v = *(const float4*)&g_h1[s * INC + 4 * j4];
        acc.x += a * v.x; acc.y += a * v.y; acc.z += a * v.z; acc.w += a * v.w;
    }
    float4 bb = *(const float4*)&b1[4 * j4];
    float4 r;
    r.x = acc.x + bb.x; r.y = acc.y + bb.y; r.z = acc.z + bb.z; r.w = acc.w + bb.w;
    r.x = r.x > 0.f ? r.x : expm1f(r.x);
    r.y = r.y > 0.f ? r.y : expm1f(r.y);
    r.z = r.z > 0.f ? r.z : expm1f(r.z);
    r.w = r.w > 0.f ? r.w : expm1f(r.w);
    *(float4*)&g_h2[n * INC + 4 * j4] = r;
}

__global__ void k_agg2(const float* __restrict__ b2, float* __restrict__ out, int E) {
    int n = blockIdx.x;
    int c4 = threadIdx.x;           // 0..63
    float4 acc = make_float4(0.f, 0.f, 0.f, 0.f);
    int p0 = g_dptr[n], p1 = g_dptr[n + 1];
    for (int i = p0; i < p1; i++) {
        int e = g_eidx[i];
        int s = (e < E) ? g_src[e] : (e - E);
        float a = g_a2[e];
        float4 v = *(const float4*)&g_h2w[s * OUTC + 4 * c4];
        acc.x += a * v.x; acc.y += a * v.y; acc.z += a * v.z; acc.w += a * v.w;
    }
    float4 o = *(float4*)&out[n * OUTC + 4 * c4];
    float4 bb = *(const float4*)&b2[4 * c4];
    o.x += acc.x + bb.x; o.y += acc.y + bb.y; o.z += acc.z + bb.z; o.w += acc.w + bb.w;
    *(float4*)&out[n * OUTC + 4 * c4] = o;
}

// ------------------------- launch --------------------------------------------
extern "C" void kernel_launch(void* const* d_in, const int* in_sizes, int n_in,
                              void* d_out, int out_size) {
    const float* x    = (const float*)d_in[0];
    const void*  ei   = d_in[1];
    const float* W1   = (const float*)d_in[2];
    const float* as1  = (const float*)d_in[3];
    const float* ad1  = (const float*)d_in[4];
    const float* b1   = (const float*)d_in[5];
    const float* W2   = (const float*)d_in[6];
    const float* as2  = (const float*)d_in[7];
    const float* ad2  = (const float*)d_in[8];
    const float* b2   = (const float*)d_in[9];
    const float* rW2  = (const float*)d_in[10];
    float* out = (float*)d_out;

    int E = in_sizes[1] / 2;
    int EP = E + NN;

    static cudaStream_t sB = 0, sC = 0;
    static cudaEvent_t ev0 = 0, evB = 0, evC = 0;
    if (!sB) {
        cudaStreamCreateWithFlags(&sB, cudaStreamNonBlocking);
        cudaStreamCreateWithFlags(&sC, cudaStreamNonBlocking);
        cudaEventCreateWithFlags(&ev0, cudaEventDisableTiming);
        cudaEventCreateWithFlags(&evB, cudaEventDisableTiming);
        cudaEventCreateWithFlags(&evC, cudaEventDisableTiming);
    }

    // fork
    cudaEventRecord(ev0, 0);
    cudaStreamWaitEvent(sB, ev0, 0);
    cudaStreamWaitEvent(sC, ev0, 0);

    // branch B: zero the 32MB A2 buffer
    k_zeroA2<<<1024, 256, 0, sB>>>();
    cudaEventRecord(evB, sB);

    // branch C: operand splits -> gemm1 -> s1
    {
        int tot8 = NX8 + NW18 + 2 * NW28;
        k_splitall<<<(tot8 + 255) / 256, 256, 0, sC>>>(x, W1, W2, rW2);
        k_gemm1<<<dim3(INC / 128, NN / 128), 256, 0, sC>>>();
        k_s1<<<(NN * NHEADS + 255) / 256, 256, 0, sC>>>(as1, ad1);
        cudaEventRecord(evC, sC);
    }

    // main chain (default stream)
    k_convert<<<(E + 255) / 256, 256>>>(ei, E);
    k_bitmap<<<(EP + 255) / 256, 256>>>(E);
    k_deg<<<16, 256>>>();
    k_scan4096<<<1, 1024>>>(0);
    k_fillcols<<<16, 256>>>();
    k_scan4096<<<1, 1024>>>(1);
    k_scatter<<<(EP + 255) / 256, 256>>>(E);
    k_spmv<<<16, 256>>>(0);
    k_spmv<<<16, 256>>>(1);

    cudaStreamWaitEvent(0, evB, 0);
    k_a2<<<NN, 128>>>();
    k_mw<<<(EP + 127) / 128, 128>>>(E);

    cudaStreamWaitEvent(0, evC, 0);
    k_softmax1<<<NN, 256>>>(E);
    k_agg1<<<NN, 128>>>(b1, E);

    {
        __nv_bfloat16 *h2hi, *h2lo;
        cudaGetSymbolAddress((void**)&h2hi, g_h2hi);
        cudaGetSymbolAddress((void**)&h2lo, g_h2lo);
        float* h2;
        cudaGetSymbolAddress((void**)&h2, g_h2);
        k_split<<<(NN * INC / 8 + 255) / 256, 256>>>(h2, h2hi, h2lo, NN * INC / 8);
    }

    k_gemm23<<<dim3(4, NN / 128), 256>>>(out);
    k_s2<<<16, 256>>>(as2, ad2);
    k_softmax2<<<NN, 32>>>(E);
    k_agg2<<<NN, 64>>>(b2, out, E);
}

// round 6
// speedup vs baseline: 2.3201x; 1.0561x over previous
#include <cuda_runtime.h>
#include <cuda_bf16.h>
#include <math.h>

#define NN 4096
#define EE_MAX 131072
#define EPMAX (EE_MAX + NN)
#define INC 512
#define NHEADS 8
#define HID 64
#define OUTC 256
#define WORDS (NN / 32)
#define NEG 0.2f
#define MAXDEG 384

// ------------------------- device scratch (static, no allocs) ---------------
__device__ int g_src[EE_MAX], g_dst[EE_MAX];
__device__ unsigned g_adj[NN * WORDS];
__device__ int g_deg[NN];
__device__ int g_rowptr[NN + 1];
__device__ int g_cols[EPMAX];
__device__ float g_d1[NN], g_d2[NN], g_d3[NN];
__device__ __align__(16) unsigned short g_A2h[NN * NN];   // 32 MB dense A@A (u16)
__device__ float g_mw[EPMAX];
__device__ float g_h1[NN * INC];
__device__ float g_h2[NN * INC];
__device__ float g_h2w[NN * OUTC];
__device__ float g_s1s[NN * NHEADS], g_s1d[NN * NHEADS];
__device__ float g_s2s[NN], g_s2d[NN];
__device__ int g_hist[NN];
__device__ int g_dptr[NN + 1];
__device__ int g_dcur[NN];
__device__ int g_eidx[EPMAX];

// bf16 split operands
__device__ __align__(16) __nv_bfloat16 g_xhi[NN * INC], g_xlo[NN * INC];
__device__ __align__(16) __nv_bfloat16 g_w1hi[INC * INC], g_w1lo[INC * INC];
__device__ __align__(16) __nv_bfloat16 g_w2hi[INC * OUTC], g_w2lo[INC * OUTC];
__device__ __align__(16) __nv_bfloat16 g_rwhi[INC * OUTC], g_rwlo[INC * OUTC];
__device__ __align__(16) __nv_bfloat16 g_h2hi[NN * INC], g_h2lo[NN * INC];

// ------------------------- convert + zero adj/hist ---------------------------
__global__ void k_convert(const void* p, int E) {
    __shared__ int any;
    if (threadIdx.x == 0) any = 0;
    __syncthreads();
    const int* w = (const int*)p;
#pragma unroll
    for (int t = 0; t < 4; t++) {
        int idx = threadIdx.x + t * 256;
        if (w[2 * idx + 1] != 0) any = 1;
    }
    __syncthreads();
    bool is64 = (any == 0);
    int i = blockIdx.x * blockDim.x + threadIdx.x;
    if (i < E) {
        if (is64) {
            const long long* q = (const long long*)p;
            g_src[i] = (int)q[i];
            g_dst[i] = (int)q[E + i];
        } else {
            const int* q = (const int*)p;
            g_src[i] = q[i];
            g_dst[i] = q[E + i];
        }
    }
    int total = gridDim.x * blockDim.x;
    uint4 zu = make_uint4(0u, 0u, 0u, 0u);
    uint4* adjv = (uint4*)g_adj;
    for (int k = i; k < NN * WORDS / 4; k += total) adjv[k] = zu;
    for (int k = i; k < NN; k += total) g_hist[k] = 0;
}

// ------------------------- fp32 -> (hi,lo) bf16 split ------------------------
__device__ __forceinline__ void split8(const float* __restrict__ src,
                                       __nv_bfloat16* __restrict__ hi,
                                       __nv_bfloat16* __restrict__ lo, int i) {
    const float4* s4 = (const float4*)src;
    float4 v0 = s4[2 * i], v1 = s4[2 * i + 1];
    float f[8] = {v0.x, v0.y, v0.z, v0.w, v1.x, v1.y, v1.z, v1.w};
    __nv_bfloat16 h[8], l[8];
#pragma unroll
    for (int k = 0; k < 8; k++) {
        h[k] = __float2bfloat16(f[k]);
        l[k] = __float2bfloat16(f[k] - __bfloat162float(h[k]));
    }
    ((uint4*)hi)[i] = *(uint4*)h;
    ((uint4*)lo)[i] = *(uint4*)l;
}

#define NX8 (NN * INC / 8)
#define NW18 (INC * INC / 8)
#define NW28 (INC * OUTC / 8)
__global__ void k_splitall(const float* __restrict__ x, const float* __restrict__ W1,
                           const float* __restrict__ W2, const float* __restrict__ rW2) {
    int i = blockIdx.x * blockDim.x + threadIdx.x;
    if (i < NX8) { split8(x, g_xhi, g_xlo, i); return; }
    i -= NX8;
    if (i < NW18) { split8(W1, g_w1hi, g_w1lo, i); return; }
    i -= NW18;
    if (i < NW28) { split8(W2, g_w2hi, g_w2lo, i); return; }
    i -= NW28;
    if (i < NW28) { split8(rW2, g_rwhi, g_rwlo, i); return; }
}

__global__ void k_split(const float* __restrict__ src, __nv_bfloat16* __restrict__ hi,
                        __nv_bfloat16* __restrict__ lo, int n8) {
    int i = blockIdx.x * blockDim.x + threadIdx.x;
    if (i < n8) split8(src, hi, lo, i);
}

// ------------------------- adjacency + dst histogram -------------------------
__global__ void k_bitmap(int E) {
    int i = blockIdx.x * blockDim.x + threadIdx.x;
    int EP = E + NN;
    if (i >= EP) return;
    int s, d;
    if (i < E) { s = g_src[i]; d = g_dst[i]; }
    else { s = i - E; d = i - E; }
    atomicOr(&g_adj[s * WORDS + (d >> 5)], 1u << (d & 31));
    atomicAdd(&g_hist[d], 1);
}

__global__ void k_deg() {
    int r = blockIdx.x * blockDim.x + threadIdx.x;
    if (r >= NN) return;
    int c = 0;
    for (int w = 0; w < WORDS; w++) c += __popc(g_adj[r * WORDS + w]);
    g_deg[r] = c;
    g_d1[r] = (float)c;
}

// which=0: deg->rowptr ; which=1: hist->dptr (+dcur copy)
__global__ void k_scan4096(int which) {
    __shared__ int s[1024];
    const int* in = which ? g_hist : g_deg;
    int* out = which ? g_dptr : g_rowptr;
    int tid = threadIdx.x;
    int base = tid * 4;
    int loc[4];
    int tot = 0;
#pragma unroll
    for (int i = 0; i < 4; i++) { loc[i] = tot; tot += in[base + i]; }
    s[tid] = tot;
    __syncthreads();
    for (int off = 1; off < 1024; off <<= 1) {
        int t = (tid >= off) ? s[tid - off] : 0;
        __syncthreads();
        s[tid] += t;
        __syncthreads();
    }
    int pre = (tid == 0) ? 0 : s[tid - 1];
#pragma unroll
    for (int i = 0; i < 4; i++) {
        out[base + i] = pre + loc[i];
        if (which) g_dcur[base + i] = pre + loc[i];
    }
    if (tid == 1023) out[4096] = s[1023];
}

__global__ void k_fillcols() {
    int r = blockIdx.x * blockDim.x + threadIdx.x;
    if (r >= NN) return;
    int p = g_rowptr[r];
    for (int w = 0; w < WORDS; w++) {
        unsigned m = g_adj[r * WORDS + w];
        while (m) {
            int b = __ffs(m) - 1;
            g_cols[p++] = w * 32 + b;
            m &= m - 1;
        }
    }
}

__global__ void k_scatter(int E) {
    int e = blockIdx.x * blockDim.x + threadIdx.x;
    int EP = E + NN;
    if (e >= EP) return;
    int d = (e < E) ? g_dst[e] : (e - E);
    int pos = atomicAdd(&g_dcur[d], 1);
    g_eidx[pos] = e;
}

__global__ void k_spmv(int which) {
    int r = blockIdx.x * blockDim.x + threadIdx.x;
    if (r >= NN) return;
    const float* vin = which ? g_d2 : g_d1;
    float s = 0.f;
    int p1 = g_rowptr[r + 1];
    for (int i = g_rowptr[r]; i < p1; i++) s += vin[g_cols[i]];
    if (which) g_d3[r] = s; else g_d2[r] = s;
}

// ------------- A2 row in shared memory (no gmem atomics, no pre-zero) --------
__global__ void __launch_bounds__(256) k_a2() {
    __shared__ unsigned short row[NN];          // 8 KB
    int tid = threadIdx.x;
    unsigned* roww = (unsigned*)row;
    for (int i = tid; i < NN / 2; i += 256) roww[i] = 0u;
    __syncthreads();
    int k = blockIdx.x;
    int p0 = g_rowptr[k], p1 = g_rowptr[k + 1];
    int wid = tid >> 5, lane = tid & 31;
    for (int mi = p0 + wid; mi < p1; mi += 8) {
        int m = g_cols[mi];
        int q1 = g_rowptr[m + 1];
        for (int j = g_rowptr[m] + lane; j < q1; j += 32) {
            int d = g_cols[j];
            atomicAdd(&roww[d >> 1], (d & 1) ? 0x10000u : 1u);
        }
    }
    __syncthreads();
    uint4* dst = (uint4*)(g_A2h + (size_t)k * NN);
    const uint4* srcv = (const uint4*)row;
    for (int i = tid; i < NN / 8; i += 256) dst[i] = srcv[i];
}

__global__ void k_mw(int E) {
    int e = blockIdx.x * blockDim.x + threadIdx.x;
    int EP = E + NN;
    if (e >= EP) return;
    int s = (e < E) ? g_src[e] : (e - E);
    int d = (e < E) ? g_dst[e] : (e - E);
    float a3 = 0.f;
    int p1 = g_rowptr[s + 1];
    for (int i = g_rowptr[s]; i < p1; i++)
        a3 += (float)g_A2h[(size_t)g_cols[i] * NN + d];
    float nm = g_d3[s];
    if (nm < 1.f) nm = 1.f;
    g_mw[e] = a3 / nm;
}

// ------------------------- split-bf16 tensor-core GEMM -----------------------
#define PAD_A 40
#define PITCH_B 136

__device__ __forceinline__ void mma_bf16(float* c, const unsigned* a, const unsigned* b) {
    asm volatile(
        "mma.sync.aligned.m16n8k16.row.col.f32.bf16.bf16.f32 "
        "{%0,%1,%2,%3}, {%4,%5,%6,%7}, {%8,%9}, {%0,%1,%2,%3};"
        : "+f"(c[0]), "+f"(c[1]), "+f"(c[2]), "+f"(c[3])
        : "r"(a[0]), "r"(a[1]), "r"(a[2]), "r"(a[3]), "r"(b[0]), "r"(b[1]));
}

__device__ __forceinline__ void gemm_split(const __nv_bfloat16* __restrict__ Ahi,
                                           const __nv_bfloat16* __restrict__ Alo,
                                           const __nv_bfloat16* __restrict__ Bhi,
                                           const __nv_bfloat16* __restrict__ Blo,
                                           int ldb, int col0,
                                           float* __restrict__ C, int ldc, int row0) {
    __shared__ __nv_bfloat16 As[2][128 * PAD_A];
    __shared__ __nv_bfloat16 Bs[2][32 * PITCH_B];
    int tid = threadIdx.x;
    int wid = tid >> 5, lane = tid & 31;
    int wm = (wid >> 2) * 64;
    int wn = (wid & 3) * 32;
    int g = lane >> 2, q = lane & 3;
    float acc[4][4][4] = {};

    for (int k0 = 0; k0 < INC; k0 += 32) {
#pragma unroll
        for (int l = 0; l < 2; l++) {
            int slot = tid + l * 256;
            int r = slot >> 2, cg = (slot & 3) << 3;
            *(float4*)&As[0][r * PAD_A + cg] = *(const float4*)&Ahi[(row0 + r) * INC + k0 + cg];
            *(float4*)&As[1][r * PAD_A + cg] = *(const float4*)&Alo[(row0 + r) * INC + k0 + cg];
        }
#pragma unroll
        for (int l = 0; l < 2; l++) {
            int slot = tid + l * 256;
            int kr = slot >> 4, ng = (slot & 15) << 3;
            *(float4*)&Bs[0][kr * PITCH_B + ng] = *(const float4*)&Bhi[(k0 + kr) * ldb + col0 + ng];
            *(float4*)&Bs[1][kr * PITCH_B + ng] = *(const float4*)&Blo[(k0 + kr) * ldb + col0 + ng];
        }
        __syncthreads();
#pragma unroll
        for (int ks = 0; ks < 2; ks++) {
            int kb = ks * 16;
            unsigned ah[4][4], al[4][4], bh[4][2], bl[4][2];
#pragma unroll
            for (int i = 0; i < 4; i++) {
                int m = wm + i * 16 + g;
                int o0 = m * PAD_A + kb + q * 2;
                int o1 = (m + 8) * PAD_A + kb + q * 2;
                ah[i][0] = *(const unsigned*)&As[0][o0];
                ah[i][1] = *(const unsigned*)&As[0][o1];
                ah[i][2] = *(const unsigned*)&As[0][o0 + 8];
                ah[i][3] = *(const unsigned*)&As[0][o1 + 8];
                al[i][0] = *(const unsigned*)&As[1][o0];
                al[i][1] = *(const unsigned*)&As[1][o1];
                al[i][2] = *(const unsigned*)&As[1][o0 + 8];
                al[i][3] = *(const unsigned*)&As[1][o1 + 8];
            }
#pragma unroll
            for (int j = 0; j < 4; j++) {
                int n = wn + j * 8 + g;
                int k2 = kb + q * 2;
#pragma unroll
                for (int t = 0; t < 2; t++) {
                    int kk = k2 + t * 8;
                    unsigned h0 = *(const unsigned short*)&Bs[0][kk * PITCH_B + n];
                    unsigned h1 = *(const unsigned short*)&Bs[0][(kk + 1) * PITCH_B + n];
                    bh[j][t] = h0 | (h1 << 16);
                    unsigned l0 = *(const unsigned short*)&Bs[1][kk * PITCH_B + n];
                    unsigned l1 = *(const unsigned short*)&Bs[1][(kk + 1) * PITCH_B + n];
                    bl[j][t] = l0 | (l1 << 16);
                }
            }
#pragma unroll
            for (int i = 0; i < 4; i++)
#pragma unroll
                for (int j = 0; j < 4; j++) {
                    mma_bf16(acc[i][j], ah[i], bh[j]);
                    mma_bf16(acc[i][j], ah[i], bl[j]);
                    mma_bf16(acc[i][j], al[i], bh[j]);
                }
        }
        __syncthreads();
    }
#pragma unroll
    for (int i = 0; i < 4; i++)
#pragma unroll
        for (int j = 0; j < 4; j++) {
            int r = row0 + wm + i * 16 + g;
            int c = col0 + wn + j * 8 + q * 2;
            C[r * ldc + c] = acc[i][j][0];
            C[r * ldc + c + 1] = acc[i][j][1];
            C[(r + 8) * ldc + c] = acc[i][j][2];
            C[(r + 8) * ldc + c + 1] = acc[i][j][3];
        }
}

__global__ void __launch_bounds__(256) k_gemm1() {
    gemm_split(g_xhi, g_xlo, g_w1hi, g_w1lo, INC, blockIdx.x * 128, g_h1, INC,
               blockIdx.y * 128);
}

__global__ void __launch_bounds__(256) k_gemm23(float* __restrict__ out) {
    int bx = blockIdx.x;
    const __nv_bfloat16* Bh = (bx < 2) ? g_w2hi : g_rwhi;
    const __nv_bfloat16* Bl = (bx < 2) ? g_w2lo : g_rwlo;
    float* C = (bx < 2) ? g_h2w : out;
    gemm_split(g_h2hi, g_h2lo, Bh, Bl, OUTC, (bx & 1) * 128, C, OUTC, blockIdx.y * 128);
}

// ------------------- attention scores (warp per node-head) -------------------
__global__ void k_s1(const float* __restrict__ as1, const float* __restrict__ ad1) {
    int n = blockIdx.x;
    int h = threadIdx.x >> 5, lane = threadIdx.x & 31;
    float2 v = *(const float2*)&g_h1[n * INC + h * HID + lane * 2];
    float2 a = *(const float2*)&as1[h * HID + lane * 2];
    float2 d = *(const float2*)&ad1[h * HID + lane * 2];
    float ss = v.x * a.x + v.y * a.y;
    float sd = v.x * d.x + v.y * d.y;
    for (int o = 16; o; o >>= 1) {
        ss += __shfl_xor_sync(0xffffffffu, ss, o);
        sd += __shfl_xor_sync(0xffffffffu, sd, o);
    }
    if (lane == 0) {
        g_s1s[n * NHEADS + h] = ss;
        g_s1d[n * NHEADS + h] = sd;
    }
}

__global__ void k_s2(const float* __restrict__ as2, const float* __restrict__ ad2) {
    int n = blockIdx.x * blockDim.x + threadIdx.x;
    if (n >= NN) return;
    const float4* hp = (const float4*)(g_h2w + n * OUTC);
    const float4* asp = (const float4*)as2;
    const float4* adp = (const float4*)ad2;
    float ss = 0.f, sd = 0.f;
#pragma unroll
    for (int c = 0; c < OUTC / 4; c++) {
        float4 v = hp[c], a = asp[c], d = adp[c];
        ss += v.x * a.x + v.y * a.y + v.z * a.z + v.w * a.w;
        sd += v.x * d.x + v.y * d.y + v.z * d.z + v.w * d.w;
    }
    g_s2s[n] = ss;
    g_s2d[n] = sd;
}

// ------------------- fused softmax + aggregate, layer 1 ----------------------
__device__ __forceinline__ float lrelu(float x) { return x > 0.f ? x : NEG * x; }

__global__ void __launch_bounds__(256) k_sma1(const float* __restrict__ b1, int E) {
    __shared__ float sal[MAXDEG * NHEADS];    // 12 KB alphas
    __shared__ int se[MAXDEG];                // src cache
    __shared__ float sm1[NHEADS], sr1[NHEADS], sm2[NHEADS], sr2[NHEADS];
    int n = blockIdx.x;
    int p0 = g_dptr[n], p1 = g_dptr[n + 1];
    int cnt = p1 - p0;
    int tid = threadIdx.x, h = tid >> 5, lane = tid & 31;
    float sd = g_s1d[n * NHEADS + h];
    float m1 = -1e30f, m2 = -1e30f;
    for (int i = lane; i < cnt; i += 32) {
        int e = g_eidx[p0 + i];
        int s = (e < E) ? g_src[e] : (e - E);
        if (h == 0 && i < MAXDEG) se[i] = s;
        float ev = g_s1s[s * NHEADS + h] + sd;
        m1 = fmaxf(m1, lrelu(ev));
        m2 = fmaxf(m2, lrelu(ev * g_mw[e]));
    }
    for (int o = 16; o; o >>= 1) {
        m1 = fmaxf(m1, __shfl_xor_sync(0xffffffffu, m1, o));
        m2 = fmaxf(m2, __shfl_xor_sync(0xffffffffu, m2, o));
    }
    float s1 = 0.f, s2 = 0.f;
    for (int i = lane; i < cnt; i += 32) {
        int e = g_eidx[p0 + i];
        int s = (e < E) ? g_src[e] : (e - E);
        float ev = g_s1s[s * NHEADS + h] + sd;
        s1 += expf(lrelu(ev) - m1);
        s2 += expf(lrelu(ev * g_mw[e]) - m2);
    }
    for (int o = 16; o; o >>= 1) {
        s1 += __shfl_xor_sync(0xffffffffu, s1, o);
        s2 += __shfl_xor_sync(0xffffffffu, s2, o);
    }
    float r1 = 0.5f / (s1 + 1e-16f);
    float r2 = 0.5f / (s2 + 1e-16f);
    for (int i = lane; i < cnt && i < MAXDEG; i += 32) {
        int e = g_eidx[p0 + i];
        int s = (e < E) ? g_src[e] : (e - E);
        float ev = g_s1s[s * NHEADS + h] + sd;
        sal[i * NHEADS + h] = expf(lrelu(ev) - m1) * r1
                            + expf(lrelu(ev * g_mw[e]) - m2) * r2;
    }
    if (lane == 0) { sm1[h] = m1; sr1[h] = r1; sm2[h] = m2; sr2[h] = r2; }
    __syncthreads();
    // aggregation: warp h handles channels [h*64, h*64+63]; lane -> float2
    int c = h * HID + lane * 2;
    float2 acc = make_float2(0.f, 0.f);
    for (int i = 0; i < cnt; i++) {
        float a;
        int s;
        if (i < MAXDEG) {
            s = se[i];
            a = sal[i * NHEADS + h];
        } else {  // overflow fallback (statistically never)
            int e = g_eidx[p0 + i];
            s = (e < E) ? g_src[e] : (e - E);
            float ev = g_s1s[s * NHEADS + h] + sd;
            a = expf(lrelu(ev) - sm1[h]) * sr1[h]
              + expf(lrelu(ev * g_mw[e]) - sm2[h]) * sr2[h];
        }
        float2 v = *(const float2*)&g_h1[s * INC + c];
        acc.x += a * v.x;
        acc.y += a * v.y;
    }
    float2 bb = *(const float2*)&b1[c];
    float rx = acc.x + bb.x, ry = acc.y + bb.y;
    rx = rx > 0.f ? rx : expm1f(rx);
    ry = ry > 0.f ? ry : expm1f(ry);
    *(float2*)&g_h2[n * INC + c] = make_float2(rx, ry);
}

// ------------------- fused softmax + aggregate, layer 2 ----------------------
__global__ void __launch_bounds__(256) k_sma2(const float* __restrict__ b2,
                                              float* __restrict__ out, int E) {
    __shared__ float sal[MAXDEG];
    __shared__ int se[MAXDEG];
    __shared__ float st[4];   // m1, r1, m2, r2
    int n = blockIdx.x;
    int p0 = g_dptr[n], p1 = g_dptr[n + 1];
    int cnt = p1 - p0;
    int tid = threadIdx.x;
    if (tid < 32) {
        int lane = tid;
        float sd = g_s2d[n];
        float m1 = -1e30f, m2 = -1e30f;
        for (int i = lane; i < cnt; i += 32) {
            int e = g_eidx[p0 + i];
            int s = (e < E) ? g_src[e] : (e - E);
            if (i < MAXDEG) se[i] = s;
            float ev = g_s2s[s] + sd;
            m1 = fmaxf(m1, lrelu(ev));
            m2 = fmaxf(m2, lrelu(ev * g_mw[e]));
        }
        for (int o = 16; o; o >>= 1) {
            m1 = fmaxf(m1, __shfl_xor_sync(0xffffffffu, m1, o));
            m2 = fmaxf(m2, __shfl_xor_sync(0xffffffffu, m2, o));
        }
        float s1 = 0.f, s2 = 0.f;
        for (int i = lane; i < cnt; i += 32) {
            int e = g_eidx[p0 + i];
            int s = (e < E) ? g_src[e] : (e - E);
            float ev = g_s2s[s] + sd;
            s1 += expf(lrelu(ev) - m1);
            s2 += expf(lrelu(ev * g_mw[e]) - m2);
        }
        for (int o = 16; o; o >>= 1) {
            s1 += __shfl_xor_sync(0xffffffffu, s1, o);
            s2 += __shfl_xor_sync(0xffffffffu, s2, o);
        }
        float r1 = 0.5f / (s1 + 1e-16f);
        float r2 = 0.5f / (s2 + 1e-16f);
        for (int i = lane; i < cnt && i < MAXDEG; i += 32) {
            int e = g_eidx[p0 + i];
            int s = (e < E) ? g_src[e] : (e - E);
            float ev = g_s2s[s] + sd;
            sal[i] = expf(lrelu(ev) - m1) * r1 + expf(lrelu(ev * g_mw[e]) - m2) * r2;
        }
        if (lane == 0) { st[0] = m1; st[1] = r1; st[2] = m2; st[3] = r2; }
    }
    __syncthreads();
    int c = tid;   // 256 threads, one channel each
    float acc = 0.f;
    float sd = g_s2d[n];
    for (int i = 0; i < cnt; i++) {
        float a;
        int s;
        if (i < MAXDEG) {
            s = se[i];
            a = sal[i];
        } else {
            int e = g_eidx[p0 + i];
            s = (e < E) ? g_src[e] : (e - E);
            float ev = g_s2s[s] + sd;
            a = expf(lrelu(ev) - st[0]) * st[1] + expf(lrelu(ev * g_mw[e]) - st[2]) * st[3];
        }
        acc += a * g_h2w[s * OUTC + c];
    }
    out[n * OUTC + c] = out[n * OUTC + c] + acc + b2[c];
}

// ------------------------- launch --------------------------------------------
extern "C" void kernel_launch(void* const* d_in, const int* in_sizes, int n_in,
                              void* d_out, int out_size) {
    const float* x    = (const float*)d_in[0];
    const void*  ei   = d_in[1];
    const float* W1   = (const float*)d_in[2];
    const float* as1  = (const float*)d_in[3];
    const float* ad1  = (const float*)d_in[4];
    const float* b1   = (const float*)d_in[5];
    const float* W2   = (const float*)d_in[6];
    const float* as2  = (const float*)d_in[7];
    const float* ad2  = (const float*)d_in[8];
    const float* b2   = (const float*)d_in[9];
    const float* rW2  = (const float*)d_in[10];
    float* out = (float*)d_out;

    int E = in_sizes[1] / 2;
    int EP = E + NN;

    static cudaStream_t sC = 0;
    static cudaEvent_t ev0 = 0, evC = 0;
    if (!sC) {
        cudaStreamCreateWithFlags(&sC, cudaStreamNonBlocking);
        cudaEventCreateWithFlags(&ev0, cudaEventDisableTiming);
        cudaEventCreateWithFlags(&evC, cudaEventDisableTiming);
    }

    // fork
    cudaEventRecord(ev0, 0);
    cudaStreamWaitEvent(sC, ev0, 0);

    // branch C: operand splits -> gemm1 -> s1
    {
        int tot8 = NX8 + NW18 + 2 * NW28;
        k_splitall<<<(tot8 + 255) / 256, 256, 0, sC>>>(x, W1, W2, rW2);
        k_gemm1<<<dim3(INC / 128, NN / 128), 256, 0, sC>>>();
        k_s1<<<NN, 256, 0, sC>>>(as1, ad1);
        cudaEventRecord(evC, sC);
    }

    // main chain (default stream)
    k_convert<<<(E + 255) / 256, 256>>>(ei, E);
    k_bitmap<<<(EP + 255) / 256, 256>>>(E);
    k_deg<<<16, 256>>>();
    k_scan4096<<<1, 1024>>>(0);
    k_fillcols<<<16, 256>>>();
    k_scan4096<<<1, 1024>>>(1);
    k_scatter<<<(EP + 255) / 256, 256>>>(E);
    k_spmv<<<16, 256>>>(0);
    k_spmv<<<16, 256>>>(1);
    k_a2<<<NN, 256>>>();
    k_mw<<<(EP + 127) / 128, 128>>>(E);

    cudaStreamWaitEvent(0, evC, 0);
    k_sma1<<<NN, 256>>>(b1, E);

    {
        __nv_bfloat16 *h2hi, *h2lo;
        cudaGetSymbolAddress((void**)&h2hi, g_h2hi);
        cudaGetSymbolAddress((void**)&h2lo, g_h2lo);
        float* h2;
        cudaGetSymbolAddress((void**)&h2, g_h2);
        k_split<<<(NN * INC / 8 + 255) / 256, 256>>>(h2, h2hi, h2lo, NN * INC / 8);
    }

    k_gemm23<<<dim3(4, NN / 128), 256>>>(out);
    k_s2<<<16, 256>>>(as2, ad2);
    k_sma2<<<NN, 256>>>(b2, out, E);
}

// round 7
// speedup vs baseline: 2.3710x; 1.0220x over previous
#include <cuda_runtime.h>
#include <cuda_bf16.h>
#include <math.h>

#define NN 4096
#define EE_MAX 131072
#define EPMAX (EE_MAX + NN)
#define INC 512
#define NHEADS 8
#define HID 64
#define OUTC 256
#define WORDS (NN / 32)
#define NEG 0.2f
#define MAXDEG 384

// ------------------------- device scratch (static, no allocs) ---------------
__device__ int g_src[EE_MAX], g_dst[EE_MAX];
__device__ unsigned g_adj[NN * WORDS];
__device__ int g_deg[NN];
__device__ int g_rowptr[NN + 1];
__device__ int g_cols[EPMAX];
__device__ float g_d1[NN], g_d2[NN], g_d3[NN];
__device__ __align__(16) unsigned short g_A2h[NN * NN];   // 32 MB dense A@A (u16)
__device__ float g_mw[EPMAX];
__device__ float g_h1[NN * INC];
__device__ float g_h2w[NN * OUTC];
__device__ float g_s1s[NN * NHEADS], g_s1d[NN * NHEADS];
__device__ float g_s2s[NN], g_s2d[NN];
__device__ int g_hist[NN];
__device__ int g_dptr[NN + 1];
__device__ int g_dcur[NN];
__device__ int g_eidx[EPMAX];

// bf16 split operands
__device__ __align__(16) __nv_bfloat16 g_xhi[NN * INC], g_xlo[NN * INC];
__device__ __align__(16) __nv_bfloat16 g_w1hi[INC * INC], g_w1lo[INC * INC];
__device__ __align__(16) __nv_bfloat16 g_w2hi[INC * OUTC], g_w2lo[INC * OUTC];
__device__ __align__(16) __nv_bfloat16 g_rwhi[INC * OUTC], g_rwlo[INC * OUTC];
__device__ __align__(16) __nv_bfloat16 g_h2hi[NN * INC], g_h2lo[NN * INC];

// ------------------------- convert + zero adj/hist ---------------------------
__global__ void k_convert(const void* p, int E) {
    __shared__ int any;
    if (threadIdx.x == 0) any = 0;
    __syncthreads();
    const int* w = (const int*)p;
#pragma unroll
    for (int t = 0; t < 4; t++) {
        int idx = threadIdx.x + t * 256;
        if (w[2 * idx + 1] != 0) any = 1;
    }
    __syncthreads();
    bool is64 = (any == 0);
    int i = blockIdx.x * blockDim.x + threadIdx.x;
    if (i < E) {
        if (is64) {
            const long long* q = (const long long*)p;
            g_src[i] = (int)q[i];
            g_dst[i] = (int)q[E + i];
        } else {
            const int* q = (const int*)p;
            g_src[i] = q[i];
            g_dst[i] = q[E + i];
        }
    }
    int total = gridDim.x * blockDim.x;
    uint4 zu = make_uint4(0u, 0u, 0u, 0u);
    uint4* adjv = (uint4*)g_adj;
    for (int k = i; k < NN * WORDS / 4; k += total) adjv[k] = zu;
    for (int k = i; k < NN; k += total) g_hist[k] = 0;
}

// ------------------------- fp32 -> (hi,lo) bf16 split ------------------------
__device__ __forceinline__ void split8(const float* __restrict__ src,
                                       __nv_bfloat16* __restrict__ hi,
                                       __nv_bfloat16* __restrict__ lo, int i) {
    const float4* s4 = (const float4*)src;
    float4 v0 = s4[2 * i], v1 = s4[2 * i + 1];
    float f[8] = {v0.x, v0.y, v0.z, v0.w, v1.x, v1.y, v1.z, v1.w};
    __nv_bfloat16 h[8], l[8];
#pragma unroll
    for (int k = 0; k < 8; k++) {
        h[k] = __float2bfloat16(f[k]);
        l[k] = __float2bfloat16(f[k] - __bfloat162float(h[k]));
    }
    ((uint4*)hi)[i] = *(uint4*)h;
    ((uint4*)lo)[i] = *(uint4*)l;
}

#define NX8 (NN * INC / 8)
#define NW18 (INC * INC / 8)
#define NW28 (INC * OUTC / 8)
__global__ void k_splitall(const float* __restrict__ x, const float* __restrict__ W1,
                           const float* __restrict__ W2, const float* __restrict__ rW2) {
    int i = blockIdx.x * blockDim.x + threadIdx.x;
    if (i < NX8) { split8(x, g_xhi, g_xlo, i); return; }
    i -= NX8;
    if (i < NW18) { split8(W1, g_w1hi, g_w1lo, i); return; }
    i -= NW18;
    if (i < NW28) { split8(W2, g_w2hi, g_w2lo, i); return; }
    i -= NW28;
    if (i < NW28) { split8(rW2, g_rwhi, g_rwlo, i); return; }
}

// ------------------------- adjacency + dst histogram -------------------------
__global__ void k_bitmap(int E) {
    int i = blockIdx.x * blockDim.x + threadIdx.x;
    int EP = E + NN;
    if (i >= EP) return;
    int s, d;
    if (i < E) { s = g_src[i]; d = g_dst[i]; }
    else { s = i - E; d = i - E; }
    atomicOr(&g_adj[s * WORDS + (d >> 5)], 1u << (d & 31));
    atomicAdd(&g_hist[d], 1);
}

__global__ void k_deg() {
    int r = blockIdx.x * blockDim.x + threadIdx.x;
    if (r >= NN) return;
    const uint4* row = (const uint4*)(g_adj + r * WORDS);
    int c = 0;
#pragma unroll
    for (int w = 0; w < WORDS / 4; w++) {
        uint4 v = row[w];
        c += __popc(v.x) + __popc(v.y) + __popc(v.z) + __popc(v.w);
    }
    g_deg[r] = c;
    g_d1[r] = (float)c;
}

// both scans in one block: deg->rowptr, hist->dptr(+dcur)
__global__ void k_dualscan() {
    __shared__ int s[1024];
    int tid = threadIdx.x;
#pragma unroll
    for (int pass = 0; pass < 2; pass++) {
        const int* in = pass ? g_hist : g_deg;
        int* out = pass ? g_dptr : g_rowptr;
        int base = tid * 4;
        int loc[4];
        int tot = 0;
#pragma unroll
        for (int i = 0; i < 4; i++) { loc[i] = tot; tot += in[base + i]; }
        s[tid] = tot;
        __syncthreads();
        for (int off = 1; off < 1024; off <<= 1) {
            int t = (tid >= off) ? s[tid - off] : 0;
            __syncthreads();
            s[tid] += t;
            __syncthreads();
        }
        int pre = (tid == 0) ? 0 : s[tid - 1];
#pragma unroll
        for (int i = 0; i < 4; i++) {
            out[base + i] = pre + loc[i];
            if (pass) g_dcur[base + i] = pre + loc[i];
        }
        if (tid == 1023) out[4096] = s[1023];
        __syncthreads();
    }
}

// fused: blocks 0..15 -> fillcols + d2 ; blocks 16.. -> scatter edges
__global__ void k_build(int E) {
    int EP = E + NN;
    if (blockIdx.x < 16) {
        int r = blockIdx.x * blockDim.x + threadIdx.x;
        if (r >= NN) return;
        int p = g_rowptr[r];
        float d2 = 0.f;
        for (int w = 0; w < WORDS; w++) {
            unsigned m = g_adj[r * WORDS + w];
            while (m) {
                int b = __ffs(m) - 1;
                int c = w * 32 + b;
                g_cols[p++] = c;
                d2 += g_d1[c];
                m &= m - 1;
            }
        }
        g_d2[r] = d2;
    } else {
        int e = (blockIdx.x - 16) * blockDim.x + threadIdx.x;
        if (e >= EP) return;
        int d = (e < E) ? g_dst[e] : (e - E);
        int pos = atomicAdd(&g_dcur[d], 1);
        g_eidx[pos] = e;
    }
}

// ------------- A2 row in shared memory + d3[k] = A*d2 ------------------------
__global__ void __launch_bounds__(256) k_a2() {
    __shared__ unsigned short row[NN];          // 8 KB
    int tid = threadIdx.x;
    unsigned* roww = (unsigned*)row;
    for (int i = tid; i < NN / 2; i += 256) roww[i] = 0u;
    __syncthreads();
    int k = blockIdx.x;
    int p0 = g_rowptr[k], p1 = g_rowptr[k + 1];
    // d3[k] = sum d2[cols]
    float d3 = 0.f;
    for (int i = p0 + tid; i < p1; i += 256) d3 += g_d2[g_cols[i]];
    for (int o = 16; o; o >>= 1) d3 += __shfl_xor_sync(0xffffffffu, d3, o);
    __shared__ float sred[8];
    if ((tid & 31) == 0) sred[tid >> 5] = d3;
    int wid = tid >> 5, lane = tid & 31;
    for (int mi = p0 + wid; mi < p1; mi += 8) {
        int m = g_cols[mi];
        int q1 = g_rowptr[m + 1];
        for (int j = g_rowptr[m] + lane; j < q1; j += 32) {
            int d = g_cols[j];
            atomicAdd(&roww[d >> 1], (d & 1) ? 0x10000u : 1u);
        }
    }
    __syncthreads();
    if (tid == 0) {
        float t = 0.f;
        for (int i = 0; i < 8; i++) t += sred[i];
        g_d3[k] = t;
    }
    uint4* dst = (uint4*)(g_A2h + (size_t)k * NN);
    const uint4* srcv = (const uint4*)row;
    for (int i = tid; i < NN / 8; i += 256) dst[i] = srcv[i];
}

__global__ void k_mw(int E) {
    int e = blockIdx.x * blockDim.x + threadIdx.x;
    int EP = E + NN;
    if (e >= EP) return;
    int s = (e < E) ? g_src[e] : (e - E);
    int d = (e < E) ? g_dst[e] : (e - E);
    float a3 = 0.f;
    int p1 = g_rowptr[s + 1];
    for (int i = g_rowptr[s]; i < p1; i++)
        a3 += (float)g_A2h[(size_t)g_cols[i] * NN + d];
    float nm = g_d3[s];
    if (nm < 1.f) nm = 1.f;
    g_mw[e] = a3 / nm;
}

// ------------------------- split-bf16 tensor-core GEMM -----------------------
#define PAD_A 40
#define PITCH_B 136

__device__ __forceinline__ void mma_bf16(float* c, const unsigned* a, const unsigned* b) {
    asm volatile(
        "mma.sync.aligned.m16n8k16.row.col.f32.bf16.bf16.f32 "
        "{%0,%1,%2,%3}, {%4,%5,%6,%7}, {%8,%9}, {%0,%1,%2,%3};"
        : "+f"(c[0]), "+f"(c[1]), "+f"(c[2]), "+f"(c[3])
        : "r"(a[0]), "r"(a[1]), "r"(a[2]), "r"(a[3]), "r"(b[0]), "r"(b[1]));
}

__device__ __forceinline__ void gemm_split(const __nv_bfloat16* __restrict__ Ahi,
                                           const __nv_bfloat16* __restrict__ Alo,
                                           const __nv_bfloat16* __restrict__ Bhi,
                                           const __nv_bfloat16* __restrict__ Blo,
                                           int ldb, int col0,
                                           float* __restrict__ C, int ldc, int row0) {
    __shared__ __nv_bfloat16 As[2][128 * PAD_A];
    __shared__ __nv_bfloat16 Bs[2][32 * PITCH_B];
    int tid = threadIdx.x;
    int wid = tid >> 5, lane = tid & 31;
    int wm = (wid >> 2) * 64;
    int wn = (wid & 3) * 32;
    int g = lane >> 2, q = lane & 3;
    float acc[4][4][4] = {};

    for (int k0 = 0; k0 < INC; k0 += 32) {
#pragma unroll
        for (int l = 0; l < 2; l++) {
            int slot = tid + l * 256;
            int r = slot >> 2, cg = (slot & 3) << 3;
            *(float4*)&As[0][r * PAD_A + cg] = *(const float4*)&Ahi[(row0 + r) * INC + k0 + cg];
            *(float4*)&As[1][r * PAD_A + cg] = *(const float4*)&Alo[(row0 + r) * INC + k0 + cg];
        }
#pragma unroll
        for (int l = 0; l < 2; l++) {
            int slot = tid + l * 256;
            int kr = slot >> 4, ng = (slot & 15) << 3;
            *(float4*)&Bs[0][kr * PITCH_B + ng] = *(const float4*)&Bhi[(k0 + kr) * ldb + col0 + ng];
            *(float4*)&Bs[1][kr * PITCH_B + ng] = *(const float4*)&Blo[(k0 + kr) * ldb + col0 + ng];
        }
        __syncthreads();
#pragma unroll
        for (int ks = 0; ks < 2; ks++) {
            int kb = ks * 16;
            unsigned ah[4][4], al[4][4], bh[4][2], bl[4][2];
#pragma unroll
            for (int i = 0; i < 4; i++) {
                int m = wm + i * 16 + g;
                int o0 = m * PAD_A + kb + q * 2;
                int o1 = (m + 8) * PAD_A + kb + q * 2;
                ah[i][0] = *(const unsigned*)&As[0][o0];
                ah[i][1] = *(const unsigned*)&As[0][o1];
                ah[i][2] = *(const unsigned*)&As[0][o0 + 8];
                ah[i][3] = *(const unsigned*)&As[0][o1 + 8];
                al[i][0] = *(const unsigned*)&As[1][o0];
                al[i][1] = *(const unsigned*)&As[1][o1];
                al[i][2] = *(const unsigned*)&As[1][o0 + 8];
                al[i][3] = *(const unsigned*)&As[1][o1 + 8];
            }
#pragma unroll
            for (int j = 0; j < 4; j++) {
                int n = wn + j * 8 + g;
                int k2 = kb + q * 2;
#pragma unroll
                for (int t = 0; t < 2; t++) {
                    int kk = k2 + t * 8;
                    unsigned h0 = *(const unsigned short*)&Bs[0][kk * PITCH_B + n];
                    unsigned h1 = *(const unsigned short*)&Bs[0][(kk + 1) * PITCH_B + n];
                    bh[j][t] = h0 | (h1 << 16);
                    unsigned l0 = *(const unsigned short*)&Bs[1][kk * PITCH_B + n];
                    unsigned l1 = *(const unsigned short*)&Bs[1][(kk + 1) * PITCH_B + n];
                    bl[j][t] = l0 | (l1 << 16);
                }
            }
#pragma unroll
            for (int i = 0; i < 4; i++)
#pragma unroll
                for (int j = 0; j < 4; j++) {
                    mma_bf16(acc[i][j], ah[i], bh[j]);
                    mma_bf16(acc[i][j], ah[i], bl[j]);
                    mma_bf16(acc[i][j], al[i], bh[j]);
                }
        }
        __syncthreads();
    }
#pragma unroll
    for (int i = 0; i < 4; i++)
#pragma unroll
        for (int j = 0; j < 4; j++) {
            int r = row0 + wm + i * 16 + g;
            int c = col0 + wn + j * 8 + q * 2;
            C[r * ldc + c] = acc[i][j][0];
            C[r * ldc + c + 1] = acc[i][j][1];
            C[(r + 8) * ldc + c] = acc[i][j][2];
            C[(r + 8) * ldc + c + 1] = acc[i][j][3];
        }
}

__global__ void __launch_bounds__(256) k_gemm1() {
    gemm_split(g_xhi, g_xlo, g_w1hi, g_w1lo, INC, blockIdx.x * 128, g_h1, INC,
               blockIdx.y * 128);
}

__global__ void __launch_bounds__(256) k_gemm23(float* __restrict__ out) {
    int bx = blockIdx.x;
    const __nv_bfloat16* Bh = (bx < 2) ? g_w2hi : g_rwhi;
    const __nv_bfloat16* Bl = (bx < 2) ? g_w2lo : g_rwlo;
    float* C = (bx < 2) ? g_h2w : out;
    gemm_split(g_h2hi, g_h2lo, Bh, Bl, OUTC, (bx & 1) * 128, C, OUTC, blockIdx.y * 128);
}

// ------------------- attention scores (warp per node-head) -------------------
__global__ void k_s1(const float* __restrict__ as1, const float* __restrict__ ad1) {
    int n = blockIdx.x;
    int h = threadIdx.x >> 5, lane = threadIdx.x & 31;
    float2 v = *(const float2*)&g_h1[n * INC + h * HID + lane * 2];
    float2 a = *(const float2*)&as1[h * HID + lane * 2];
    float2 d = *(const float2*)&ad1[h * HID + lane * 2];
    float ss = v.x * a.x + v.y * a.y;
    float sd = v.x * d.x + v.y * d.y;
    for (int o = 16; o; o >>= 1) {
        ss += __shfl_xor_sync(0xffffffffu, ss, o);
        sd += __shfl_xor_sync(0xffffffffu, sd, o);
    }
    if (lane == 0) {
        g_s1s[n * NHEADS + h] = ss;
        g_s1d[n * NHEADS + h] = sd;
    }
}

__global__ void k_s2(const float* __restrict__ as2, const float* __restrict__ ad2) {
    int n = blockIdx.x * blockDim.x + threadIdx.x;
    if (n >= NN) return;
    const float4* hp = (const float4*)(g_h2w + n * OUTC);
    const float4* asp = (const float4*)as2;
    const float4* adp = (const float4*)ad2;
    float ss = 0.f, sd = 0.f;
#pragma unroll
    for (int c = 0; c < OUTC / 4; c++) {
        float4 v = hp[c], a = asp[c], d = adp[c];
        ss += v.x * a.x + v.y * a.y + v.z * a.z + v.w * a.w;
        sd += v.x * d.x + v.y * d.y + v.z * d.z + v.w * d.w;
    }
    g_s2s[n] = ss;
    g_s2d[n] = sd;
}

// ------------------- fused softmax + aggregate + split, layer 1 --------------
__device__ __forceinline__ float lrelu(float x) { return x > 0.f ? x : NEG * x; }

__global__ void __launch_bounds__(256) k_sma1(const float* __restrict__ b1, int E) {
    __shared__ float sal[MAXDEG * NHEADS];    // 12 KB alphas
    __shared__ int se[MAXDEG];                // src cache
    __shared__ float sm1[NHEADS], sr1[NHEADS], sm2[NHEADS], sr2[NHEADS];
    int n = blockIdx.x;
    int p0 = g_dptr[n], p1 = g_dptr[n + 1];
    int cnt = p1 - p0;
    int tid = threadIdx.x, h = tid >> 5, lane = tid & 31;
    float sd = g_s1d[n * NHEADS + h];
    float m1 = -1e30f, m2 = -1e30f;
    for (int i = lane; i < cnt; i += 32) {
        int e = g_eidx[p0 + i];
        int s = (e < E) ? g_src[e] : (e - E);
        if (h == 0 && i < MAXDEG) se[i] = s;
        float ev = g_s1s[s * NHEADS + h] + sd;
        m1 = fmaxf(m1, lrelu(ev));
        m2 = fmaxf(m2, lrelu(ev * g_mw[e]));
    }
    for (int o = 16; o; o >>= 1) {
        m1 = fmaxf(m1, __shfl_xor_sync(0xffffffffu, m1, o));
        m2 = fmaxf(m2, __shfl_xor_sync(0xffffffffu, m2, o));
    }
    float s1 = 0.f, s2 = 0.f;
    for (int i = lane; i < cnt; i += 32) {
        int e = g_eidx[p0 + i];
        int s = (e < E) ? g_src[e] : (e - E);
        float ev = g_s1s[s * NHEADS + h] + sd;
        s1 += expf(lrelu(ev) - m1);
        s2 += expf(lrelu(ev * g_mw[e]) - m2);
    }
    for (int o = 16; o; o >>= 1) {
        s1 += __shfl_xor_sync(0xffffffffu, s1, o);
        s2 += __shfl_xor_sync(0xffffffffu, s2, o);
    }
    float r1 = 0.5f / (s1 + 1e-16f);
    float r2 = 0.5f / (s2 + 1e-16f);
    for (int i = lane; i < cnt && i < MAXDEG; i += 32) {
        int e = g_eidx[p0 + i];
        int s = (e < E) ? g_src[e] : (e - E);
        float ev = g_s1s[s * NHEADS + h] + sd;
        sal[i * NHEADS + h] = expf(lrelu(ev) - m1) * r1
                            + expf(lrelu(ev * g_mw[e]) - m2) * r2;
    }
    if (lane == 0) { sm1[h] = m1; sr1[h] = r1; sm2[h] = m2; sr2[h] = r2; }
    __syncthreads();
    // aggregation: warp h handles channels [h*64, h*64+63]; lane -> float2
    int c = h * HID + lane * 2;
    float2 acc = make_float2(0.f, 0.f);
    for (int i = 0; i < cnt; i++) {
        float a;
        int s;
        if (i < MAXDEG) {
            s = se[i];
            a = sal[i * NHEADS + h];
        } else {  // overflow fallback (statistically never)
            int e = g_eidx[p0 + i];
            s = (e < E) ? g_src[e] : (e - E);
            float ev = g_s1s[s * NHEADS + h] + sd;
            a = expf(lrelu(ev) - sm1[h]) * sr1[h]
              + expf(lrelu(ev * g_mw[e]) - sm2[h]) * sr2[h];
        }
        float2 v = *(const float2*)&g_h1[s * INC + c];
        acc.x += a * v.x;
        acc.y += a * v.y;
    }
    float2 bb = *(const float2*)&b1[c];
    float rx = acc.x + bb.x, ry = acc.y + bb.y;
    rx = rx > 0.f ? rx : expm1f(rx);
    ry = ry > 0.f ? ry : expm1f(ry);
    // write bf16 split of elu(h2) directly (gemm23 reads only the split)
    __nv_bfloat16 hx = __float2bfloat16(rx);
    __nv_bfloat16 hy = __float2bfloat16(ry);
    __nv_bfloat16 lx = __float2bfloat16(rx - __bfloat162float(hx));
    __nv_bfloat16 ly = __float2bfloat16(ry - __bfloat162float(hy));
    __nv_bfloat162 hp; hp.x = hx; hp.y = hy;
    __nv_bfloat162 lp; lp.x = lx; lp.y = ly;
    *(__nv_bfloat162*)&g_h2hi[n * INC + c] = hp;
    *(__nv_bfloat162*)&g_h2lo[n * INC + c] = lp;
}

// ------------------- fused softmax + aggregate, layer 2 ----------------------
__global__ void __launch_bounds__(256) k_sma2(const float* __restrict__ b2,
                                              float* __restrict__ out, int E) {
    __shared__ float sal[MAXDEG];
    __shared__ int se[MAXDEG];
    __shared__ float st[4];   // m1, r1, m2, r2
    int n = blockIdx.x;
    int p0 = g_dptr[n], p1 = g_dptr[n + 1];
    int cnt = p1 - p0;
    int tid = threadIdx.x;
    if (tid < 32) {
        int lane = tid;
        float sd = g_s2d[n];
        float m1 = -1e30f, m2 = -1e30f;
        for (int i = lane; i < cnt; i += 32) {
            int e = g_eidx[p0 + i];
            int s = (e < E) ? g_src[e] : (e - E);
            if (i < MAXDEG) se[i] = s;
            float ev = g_s2s[s] + sd;
            m1 = fmaxf(m1, lrelu(ev));
            m2 = fmaxf(m2, lrelu(ev * g_mw[e]));
        }
        for (int o = 16; o; o >>= 1) {
            m1 = fmaxf(m1, __shfl_xor_sync(0xffffffffu, m1, o));
            m2 = fmaxf(m2, __shfl_xor_sync(0xffffffffu, m2, o));
        }
        float s1 = 0.f, s2 = 0.f;
        for (int i = lane; i < cnt; i += 32) {
            int e = g_eidx[p0 + i];
            int s = (e < E) ? g_src[e] : (e - E);
            float ev = g_s2s[s] + sd;
            s1 += expf(lrelu(ev) - m1);
            s2 += expf(lrelu(ev * g_mw[e]) - m2);
        }
        for (int o = 16; o; o >>= 1) {
            s1 += __shfl_xor_sync(0xffffffffu, s1, o);
            s2 += __shfl_xor_sync(0xffffffffu, s2, o);
        }
        float r1 = 0.5f / (s1 + 1e-16f);
        float r2 = 0.5f / (s2 + 1e-16f);
        for (int i = lane; i < cnt && i < MAXDEG; i += 32) {
            int e = g_eidx[p0 + i];
            int s = (e < E) ? g_src[e] : (e - E);
            float ev = g_s2s[s] + sd;
            sal[i] = expf(lrelu(ev) - m1) * r1 + expf(lrelu(ev * g_mw[e]) - m2) * r2;
        }
        if (lane == 0) { st[0] = m1; st[1] = r1; st[2] = m2; st[3] = r2; }
    }
    __syncthreads();
    int c = tid;
    float acc = 0.f;
    float sd = g_s2d[n];
    for (int i = 0; i < cnt; i++) {
        float a;
        int s;
        if (i < MAXDEG) {
            s = se[i];
            a = sal[i];
        } else {
            int e = g_eidx[p0 + i];
            s = (e < E) ? g_src[e] : (e - E);
            float ev = g_s2s[s] + sd;
            a = expf(lrelu(ev) - st[0]) * st[1] + expf(lrelu(ev * g_mw[e]) - st[2]) * st[3];
        }
        acc += a * g_h2w[s * OUTC + c];
    }
    out[n * OUTC + c] = out[n * OUTC + c] + acc + b2[c];
}

// ------------------------- launch --------------------------------------------
extern "C" void kernel_launch(void* const* d_in, const int* in_sizes, int n_in,
                              void* d_out, int out_size) {
    const float* x    = (const float*)d_in[0];
    const void*  ei   = d_in[1];
    const float* W1   = (const float*)d_in[2];
    const float* as1  = (const float*)d_in[3];
    const float* ad1  = (const float*)d_in[4];
    const float* b1   = (const float*)d_in[5];
    const float* W2   = (const float*)d_in[6];
    const float* as2  = (const float*)d_in[7];
    const float* ad2  = (const float*)d_in[8];
    const float* b2   = (const float*)d_in[9];
    const float* rW2  = (const float*)d_in[10];
    float* out = (float*)d_out;

    int E = in_sizes[1] / 2;
    int EP = E + NN;

    static cudaStream_t sC = 0;
    static cudaEvent_t ev0 = 0, evC = 0;
    if (!sC) {
        cudaStreamCreateWithFlags(&sC, cudaStreamNonBlocking);
        cudaEventCreateWithFlags(&ev0, cudaEventDisableTiming);
        cudaEventCreateWithFlags(&evC, cudaEventDisableTiming);
    }

    // fork
    cudaEventRecord(ev0, 0);
    cudaStreamWaitEvent(sC, ev0, 0);

    // branch C: operand splits -> gemm1 -> s1
    {
        int tot8 = NX8 + NW18 + 2 * NW28;
        k_splitall<<<(tot8 + 255) / 256, 256, 0, sC>>>(x, W1, W2, rW2);
        k_gemm1<<<dim3(INC / 128, NN / 128), 256, 0, sC>>>();
        k_s1<<<NN, 256, 0, sC>>>(as1, ad1);
        cudaEventRecord(evC, sC);
    }

    // main chain (default stream)
    k_convert<<<(E + 255) / 256, 256>>>(ei, E);
    k_bitmap<<<(EP + 255) / 256, 256>>>(E);
    k_deg<<<16, 256>>>();
    k_dualscan<<<1, 1024>>>();
    k_build<<<16 + (EP + 255) / 256, 256>>>(E);
    k_a2<<<NN, 256>>>();
    k_mw<<<(EP + 127) / 128, 128>>>(E);

    cudaStreamWaitEvent(0, evC, 0);
    k_sma1<<<NN, 256>>>(b1, E);
    k_gemm23<<<dim3(4, NN / 128), 256>>>(out);
    k_s2<<<16, 256>>>(as2, ad2);
    k_sma2<<<NN, 256>>>(b2, out, E);
}

// round 10
// speedup vs baseline: 2.4137x; 1.0180x over previous
#include <cuda_runtime.h>
#include <cuda_bf16.h>
#include <stdint.h>
#include <math.h>

#define NN 4096
#define EE_MAX 131072
#define EPMAX (EE_MAX + NN)
#define INC 512
#define NHEADS 8
#define HID 64
#define OUTC 256
#define WORDS (NN / 32)
#define NEG 0.2f
#define MAXDEG 384

// ------------------------- device scratch (static, no allocs) ---------------
__device__ int g_src[EE_MAX], g_dst[EE_MAX];
__device__ __align__(16) unsigned g_adj[NN * WORDS];   // zero at load; re-zeroed by sma2 tail
__device__ int g_deg[NN];
__device__ int g_rowptr[NN + 1];
__device__ int g_cols[EPMAX];
__device__ float g_d1[NN], g_d2[NN], g_d3[NN];
__device__ __align__(16) unsigned short g_A2h[NN * NN];   // 32 MB dense A@A (u16)
__device__ float g_mw[EPMAX];
__device__ float g_h1[NN * INC];
__device__ float g_h2w[NN * OUTC];
__device__ float g_s1s[NN * NHEADS], g_s1d[NN * NHEADS];
__device__ float g_s2s[NN], g_s2d[NN];
__device__ __align__(16) int g_hist[NN];               // zero at load; re-zeroed by sma2 tail
__device__ int g_dptr[NN + 1];
__device__ int g_dcur[NN];
__device__ int g_eidx[EPMAX];

// bf16 split operands (hi + lo)
__device__ __align__(16) __nv_bfloat16 g_xhi[NN * INC], g_xlo[NN * INC];
__device__ __align__(16) __nv_bfloat16 g_w1hi[INC * INC], g_w1lo[INC * INC];
__device__ __align__(16) __nv_bfloat16 g_w2hi[INC * OUTC], g_w2lo[INC * OUTC];
__device__ __align__(16) __nv_bfloat16 g_rwhi[INC * OUTC], g_rwlo[INC * OUTC];
__device__ __align__(16) __nv_bfloat16 g_h2hi[NN * INC], g_h2lo[NN * INC];

// ------------------ convert + bitmap + hist (adj/hist pre-zeroed) ------------
__global__ void k_convert(const void* p, int E) {
    __shared__ int any;
    if (threadIdx.x == 0) any = 0;
    __syncthreads();
    const int* w = (const int*)p;
#pragma unroll
    for (int t = 0; t < 4; t++) {
        int idx = threadIdx.x + t * 256;
        if (w[2 * idx + 1] != 0) any = 1;
    }
    __syncthreads();
    bool is64 = (any == 0);
    int i = blockIdx.x * blockDim.x + threadIdx.x;
    int EP = E + NN;
    if (i >= EP) return;
    int s, d;
    if (i < E) {
        if (is64) {
            const long long* q = (const long long*)p;
            s = (int)q[i];
            d = (int)q[E + i];
        } else {
            const int* q = (const int*)p;
            s = q[i];
            d = q[E + i];
        }
        g_src[i] = s;
        g_dst[i] = d;
    } else {
        s = i - E;
        d = i - E;
    }
    atomicOr(&g_adj[s * WORDS + (d >> 5)], 1u << (d & 31));
    atomicAdd(&g_hist[d], 1);
}

// ------------------------- fp32 -> (hi,lo) bf16 split ------------------------
__device__ __forceinline__ void split8(const float* __restrict__ src,
                                       __nv_bfloat16* __restrict__ hi,
                                       __nv_bfloat16* __restrict__ lo, int i) {
    const float4* s4 = (const float4*)src;
    float4 v0 = s4[2 * i], v1 = s4[2 * i + 1];
    float f[8] = {v0.x, v0.y, v0.z, v0.w, v1.x, v1.y, v1.z, v1.w};
    __nv_bfloat16 h[8], l[8];
#pragma unroll
    for (int k = 0; k < 8; k++) {
        h[k] = __float2bfloat16(f[k]);
        l[k] = __float2bfloat16(f[k] - __bfloat162float(h[k]));
    }
    ((uint4*)hi)[i] = *(uint4*)h;
    ((uint4*)lo)[i] = *(uint4*)l;
}

#define NX8 (NN * INC / 8)
#define NW18 (INC * INC / 8)
#define NW28 (INC * OUTC / 8)
__global__ void k_splitall(const float* __restrict__ x, const float* __restrict__ W1,
                           const float* __restrict__ W2, const float* __restrict__ rW2) {
    int i = blockIdx.x * blockDim.x + threadIdx.x;
    if (i < NX8) { split8(x, g_xhi, g_xlo, i); return; }
    i -= NX8;
    if (i < NW18) { split8(W1, g_w1hi, g_w1lo, i); return; }
    i -= NW18;
    if (i < NW28) { split8(W2, g_w2hi, g_w2lo, i); return; }
    i -= NW28;
    if (i < NW28) { split8(rW2, g_rwhi, g_rwlo, i); return; }
}

// ------------------------- degree / scans / build ----------------------------
__global__ void k_deg() {
    int r = blockIdx.x * blockDim.x + threadIdx.x;
    if (r >= NN) return;
    const uint4* row = (const uint4*)(g_adj + r * WORDS);
    int c = 0;
#pragma unroll
    for (int w = 0; w < WORDS / 4; w++) {
        uint4 v = row[w];
        c += __popc(v.x) + __popc(v.y) + __popc(v.z) + __popc(v.w);
    }
    g_deg[r] = c;
    g_d1[r] = (float)c;
}

__global__ void k_dualscan() {
    __shared__ int s[1024];
    int tid = threadIdx.x;
#pragma unroll
    for (int pass = 0; pass < 2; pass++) {
        const int* in = pass ? g_hist : g_deg;
        int* out = pass ? g_dptr : g_rowptr;
        int base = tid * 4;
        int loc[4];
        int tot = 0;
#pragma unroll
        for (int i = 0; i < 4; i++) { loc[i] = tot; tot += in[base + i]; }
        s[tid] = tot;
        __syncthreads();
        for (int off = 1; off < 1024; off <<= 1) {
            int t = (tid >= off) ? s[tid - off] : 0;
            __syncthreads();
            s[tid] += t;
            __syncthreads();
        }
        int pre = (tid == 0) ? 0 : s[tid - 1];
#pragma unroll
        for (int i = 0; i < 4; i++) {
            out[base + i] = pre + loc[i];
            if (pass) g_dcur[base + i] = pre + loc[i];
        }
        if (tid == 1023) out[4096] = s[1023];
        __syncthreads();
    }
}

__global__ void k_build(int E) {
    int EP = E + NN;
    if (blockIdx.x < 16) {
        int r = blockIdx.x * blockDim.x + threadIdx.x;
        if (r >= NN) return;
        int p = g_rowptr[r];
        float d2 = 0.f;
        for (int w = 0; w < WORDS; w++) {
            unsigned m = g_adj[r * WORDS + w];
            while (m) {
                int b = __ffs(m) - 1;
                int c = w * 32 + b;
                g_cols[p++] = c;
                d2 += g_d1[c];
                m &= m - 1;
            }
        }
        g_d2[r] = d2;
    } else {
        int e = (blockIdx.x - 16) * blockDim.x + threadIdx.x;
        if (e >= EP) return;
        int d = (e < E) ? g_dst[e] : (e - E);
        int pos = atomicAdd(&g_dcur[d], 1);
        g_eidx[pos] = e;
    }
}

// ------------- A2 row in shared memory + d3[k] = A*d2 ------------------------
__global__ void __launch_bounds__(256) k_a2() {
    __shared__ unsigned short row[NN];
    int tid = threadIdx.x;
    unsigned* roww = (unsigned*)row;
    for (int i = tid; i < NN / 2; i += 256) roww[i] = 0u;
    __syncthreads();
    int k = blockIdx.x;
    int p0 = g_rowptr[k], p1 = g_rowptr[k + 1];
    float d3 = 0.f;
    for (int i = p0 + tid; i < p1; i += 256) d3 += g_d2[g_cols[i]];
    for (int o = 16; o; o >>= 1) d3 += __shfl_xor_sync(0xffffffffu, d3, o);
    __shared__ float sred[8];
    if ((tid & 31) == 0) sred[tid >> 5] = d3;
    int wid = tid >> 5, lane = tid & 31;
    for (int mi = p0 + wid; mi < p1; mi += 8) {
        int m = g_cols[mi];
        int q1 = g_rowptr[m + 1];
        for (int j = g_rowptr[m] + lane; j < q1; j += 32) {
            int d = g_cols[j];
            atomicAdd(&roww[d >> 1], (d & 1) ? 0x10000u : 1u);
        }
    }
    __syncthreads();
    if (tid == 0) {
        float t = 0.f;
        for (int i = 0; i < 8; i++) t += sred[i];
        g_d3[k] = t;
    }
    uint4* dst = (uint4*)(g_A2h + (size_t)k * NN);
    const uint4* srcv = (const uint4*)row;
    for (int i = tid; i < NN / 8; i += 256) dst[i] = srcv[i];
}

__global__ void k_mw(int E) {
    int e = blockIdx.x * blockDim.x + threadIdx.x;
    int EP = E + NN;
    if (e >= EP) return;
    int s = (e < E) ? g_src[e] : (e - E);
    int d = (e < E) ? g_dst[e] : (e - E);
    float a3 = 0.f;
    int p1 = g_rowptr[s + 1];
    for (int i = g_rowptr[s]; i < p1; i++)
        a3 += (float)g_A2h[(size_t)g_cols[i] * NN + d];
    float nm = g_d3[s];
    if (nm < 1.f) nm = 1.f;
    g_mw[e] = a3 / nm;
}

// ------------------------- split-bf16 HMMA GEMM ------------------------------
#define PAD_A 40
#define PITCH_B 136

__device__ __forceinline__ void mma_bf16(float* c, const unsigned* a, const unsigned* b) {
    asm volatile(
        "mma.sync.aligned.m16n8k16.row.col.f32.bf16.bf16.f32 "
        "{%0,%1,%2,%3}, {%4,%5,%6,%7}, {%8,%9}, {%0,%1,%2,%3};"
        : "+f"(c[0]), "+f"(c[1]), "+f"(c[2]), "+f"(c[3])
        : "r"(a[0]), "r"(a[1]), "r"(a[2]), "r"(a[3]), "r"(b[0]), "r"(b[1]));
}

__device__ __forceinline__ void gemm_split(const __nv_bfloat16* __restrict__ Ahi,
                                           const __nv_bfloat16* __restrict__ Alo,
                                           const __nv_bfloat16* __restrict__ Bhi,
                                           const __nv_bfloat16* __restrict__ Blo,
                                           int ldb, int col0,
                                           float* __restrict__ C, int ldc, int row0) {
    __shared__ __nv_bfloat16 As[2][128 * PAD_A];
    __shared__ __nv_bfloat16 Bs[2][32 * PITCH_B];
    int tid = threadIdx.x;
    int wid = tid >> 5, lane = tid & 31;
    int wm = (wid >> 2) * 64;
    int wn = (wid & 3) * 32;
    int g = lane >> 2, q = lane & 3;
    float acc[4][4][4] = {};

    for (int k0 = 0; k0 < INC; k0 += 32) {
#pragma unroll
        for (int l = 0; l < 2; l++) {
            int slot = tid + l * 256;
            int r = slot >> 2, cg = (slot & 3) << 3;
            *(float4*)&As[0][r * PAD_A + cg] = *(const float4*)&Ahi[(row0 + r) * INC + k0 + cg];
            *(float4*)&As[1][r * PAD_A + cg] = *(const float4*)&Alo[(row0 + r) * INC + k0 + cg];
        }
#pragma unroll
        for (int l = 0; l < 2; l++) {
            int slot = tid + l * 256;
            int kr = slot >> 4, ng = (slot & 15) << 3;
            *(float4*)&Bs[0][kr * PITCH_B + ng] = *(const float4*)&Bhi[(k0 + kr) * ldb + col0 + ng];
            *(float4*)&Bs[1][kr * PITCH_B + ng] = *(const float4*)&Blo[(k0 + kr) * ldb + col0 + ng];
        }
        __syncthreads();
#pragma unroll
        for (int ks = 0; ks < 2; ks++) {
            int kb = ks * 16;
            unsigned ah[4][4], al[4][4], bh[4][2], bl[4][2];
#pragma unroll
            for (int i = 0; i < 4; i++) {
                int m = wm + i * 16 + g;
                int o0 = m * PAD_A + kb + q * 2;
                int o1 = (m + 8) * PAD_A + kb + q * 2;
                ah[i][0] = *(const unsigned*)&As[0][o0];
                ah[i][1] = *(const unsigned*)&As[0][o1];
                ah[i][2] = *(const unsigned*)&As[0][o0 + 8];
                ah[i][3] = *(const unsigned*)&As[0][o1 + 8];
                al[i][0] = *(const unsigned*)&As[1][o0];
                al[i][1] = *(const unsigned*)&As[1][o1];
                al[i][2] = *(const unsigned*)&As[1][o0 + 8];
                al[i][3] = *(const unsigned*)&As[1][o1 + 8];
            }
#pragma unroll
            for (int j = 0; j < 4; j++) {
                int n = wn + j * 8 + g;
                int k2 = kb + q * 2;
#pragma unroll
                for (int t = 0; t < 2; t++) {
                    int kk = k2 + t * 8;
                    unsigned h0 = *(const unsigned short*)&Bs[0][kk * PITCH_B + n];
                    unsigned h1 = *(const unsigned short*)&Bs[0][(kk + 1) * PITCH_B + n];
                    bh[j][t] = h0 | (h1 << 16);
                    unsigned l0 = *(const unsigned short*)&Bs[1][kk * PITCH_B + n];
                    unsigned l1 = *(const unsigned short*)&Bs[1][(kk + 1) * PITCH_B + n];
                    bl[j][t] = l0 | (l1 << 16);
                }
            }
#pragma unroll
            for (int i = 0; i < 4; i++)
#pragma unroll
                for (int j = 0; j < 4; j++) {
                    mma_bf16(acc[i][j], ah[i], bh[j]);
                    mma_bf16(acc[i][j], ah[i], bl[j]);
                    mma_bf16(acc[i][j], al[i], bh[j]);
                }
        }
        __syncthreads();
    }
#pragma unroll
    for (int i = 0; i < 4; i++)
#pragma unroll
        for (int j = 0; j < 4; j++) {
            int r = row0 + wm + i * 16 + g;
            int c = col0 + wn + j * 8 + q * 2;
            C[r * ldc + c] = acc[i][j][0];
            C[r * ldc + c + 1] = acc[i][j][1];
            C[(r + 8) * ldc + c] = acc[i][j][2];
            C[(r + 8) * ldc + c + 1] = acc[i][j][3];
        }
}

__global__ void __launch_bounds__(256) k_gemm1() {
    gemm_split(g_xhi, g_xlo, g_w1hi, g_w1lo, INC, blockIdx.x * 128, g_h1, INC,
               blockIdx.y * 128);
}

// bx 0,1: g_h2w = h2 @ W2 ; bx 2,3: out = h2 @ resW2
__global__ void __launch_bounds__(256) k_gemm23(float* __restrict__ out) {
    int bx = blockIdx.x;
    const __nv_bfloat16* Bh = (bx < 2) ? g_w2hi : g_rwhi;
    const __nv_bfloat16* Bl = (bx < 2) ? g_w2lo : g_rwlo;
    float* C = (bx < 2) ? g_h2w : out;
    gemm_split(g_h2hi, g_h2lo, Bh, Bl, OUTC, (bx & 1) * 128, C, OUTC, blockIdx.y * 128);
}

// ------------------- attention scores ---------------------------------------
__global__ void k_s1(const float* __restrict__ as1, const float* __restrict__ ad1) {
    int n = blockIdx.x;
    int h = threadIdx.x >> 5, lane = threadIdx.x & 31;
    float2 v = *(const float2*)&g_h1[n * INC + h * HID + lane * 2];
    float2 a = *(const float2*)&as1[h * HID + lane * 2];
    float2 d = *(const float2*)&ad1[h * HID + lane * 2];
    float ss = v.x * a.x + v.y * a.y;
    float sd = v.x * d.x + v.y * d.y;
    for (int o = 16; o; o >>= 1) {
        ss += __shfl_xor_sync(0xffffffffu, ss, o);
        sd += __shfl_xor_sync(0xffffffffu, sd, o);
    }
    if (lane == 0) {
        g_s1s[n * NHEADS + h] = ss;
        g_s1d[n * NHEADS + h] = sd;
    }
}

__global__ void k_s2(const float* __restrict__ as2, const float* __restrict__ ad2) {
    int n = blockIdx.x * blockDim.x + threadIdx.x;
    if (n >= NN) return;
    const float4* hp = (const float4*)(g_h2w + n * OUTC);
    const float4* asp = (const float4*)as2;
    const float4* adp = (const float4*)ad2;
    float ss = 0.f, sd = 0.f;
#pragma unroll
    for (int c = 0; c < OUTC / 4; c++) {
        float4 v = hp[c], a = asp[c], d = adp[c];
        ss += v.x * a.x + v.y * a.y + v.z * a.z + v.w * a.w;
        sd += v.x * d.x + v.y * d.y + v.z * d.z + v.w * d.w;
    }
    g_s2s[n] = ss;
    g_s2d[n] = sd;
}

// ------------------- fused softmax + aggregate + split, layer 1 --------------
__device__ __forceinline__ float lrelu(float x) { return x > 0.f ? x : NEG * x; }

__global__ void __launch_bounds__(256) k_sma1(const float* __restrict__ b1, int E) {
    __shared__ float sal[MAXDEG * NHEADS];
    __shared__ int se[MAXDEG];
    __shared__ float sm1[NHEADS], sr1[NHEADS], sm2[NHEADS], sr2[NHEADS];
    int n = blockIdx.x;
    int p0 = g_dptr[n], p1 = g_dptr[n + 1];
    int cnt = p1 - p0;
    int tid = threadIdx.x, h = tid >> 5, lane = tid & 31;
    float sd = g_s1d[n * NHEADS + h];
    float m1 = -1e30f, m2 = -1e30f;
    for (int i = lane; i < cnt; i += 32) {
        int e = g_eidx[p0 + i];
        int s = (e < E) ? g_src[e] : (e - E);
        if (h == 0 && i < MAXDEG) se[i] = s;
        float ev = g_s1s[s * NHEADS + h] + sd;
        m1 = fmaxf(m1, lrelu(ev));
        m2 = fmaxf(m2, lrelu(ev * g_mw[e]));
    }
    for (int o = 16; o; o >>= 1) {
        m1 = fmaxf(m1, __shfl_xor_sync(0xffffffffu, m1, o));
        m2 = fmaxf(m2, __shfl_xor_sync(0xffffffffu, m2, o));
    }
    float s1 = 0.f, s2 = 0.f;
    for (int i = lane; i < cnt; i += 32) {
        int e = g_eidx[p0 + i];
        int s = (e < E) ? g_src[e] : (e - E);
        float ev = g_s1s[s * NHEADS + h] + sd;
        s1 += expf(lrelu(ev) - m1);
        s2 += expf(lrelu(ev * g_mw[e]) - m2);
    }
    for (int o = 16; o; o >>= 1) {
        s1 += __shfl_xor_sync(0xffffffffu, s1, o);
        s2 += __shfl_xor_sync(0xffffffffu, s2, o);
    }
    float r1 = 0.5f / (s1 + 1e-16f);
    float r2 = 0.5f / (s2 + 1e-16f);
    for (int i = lane; i < cnt && i < MAXDEG; i += 32) {
        int e = g_eidx[p0 + i];
        int s = (e < E) ? g_src[e] : (e - E);
        float ev = g_s1s[s * NHEADS + h] + sd;
        sal[i * NHEADS + h] = expf(lrelu(ev) - m1) * r1
                            + expf(lrelu(ev * g_mw[e]) - m2) * r2;
    }
    if (lane == 0) { sm1[h] = m1; sr1[h] = r1; sm2[h] = m2; sr2[h] = r2; }
    __syncthreads();
    int c = h * HID + lane * 2;
    float2 acc = make_float2(0.f, 0.f);
    for (int i = 0; i < cnt; i++) {
        float a;
        int s;
        if (i < MAXDEG) {
            s = se[i];
            a = sal[i * NHEADS + h];
        } else {
            int e = g_eidx[p0 + i];
            s = (e < E) ? g_src[e] : (e - E);
            float ev = g_s1s[s * NHEADS + h] + sd;
            a = expf(lrelu(ev) - sm1[h]) * sr1[h]
              + expf(lrelu(ev * g_mw[e]) - sm2[h]) * sr2[h];
        }
        float2 v = *(const float2*)&g_h1[s * INC + c];
        acc.x += a * v.x;
        acc.y += a * v.y;
    }
    float2 bb = *(const float2*)&b1[c];
    float rx = acc.x + bb.x, ry = acc.y + bb.y;
    rx = rx > 0.f ? rx : expm1f(rx);
    ry = ry > 0.f ? ry : expm1f(ry);
    __nv_bfloat16 hx = __float2bfloat16(rx);
    __nv_bfloat16 hy = __float2bfloat16(ry);
    __nv_bfloat16 lx = __float2bfloat16(rx - __bfloat162float(hx));
    __nv_bfloat16 ly = __float2bfloat16(ry - __bfloat162float(hy));
    __nv_bfloat162 hp; hp.x = hx; hp.y = hy;
    __nv_bfloat162 lp; lp.x = lx; lp.y = ly;
    *(__nv_bfloat162*)&g_h2hi[n * INC + c] = hp;
    *(__nv_bfloat162*)&g_h2lo[n * INC + c] = lp;
}

// ------------- fused softmax + aggregate, layer 2 (+ tail cleanup) -----------
__global__ void __launch_bounds__(256) k_sma2(const float* __restrict__ b2,
                                              float* __restrict__ out, int E) {
    int n = blockIdx.x;
    if (n >= NN) {   // cleanup blocks: re-zero adj + hist for the next launch
        int idx = (n - NN) * 256 + threadIdx.x;
        uint4 zu = make_uint4(0u, 0u, 0u, 0u);
        uint4* adjv = (uint4*)g_adj;
        for (int i = idx; i < NN * WORDS / 4; i += 64 * 256) adjv[i] = zu;
        uint4* hv = (uint4*)g_hist;
        for (int i = idx; i < NN / 4; i += 64 * 256) hv[i] = zu;
        return;
    }
    __shared__ float sal[MAXDEG];
    __shared__ int se[MAXDEG];
    __shared__ float st[4];
    int p0 = g_dptr[n], p1 = g_dptr[n + 1];
    int cnt = p1 - p0;
    int tid = threadIdx.x;
    if (tid < 32) {
        int lane = tid;
        float sd = g_s2d[n];
        float m1 = -1e30f, m2 = -1e30f;
        for (int i = lane; i < cnt; i += 32) {
            int e = g_eidx[p0 + i];
            int s = (e < E) ? g_src[e] : (e - E);
            if (i < MAXDEG) se[i] = s;
            float ev = g_s2s[s] + sd;
            m1 = fmaxf(m1, lrelu(ev));
            m2 = fmaxf(m2, lrelu(ev * g_mw[e]));
        }
        for (int o = 16; o; o >>= 1) {
            m1 = fmaxf(m1, __shfl_xor_sync(0xffffffffu, m1, o));
            m2 = fmaxf(m2, __shfl_xor_sync(0xffffffffu, m2, o));
        }
        float s1 = 0.f, s2 = 0.f;
        for (int i = lane; i < cnt; i += 32) {
            int e = g_eidx[p0 + i];
            int s = (e < E) ? g_src[e] : (e - E);
            float ev = g_s2s[s] + sd;
            s1 += expf(lrelu(ev) - m1);
            s2 += expf(lrelu(ev * g_mw[e]) - m2);
        }
        for (int o = 16; o; o >>= 1) {
            s1 += __shfl_xor_sync(0xffffffffu, s1, o);
            s2 += __shfl_xor_sync(0xffffffffu, s2, o);
        }
        float r1 = 0.5f / (s1 + 1e-16f);
        float r2 = 0.5f / (s2 + 1e-16f);
        for (int i = lane; i < cnt && i < MAXDEG; i += 32) {
            int e = g_eidx[p0 + i];
            int s = (e < E) ? g_src[e] : (e - E);
            float ev = g_s2s[s] + sd;
            sal[i] = expf(lrelu(ev) - m1) * r1 + expf(lrelu(ev * g_mw[e]) - m2) * r2;
        }
        if (lane == 0) { st[0] = m1; st[1] = r1; st[2] = m2; st[3] = r2; }
    }
    __syncthreads();
    int c = tid;
    float acc = 0.f;
    float sd = g_s2d[n];
    for (int i = 0; i < cnt; i++) {
        float a;
        int s;
        if (i < MAXDEG) {
            s = se[i];
            a = sal[i];
        } else {
            int e = g_eidx[p0 + i];
            s = (e < E) ? g_src[e] : (e - E);
            float ev = g_s2s[s] + sd;
            a = expf(lrelu(ev) - st[0]) * st[1] + expf(lrelu(ev * g_mw[e]) - st[2]) * st[3];
        }
        acc += a * g_h2w[s * OUTC + c];
    }
    out[n * OUTC + c] = out[n * OUTC + c] + acc + b2[c];
}

// ------------------------- launch --------------------------------------------
extern "C" void kernel_launch(void* const* d_in, const int* in_sizes, int n_in,
                              void* d_out, int out_size) {
    const float* x    = (const float*)d_in[0];
    const void*  ei   = d_in[1];
    const float* W1   = (const float*)d_in[2];
    const float* as1  = (const float*)d_in[3];
    const float* ad1  = (const float*)d_in[4];
    const float* b1   = (const float*)d_in[5];
    const float* W2   = (const float*)d_in[6];
    const float* as2  = (const float*)d_in[7];
    const float* ad2  = (const float*)d_in[8];
    const float* b2   = (const float*)d_in[9];
    const float* rW2  = (const float*)d_in[10];
    float* out = (float*)d_out;

    int E = in_sizes[1] / 2;
    int EP = E + NN;

    static cudaStream_t sC = 0;
    static cudaEvent_t ev0 = 0, evC = 0;
    if (!sC) {
        cudaStreamCreateWithFlags(&sC, cudaStreamNonBlocking);
        cudaEventCreateWithFlags(&ev0, cudaEventDisableTiming);
        cudaEventCreateWithFlags(&evC, cudaEventDisableTiming);
    }

    // fork
    cudaEventRecord(ev0, 0);
    cudaStreamWaitEvent(sC, ev0, 0);

    // branch C: operand splits -> gemm1 -> s1
    {
        int tot = NX8 + NW18 + 2 * NW28;
        k_splitall<<<(tot + 255) / 256, 256, 0, sC>>>(x, W1, W2, rW2);
        k_gemm1<<<dim3(INC / 128, NN / 128), 256, 0, sC>>>();
        k_s1<<<NN, 256, 0, sC>>>(as1, ad1);
        cudaEventRecord(evC, sC);
    }

    // main chain
    k_convert<<<(EP + 255) / 256, 256>>>(ei, E);
    k_deg<<<16, 256>>>();
    k_dualscan<<<1, 1024>>>();
    k_build<<<16 + (EP + 255) / 256, 256>>>(E);
    k_a2<<<NN, 256>>>();
    k_mw<<<(EP + 127) / 128, 128>>>(E);

    cudaStreamWaitEvent(0, evC, 0);
    k_sma1<<<NN, 256>>>(b1, E);
    k_gemm23<<<dim3(4, NN / 128), 256>>>(out);
    k_s2<<<16, 256>>>(as2, ad2);
    k_sma2<<<NN + 64, 256>>>(b2, out, E);
}